// round 4
// baseline (speedup 1.0000x reference)
#include <cuda_runtime.h>
#include <math.h>

#define DM   1024
#define NH   16
#define DK   64
#define SEQ  2048
#define BB   2
#define TOK  (BB*SEQ)   // 4096

typedef unsigned long long u64t;

// ---- packed f32x2 helpers (Blackwell FFMA2 path; exact fp32 semantics) ----
__device__ __forceinline__ u64t pack2(float lo, float hi) {
    u64t r; asm("mov.b64 %0, {%1,%2};" : "=l"(r) : "f"(lo), "f"(hi)); return r;
}
__device__ __forceinline__ float2 unpack2(u64t v) {
    float2 f; asm("mov.b64 {%0,%1}, %2;" : "=f"(f.x), "=f"(f.y) : "l"(v)); return f;
}
#define FMA2(d, a, b, c) \
    asm("fma.rn.f32x2 %0, %1, %2, %3;" : "=l"(d) : "l"(a), "l"(b), "l"(c))
#define MUL2(d, a, b) \
    asm("mul.rn.f32x2 %0, %1, %2;" : "=l"(d) : "l"(a), "l"(b))

// ---------------- scratch (__device__ globals; no allocation allowed) -------
__device__ float g_Qh[BB*NH*SEQ*DK];   // [B,H,S,DK]
__device__ float g_Kh[BB*NH*SEQ*DK];
__device__ float g_Vh[BB*NH*SEQ*DK];
__device__ float g_ctx[TOK*DM];        // [B,S,DM]

// ---------------------------------------------------------------------------
// GEMM: C = A[M,DM] @ W[N,DM]^T + bias.  64x64 tile, BK=16, 256 thr, 4x4/thr.
// A staged in smem DUPLICATED (a,a pairs) so FFMA2 dup operands come from one
// LDS.128; B staged normally so (b0,b1) pairs are consecutive 64-bit words.
// HEADLAYOUT=1: write [B,H,S,DK]; 0: plain [t,n].
// ---------------------------------------------------------------------------
template<int HEADLAYOUT>
__device__ __forceinline__
void gemm_core(const float* __restrict__ A, const float* __restrict__ W,
               const float* __restrict__ bias, float* __restrict__ C)
{
    __shared__ float As2[16][132];  // [k][2m] duplicated pairs (128 payload)
    __shared__ float Bs[16][68];    // [k][n]

    const int tid = threadIdx.x;
    const int tx  = tid & 15;       // n sub
    const int ty  = tid >> 4;       // m sub
    const int m0  = blockIdx.y << 6;
    const int n0  = blockIdx.x << 6;

    const int lm  = tid >> 2;            // 0..63 row within tile
    const int lk4 = (tid & 3) << 2;      // 0,4,8,12

    const float* Ap = A + (size_t)(m0 + lm) * DM + lk4;
    const float* Wp = W + (size_t)(n0 + lm) * DM + lk4;

    u64t acc2[4][2];
    #pragma unroll
    for (int i = 0; i < 4; i++) { acc2[i][0] = 0ull; acc2[i][1] = 0ull; }

    for (int k0 = 0; k0 < DM; k0 += 16) {
        float4 av = *(const float4*)(Ap + k0);
        float4 wv = *(const float4*)(Wp + k0);
        *(float2*)&As2[lk4+0][2*lm] = make_float2(av.x, av.x);
        *(float2*)&As2[lk4+1][2*lm] = make_float2(av.y, av.y);
        *(float2*)&As2[lk4+2][2*lm] = make_float2(av.z, av.z);
        *(float2*)&As2[lk4+3][2*lm] = make_float2(av.w, av.w);
        Bs[lk4+0][lm] = wv.x; Bs[lk4+1][lm] = wv.y;
        Bs[lk4+2][lm] = wv.z; Bs[lk4+3][lm] = wv.w;
        __syncthreads();

        #pragma unroll
        for (int kk = 0; kk < 16; kk++) {
            ulonglong2 a01 = *(const ulonglong2*)&As2[kk][(ty << 3)];      // (a0,a0)(a1,a1)
            ulonglong2 a23 = *(const ulonglong2*)&As2[kk][(ty << 3) + 4];  // (a2,a2)(a3,a3)
            ulonglong2 bp  = *(const ulonglong2*)&Bs[kk][(tx << 2)];       // (b0,b1)(b2,b3)
            u64t ad[4] = {a01.x, a01.y, a23.x, a23.y};
            #pragma unroll
            for (int i = 0; i < 4; i++) {
                FMA2(acc2[i][0], ad[i], bp.x, acc2[i][0]);
                FMA2(acc2[i][1], ad[i], bp.y, acc2[i][1]);
            }
        }
        __syncthreads();
    }

    const int n = n0 + (tx << 2);
    float b0 = bias[n+0], b1 = bias[n+1], b2 = bias[n+2], b3 = bias[n+3];
    #pragma unroll
    for (int i = 0; i < 4; i++) {
        int t = m0 + (ty << 2) + i;
        float2 p0 = unpack2(acc2[i][0]);
        float2 p1 = unpack2(acc2[i][1]);
        float4 r = make_float4(p0.x + b0, p0.y + b1, p1.x + b2, p1.y + b3);
        if (HEADLAYOUT) {
            int bb = t >> 11;          // t / SEQ
            int s  = t & (SEQ - 1);
            int h  = n >> 6;           // whole tile is one head (n0 multiple of 64)
            int d  = n & 63;
            *(float4*)&C[(size_t)(((bb*NH + h)*SEQ) + s)*DK + d] = r;
        } else {
            *(float4*)&C[(size_t)t * DM + n] = r;
        }
    }
}

// Fused Q/K/V projections: blockIdx.z in {0,1,2} selects which projection.
__global__ __launch_bounds__(256)
void gemm_qkv(const float* __restrict__ q_in, const float* __restrict__ k_in,
              const float* __restrict__ v_in,
              const float* __restrict__ Wq, const float* __restrict__ bq,
              const float* __restrict__ Wk, const float* __restrict__ bk,
              const float* __restrict__ Wv, const float* __restrict__ bv,
              float* __restrict__ Qh, float* __restrict__ Kh,
              float* __restrict__ Vh)
{
    const int z = blockIdx.z;
    const float* A    = (z == 0) ? q_in : (z == 1) ? k_in : v_in;
    const float* W    = (z == 0) ? Wq   : (z == 1) ? Wk   : Wv;
    const float* bias = (z == 0) ? bq   : (z == 1) ? bk   : bv;
    float*       C    = (z == 0) ? Qh   : (z == 1) ? Kh   : Vh;
    gemm_core<1>(A, W, bias, C);
}

__global__ __launch_bounds__(256)
void gemm_out(const float* __restrict__ A, const float* __restrict__ W,
              const float* __restrict__ bias, float* __restrict__ C)
{
    gemm_core<0>(A, W, bias, C);
}

// ---------------------------------------------------------------------------
// Flash attention with FFMA2 inner loops.
// Qs: [d][2q] duplicated pairs (stride 132). KVs: K as [d][k] / V as [k][d]
// (stride 68). Ps: [k][2q] duplicated pairs (stride 132).
// ---------------------------------------------------------------------------
__global__ __launch_bounds__(256)
void flash_kernel(const float* __restrict__ Qh, const float* __restrict__ Kh,
                  const float* __restrict__ Vh, const int* __restrict__ mask,
                  float* __restrict__ ctx)
{
    extern __shared__ float sm[];
    float* Qs  = sm;                     // 64 x 132 (dup pairs along q)
    float* KVs = sm + 64*132;            // 64 x 68
    float* Ps  = sm + 64*132 + 64*68;    // 64 x 132 (dup pairs along q)

    const int tid = threadIdx.x;
    const int tx  = tid & 15;
    const int ty  = tid >> 4;
    const int q0  = blockIdx.x << 6;
    const int h   = blockIdx.y;
    const int b   = blockIdx.z;

    const float* Qg = Qh + (size_t)((b*NH + h)*SEQ + q0) * DK;
    const float* Kg = Kh + (size_t)((b*NH + h)*SEQ) * DK;
    const float* Vg = Vh + (size_t)((b*NH + h)*SEQ) * DK;
    const int*   mb = mask + b * SEQ;

    // load Q tile transposed+duplicated, pre-scaled by 1/sqrt(64)
    {
        const float sc = 0.125f;
        #pragma unroll
        for (int r = 0; r < 4; r++) {
            int q  = (tid >> 4) + r*16;
            int d4 = (tid & 15) << 2;
            float4 v = *(const float4*)(Qg + (size_t)q*DK + d4);
            *(float2*)&Qs[(d4+0)*132 + 2*q] = make_float2(v.x*sc, v.x*sc);
            *(float2*)&Qs[(d4+1)*132 + 2*q] = make_float2(v.y*sc, v.y*sc);
            *(float2*)&Qs[(d4+2)*132 + 2*q] = make_float2(v.z*sc, v.z*sc);
            *(float2*)&Qs[(d4+3)*132 + 2*q] = make_float2(v.w*sc, v.w*sc);
        }
    }

    float m_[4], l_[4];
    u64t  O2[4][2];
    #pragma unroll
    for (int i = 0; i < 4; i++) {
        m_[i] = -1e30f; l_[i] = 0.f;
        O2[i][0] = 0ull; O2[i][1] = 0ull;
    }

    for (int kt = 0; kt < SEQ/64; kt++) {
        const int k0 = kt << 6;
        __syncthreads();                       // prev O-GEMM done with KVs/Ps
        // load K tile transposed: KVs[d][k]
        #pragma unroll
        for (int r = 0; r < 4; r++) {
            int k  = (tid >> 4) + r*16;
            int d4 = (tid & 15) << 2;
            float4 v = *(const float4*)(Kg + (size_t)(k0 + k)*DK + d4);
            KVs[(d4+0)*68 + k] = v.x;
            KVs[(d4+1)*68 + k] = v.y;
            KVs[(d4+2)*68 + k] = v.z;
            KVs[(d4+3)*68 + k] = v.w;
        }
        __syncthreads();

        // scores: s2[i][jp] pairs along k, FFMA2
        u64t s2[4][2];
        #pragma unroll
        for (int i = 0; i < 4; i++) { s2[i][0] = 0ull; s2[i][1] = 0ull; }

        #pragma unroll 8
        for (int d = 0; d < 64; d++) {
            ulonglong2 qa = *(const ulonglong2*)&Qs[d*132 + (ty << 3)];      // (q0,q0)(q1,q1)
            ulonglong2 qb = *(const ulonglong2*)&Qs[d*132 + (ty << 3) + 4];  // (q2,q2)(q3,q3)
            ulonglong2 kp = *(const ulonglong2*)&KVs[d*68 + (tx << 2)];      // (k0,k1)(k2,k3)
            u64t qd[4] = {qa.x, qa.y, qb.x, qb.y};
            #pragma unroll
            for (int i = 0; i < 4; i++) {
                FMA2(s2[i][0], qd[i], kp.x, s2[i][0]);
                FMA2(s2[i][1], qd[i], kp.y, s2[i][1]);
            }
        }

        // unpack scores
        float s[4][4];
        #pragma unroll
        for (int i = 0; i < 4; i++) {
            float2 f0 = unpack2(s2[i][0]);
            float2 f1 = unpack2(s2[i][1]);
            s[i][0] = f0.x; s[i][1] = f0.y; s[i][2] = f1.x; s[i][3] = f1.y;
        }

        // mask (key-only)
        int mk[4];
        #pragma unroll
        for (int j = 0; j < 4; j++) mk[j] = mb[k0 + (tx << 2) + j];
        #pragma unroll
        for (int i = 0; i < 4; i++)
            #pragma unroll
            for (int j = 0; j < 4; j++)
                if (mk[j] == 0) s[i][j] = -1.0e9f;

        // online softmax update per query row
        #pragma unroll
        for (int i = 0; i < 4; i++) {
            float rm = fmaxf(fmaxf(s[i][0], s[i][1]), fmaxf(s[i][2], s[i][3]));
            #pragma unroll
            for (int off = 8; off >= 1; off >>= 1)
                rm = fmaxf(rm, __shfl_xor_sync(0xffffffffu, rm, off));
            float nm   = fmaxf(m_[i], rm);
            float corr = __expf(m_[i] - nm);
            float rs = 0.f;
            #pragma unroll
            for (int j = 0; j < 4; j++) {
                float p = __expf(s[i][j] - nm);
                s[i][j] = p;
                rs += p;
            }
            #pragma unroll
            for (int off = 8; off >= 1; off >>= 1)
                rs += __shfl_xor_sync(0xffffffffu, rs, off);
            l_[i] = l_[i] * corr + rs;
            m_[i] = nm;
            u64t cd = pack2(corr, corr);
            MUL2(O2[i][0], O2[i][0], cd);
            MUL2(O2[i][1], O2[i][1], cd);
        }

        // store P transposed + duplicated: Ps[k][2q]
        #pragma unroll
        for (int j = 0; j < 4; j++)
            #pragma unroll
            for (int i = 0; i < 4; i++)
                *(float2*)&Ps[((tx << 2) + j)*132 + 2*((ty << 2) + i)] =
                    make_float2(s[i][j], s[i][j]);
        __syncthreads();                       // P ready; K reads done

        // load V tile (natural layout): KVs[k][d]
        #pragma unroll
        for (int r = 0; r < 4; r++) {
            int k  = (tid >> 4) + r*16;
            int d4 = (tid & 15) << 2;
            float4 v = *(const float4*)(Vg + (size_t)(k0 + k)*DK + d4);
            *(float4*)&KVs[k*68 + d4] = v;
        }
        __syncthreads();

        // O += P*V, FFMA2 (pairs along d)
        #pragma unroll 8
        for (int k = 0; k < 64; k++) {
            ulonglong2 pa = *(const ulonglong2*)&Ps[k*132 + (ty << 3)];
            ulonglong2 pb = *(const ulonglong2*)&Ps[k*132 + (ty << 3) + 4];
            ulonglong2 vp = *(const ulonglong2*)&KVs[k*68 + (tx << 2)];
            u64t pd[4] = {pa.x, pa.y, pb.x, pb.y};
            #pragma unroll
            for (int i = 0; i < 4; i++) {
                FMA2(O2[i][0], pd[i], vp.x, O2[i][0]);
                FMA2(O2[i][1], pd[i], vp.y, O2[i][1]);
            }
        }
    }

    // finalize: divide by l, write ctx in [B,S,DM] layout
    #pragma unroll
    for (int i = 0; i < 4; i++) {
        float inv = 1.0f / l_[i];
        int s = q0 + (ty << 2) + i;
        float2 o0 = unpack2(O2[i][0]);
        float2 o1 = unpack2(O2[i][1]);
        float4 r = make_float4(o0.x*inv, o0.y*inv, o1.x*inv, o1.y*inv);
        *(float4*)&ctx[(size_t)(b*SEQ + s)*DM + h*DK + (tx << 2)] = r;
    }
}

// ---------------------------------------------------------------------------
extern "C" void kernel_launch(void* const* d_in, const int* in_sizes, int n_in,
                              void* d_out, int out_size)
{
    (void)in_sizes; (void)n_in; (void)out_size;
    const float* query = (const float*)d_in[0];
    const float* key_  = (const float*)d_in[1];
    const float* value = (const float*)d_in[2];
    const int*   mask  = (const int*)  d_in[3];
    const float* Wq = (const float*)d_in[4];
    const float* bq = (const float*)d_in[5];
    const float* Wk = (const float*)d_in[6];
    const float* bk = (const float*)d_in[7];
    const float* Wv = (const float*)d_in[8];
    const float* bv = (const float*)d_in[9];
    const float* Wo = (const float*)d_in[10];
    const float* bo = (const float*)d_in[11];
    float* out = (float*)d_out;

    float *Qh, *Kh, *Vh, *ctx;
    cudaGetSymbolAddress((void**)&Qh,  g_Qh);
    cudaGetSymbolAddress((void**)&Kh,  g_Kh);
    cudaGetSymbolAddress((void**)&Vh,  g_Vh);
    cudaGetSymbolAddress((void**)&ctx, g_ctx);

    gemm_qkv<<<dim3(DM/64, TOK/64, 3), 256>>>(query, key_, value,
                                              Wq, bq, Wk, bk, Wv, bv,
                                              Qh, Kh, Vh);

    size_t shm = (size_t)(64*132 + 64*68 + 64*132) * sizeof(float);  // 84992 B
    cudaFuncSetAttribute(flash_kernel,
                         cudaFuncAttributeMaxDynamicSharedMemorySize, (int)shm);
    flash_kernel<<<dim3(SEQ/64, NH, BB), 256, shm>>>(Qh, Kh, Vh, mask, ctx);

    gemm_out<<<dim3(DM/64, TOK/64), 256>>>(ctx, Wo, bo, out);
}

// round 5
// speedup vs baseline: 1.4283x; 1.4283x over previous
#include <cuda_runtime.h>
#include <math.h>

#define DM   1024
#define NH   16
#define DK   64
#define SEQ  2048
#define BB   2
#define TOK  (BB*SEQ)   // 4096

// ---------------- scratch (__device__ globals; no allocation allowed) -------
__device__ float g_Qh[BB*NH*SEQ*DK];   // [B,H,S,DK]
__device__ float g_Kh[BB*NH*SEQ*DK];
__device__ float g_Vh[BB*NH*SEQ*DK];
__device__ float g_ctx[TOK*DM];        // [B,S,DM]

// ---------------------------------------------------------------------------
// GEMM: C = A[M,DM] @ W[N,DM]^T + bias.
// 128x128 CTA tile, BK=16, 256 threads, 8x8 register microtile (1.0 B/FMA
// of shared traffic -- half of the 4x4 version that was crossbar-bound).
// HEADLAYOUT=1: write [B,H,S,DK]; 0: plain [t,n].
// ---------------------------------------------------------------------------
template<int HEADLAYOUT>
__device__ __forceinline__
void gemm_core(const float* __restrict__ A, const float* __restrict__ W,
               const float* __restrict__ bias, float* __restrict__ C)
{
    __shared__ float As[16][132];   // [k][m], m=128 + pad
    __shared__ float Bs[16][132];   // [k][n]

    const int tid = threadIdx.x;
    const int tx  = tid & 15;            // n sub (8-wide)
    const int ty  = tid >> 4;            // m sub (8-wide)
    const int m0  = blockIdx.y << 7;
    const int n0  = blockIdx.x << 7;

    const int lm  = tid >> 1;            // 0..127 row within tile
    const int lk8 = (tid & 1) << 3;      // 0 or 8

    const float* Ap = A + (size_t)(m0 + lm) * DM + lk8;
    const float* Wp = W + (size_t)(n0 + lm) * DM + lk8;

    float acc[8][8];
    #pragma unroll
    for (int i = 0; i < 8; i++)
        #pragma unroll
        for (int j = 0; j < 8; j++) acc[i][j] = 0.f;

    for (int k0 = 0; k0 < DM; k0 += 16) {
        float4 a0 = *(const float4*)(Ap + k0);
        float4 a1 = *(const float4*)(Ap + k0 + 4);
        float4 w0 = *(const float4*)(Wp + k0);
        float4 w1 = *(const float4*)(Wp + k0 + 4);
        As[lk8+0][lm] = a0.x; As[lk8+1][lm] = a0.y;
        As[lk8+2][lm] = a0.z; As[lk8+3][lm] = a0.w;
        As[lk8+4][lm] = a1.x; As[lk8+5][lm] = a1.y;
        As[lk8+6][lm] = a1.z; As[lk8+7][lm] = a1.w;
        Bs[lk8+0][lm] = w0.x; Bs[lk8+1][lm] = w0.y;
        Bs[lk8+2][lm] = w0.z; Bs[lk8+3][lm] = w0.w;
        Bs[lk8+4][lm] = w1.x; Bs[lk8+5][lm] = w1.y;
        Bs[lk8+6][lm] = w1.z; Bs[lk8+7][lm] = w1.w;
        __syncthreads();

        #pragma unroll
        for (int kk = 0; kk < 16; kk++) {
            float4 va0 = *(const float4*)&As[kk][(ty << 3)];
            float4 va1 = *(const float4*)&As[kk][(ty << 3) + 4];
            float4 vb0 = *(const float4*)&Bs[kk][(tx << 3)];
            float4 vb1 = *(const float4*)&Bs[kk][(tx << 3) + 4];
            float am[8] = {va0.x, va0.y, va0.z, va0.w, va1.x, va1.y, va1.z, va1.w};
            float bn[8] = {vb0.x, vb0.y, vb0.z, vb0.w, vb1.x, vb1.y, vb1.z, vb1.w};
            #pragma unroll
            for (int i = 0; i < 8; i++)
                #pragma unroll
                for (int j = 0; j < 8; j++)
                    acc[i][j] = fmaf(am[i], bn[j], acc[i][j]);
        }
        __syncthreads();
    }

    const int nb = n0 + (tx << 3);
    float bb_[8];
    #pragma unroll
    for (int j = 0; j < 8; j++) bb_[j] = bias[nb + j];

    #pragma unroll
    for (int i = 0; i < 8; i++) {
        int t = m0 + (ty << 3) + i;
        float4 r0 = make_float4(acc[i][0]+bb_[0], acc[i][1]+bb_[1],
                                acc[i][2]+bb_[2], acc[i][3]+bb_[3]);
        float4 r1 = make_float4(acc[i][4]+bb_[4], acc[i][5]+bb_[5],
                                acc[i][6]+bb_[6], acc[i][7]+bb_[7]);
        if (HEADLAYOUT) {
            int bbx = t >> 11;           // t / SEQ
            int s   = t & (SEQ - 1);
            int h   = nb >> 6;           // 8-col slice never straddles a head
            int d   = nb & 63;
            float* dst = &C[(size_t)(((bbx*NH + h)*SEQ) + s)*DK + d];
            *(float4*)(dst)     = r0;
            *(float4*)(dst + 4) = r1;
        } else {
            float* dst = &C[(size_t)t * DM + nb];
            *(float4*)(dst)     = r0;
            *(float4*)(dst + 4) = r1;
        }
    }
}

// Fused Q/K/V projections: blockIdx.z in {0,1,2} selects which projection.
__global__ __launch_bounds__(256)
void gemm_qkv(const float* __restrict__ q_in, const float* __restrict__ k_in,
              const float* __restrict__ v_in,
              const float* __restrict__ Wq, const float* __restrict__ bq,
              const float* __restrict__ Wk, const float* __restrict__ bk,
              const float* __restrict__ Wv, const float* __restrict__ bv,
              float* __restrict__ Qh, float* __restrict__ Kh,
              float* __restrict__ Vh)
{
    const int z = blockIdx.z;
    const float* A    = (z == 0) ? q_in : (z == 1) ? k_in : v_in;
    const float* W    = (z == 0) ? Wq   : (z == 1) ? Wk   : Wv;
    const float* bias = (z == 0) ? bq   : (z == 1) ? bk   : bv;
    float*       C    = (z == 0) ? Qh   : (z == 1) ? Kh   : Vh;
    gemm_core<1>(A, W, bias, C);
}

__global__ __launch_bounds__(256)
void gemm_out(const float* __restrict__ A, const float* __restrict__ W,
              const float* __restrict__ bias, float* __restrict__ C)
{
    gemm_core<0>(A, W, bias, C);
}

// ---------------------------------------------------------------------------
// Flash attention: one block = (b, h, 128-query tile), 64-key tiles.
// 256 threads; 8q x 4k microtile for QK^T, 8q x 4d for PV.
// Q pre-scaled by 1/sqrt(DK). Mask key-only; masked scores -> exactly -1e9.
// ---------------------------------------------------------------------------
__global__ __launch_bounds__(256)
void flash_kernel(const float* __restrict__ Qh, const float* __restrict__ Kh,
                  const float* __restrict__ Vh, const int* __restrict__ mask,
                  float* __restrict__ ctx)
{
    extern __shared__ float sm[];
    float* Qs  = sm;                     // [d][q]  64 x 132 (transposed)
    float* Ps  = sm + 64*132;            // [k][q]  64 x 132 (transposed)
    float* KVs = sm + 2*64*132;          // K: [d][k] / V: [k][d], 64 x 68

    const int tid = threadIdx.x;
    const int tx  = tid & 15;            // 4-wide (k in QK, d in PV)
    const int ty  = tid >> 4;            // 8-wide (q)
    const int q0  = blockIdx.x << 7;
    const int h   = blockIdx.y;
    const int b   = blockIdx.z;

    const float* Qg = Qh + (size_t)((b*NH + h)*SEQ + q0) * DK;
    const float* Kg = Kh + (size_t)((b*NH + h)*SEQ) * DK;
    const float* Vg = Vh + (size_t)((b*NH + h)*SEQ) * DK;
    const int*   mb = mask + b * SEQ;

    // load Q tile (128 x 64) transposed, pre-scaled by 1/sqrt(64)
    {
        const float sc = 0.125f;
        #pragma unroll
        for (int r = 0; r < 8; r++) {
            int q  = (tid >> 4) + r*16;          // 0..127
            int d4 = (tid & 15) << 2;
            float4 v = *(const float4*)(Qg + (size_t)q*DK + d4);
            Qs[(d4+0)*132 + q] = v.x * sc;
            Qs[(d4+1)*132 + q] = v.y * sc;
            Qs[(d4+2)*132 + q] = v.z * sc;
            Qs[(d4+3)*132 + q] = v.w * sc;
        }
    }

    float m_[8], l_[8], O[8][4];
    #pragma unroll
    for (int i = 0; i < 8; i++) {
        m_[i] = -1e30f; l_[i] = 0.f;
        #pragma unroll
        for (int j = 0; j < 4; j++) O[i][j] = 0.f;
    }

    for (int kt = 0; kt < SEQ/64; kt++) {
        const int k0 = kt << 6;
        __syncthreads();                       // prev PV done with KVs/Ps
        // load K tile transposed: KVs[d][k]
        #pragma unroll
        for (int r = 0; r < 4; r++) {
            int k  = (tid >> 4) + r*16;
            int d4 = (tid & 15) << 2;
            float4 v = *(const float4*)(Kg + (size_t)(k0 + k)*DK + d4);
            KVs[(d4+0)*68 + k] = v.x;
            KVs[(d4+1)*68 + k] = v.y;
            KVs[(d4+2)*68 + k] = v.z;
            KVs[(d4+3)*68 + k] = v.w;
        }
        __syncthreads();

        // scores s[8q][4k]
        float s[8][4];
        #pragma unroll
        for (int i = 0; i < 8; i++)
            #pragma unroll
            for (int j = 0; j < 4; j++) s[i][j] = 0.f;

        #pragma unroll 4
        for (int d = 0; d < 64; d++) {
            float4 qa = *(const float4*)&Qs[d*132 + (ty << 3)];
            float4 qb = *(const float4*)&Qs[d*132 + (ty << 3) + 4];
            float4 kp = *(const float4*)&KVs[d*68 + (tx << 2)];
            float qr[8] = {qa.x, qa.y, qa.z, qa.w, qb.x, qb.y, qb.z, qb.w};
            float kr[4] = {kp.x, kp.y, kp.z, kp.w};
            #pragma unroll
            for (int i = 0; i < 8; i++)
                #pragma unroll
                for (int j = 0; j < 4; j++)
                    s[i][j] = fmaf(qr[i], kr[j], s[i][j]);
        }

        // mask (key-only)
        int mk[4];
        #pragma unroll
        for (int j = 0; j < 4; j++) mk[j] = mb[k0 + (tx << 2) + j];
        #pragma unroll
        for (int i = 0; i < 8; i++)
            #pragma unroll
            for (int j = 0; j < 4; j++)
                if (mk[j] == 0) s[i][j] = -1.0e9f;

        // online softmax per query row (reduce across 16 tx lanes)
        #pragma unroll
        for (int i = 0; i < 8; i++) {
            float rm = fmaxf(fmaxf(s[i][0], s[i][1]), fmaxf(s[i][2], s[i][3]));
            #pragma unroll
            for (int off = 8; off >= 1; off >>= 1)
                rm = fmaxf(rm, __shfl_xor_sync(0xffffffffu, rm, off));
            float nm   = fmaxf(m_[i], rm);
            float corr = __expf(m_[i] - nm);
            float rs = 0.f;
            #pragma unroll
            for (int j = 0; j < 4; j++) {
                float p = __expf(s[i][j] - nm);
                s[i][j] = p;
                rs += p;
            }
            #pragma unroll
            for (int off = 8; off >= 1; off >>= 1)
                rs += __shfl_xor_sync(0xffffffffu, rs, off);
            l_[i] = l_[i] * corr + rs;
            m_[i] = nm;
            #pragma unroll
            for (int j = 0; j < 4; j++) O[i][j] *= corr;
        }

        // store P transposed: Ps[k][q]
        #pragma unroll
        for (int j = 0; j < 4; j++)
            #pragma unroll
            for (int i = 0; i < 8; i++)
                Ps[((tx << 2) + j)*132 + (ty << 3) + i] = s[i][j];
        __syncthreads();                       // P ready; K reads done

        // load V tile (natural layout): KVs[k][d]
        #pragma unroll
        for (int r = 0; r < 4; r++) {
            int k  = (tid >> 4) + r*16;
            int d4 = (tid & 15) << 2;
            float4 v = *(const float4*)(Vg + (size_t)(k0 + k)*DK + d4);
            *(float4*)&KVs[k*68 + d4] = v;
        }
        __syncthreads();

        // O += P*V over 64 keys
        #pragma unroll 4
        for (int k = 0; k < 64; k++) {
            float4 pa = *(const float4*)&Ps[k*132 + (ty << 3)];
            float4 pb = *(const float4*)&Ps[k*132 + (ty << 3) + 4];
            float4 vp = *(const float4*)&KVs[k*68 + (tx << 2)];
            float pr[8] = {pa.x, pa.y, pa.z, pa.w, pb.x, pb.y, pb.z, pb.w};
            float vr[4] = {vp.x, vp.y, vp.z, vp.w};
            #pragma unroll
            for (int i = 0; i < 8; i++)
                #pragma unroll
                for (int j = 0; j < 4; j++)
                    O[i][j] = fmaf(pr[i], vr[j], O[i][j]);
        }
    }

    // finalize: divide by l, write ctx in [B,S,DM] layout
    #pragma unroll
    for (int i = 0; i < 8; i++) {
        float inv = 1.0f / l_[i];
        int s = q0 + (ty << 3) + i;
        float4 r = make_float4(O[i][0]*inv, O[i][1]*inv, O[i][2]*inv, O[i][3]*inv);
        *(float4*)&ctx[(size_t)(b*SEQ + s)*DM + h*DK + (tx << 2)] = r;
    }
}

// ---------------------------------------------------------------------------
extern "C" void kernel_launch(void* const* d_in, const int* in_sizes, int n_in,
                              void* d_out, int out_size)
{
    (void)in_sizes; (void)n_in; (void)out_size;
    const float* query = (const float*)d_in[0];
    const float* key_  = (const float*)d_in[1];
    const float* value = (const float*)d_in[2];
    const int*   mask  = (const int*)  d_in[3];
    const float* Wq = (const float*)d_in[4];
    const float* bq = (const float*)d_in[5];
    const float* Wk = (const float*)d_in[6];
    const float* bk = (const float*)d_in[7];
    const float* Wv = (const float*)d_in[8];
    const float* bv = (const float*)d_in[9];
    const float* Wo = (const float*)d_in[10];
    const float* bo = (const float*)d_in[11];
    float* out = (float*)d_out;

    float *Qh, *Kh, *Vh, *ctx;
    cudaGetSymbolAddress((void**)&Qh,  g_Qh);
    cudaGetSymbolAddress((void**)&Kh,  g_Kh);
    cudaGetSymbolAddress((void**)&Vh,  g_Vh);
    cudaGetSymbolAddress((void**)&ctx, g_ctx);

    // Fused QKV projections: 128x128 tiles -> (8, 32, 3)
    gemm_qkv<<<dim3(DM/128, TOK/128, 3), 256>>>(query, key_, value,
                                                Wq, bq, Wk, bk, Wv, bv,
                                                Qh, Kh, Vh);

    size_t shm = (size_t)(2*64*132 + 64*68) * sizeof(float);   // 84992 B
    cudaFuncSetAttribute(flash_kernel,
                         cudaFuncAttributeMaxDynamicSharedMemorySize, (int)shm);
    flash_kernel<<<dim3(SEQ/128, NH, BB), 256, shm>>>(Qh, Kh, Vh, mask, ctx);

    gemm_out<<<dim3(DM/128, TOK/128), 256>>>(ctx, Wo, bo, out);
}

// round 6
// speedup vs baseline: 1.4465x; 1.0127x over previous
#include <cuda_runtime.h>
#include <math.h>

#define DM   1024
#define NH   16
#define DK   64
#define SEQ  2048
#define BB   2
#define TOK  (BB*SEQ)   // 4096

// ---------------- scratch (__device__ globals; no allocation allowed) -------
__device__ float g_Qh[BB*NH*SEQ*DK];   // [B,H,S,DK]
__device__ float g_Kh[BB*NH*SEQ*DK];
__device__ float g_Vh[BB*NH*SEQ*DK];
__device__ float g_ctx[TOK*DM];        // [B,S,DM]

// ---- tf32 helpers ----------------------------------------------------------
__device__ __forceinline__ unsigned f2tf(float f) {
    unsigned r; asm("cvt.rna.tf32.f32 %0, %1;" : "=r"(r) : "f"(f)); return r;
}
__device__ __forceinline__ void mma8(float d[4], const unsigned a[4],
                                     const unsigned b[2]) {
    asm("mma.sync.aligned.m16n8k8.row.col.f32.tf32.tf32.f32 "
        "{%0,%1,%2,%3}, {%4,%5,%6,%7}, {%8,%9}, {%0,%1,%2,%3};"
        : "+f"(d[0]), "+f"(d[1]), "+f"(d[2]), "+f"(d[3])
        : "r"(a[0]), "r"(a[1]), "r"(a[2]), "r"(a[3]), "r"(b[0]), "r"(b[1]));
}

// ---------------------------------------------------------------------------
// 3xTF32 tensor-core GEMM: C = A[M,DM] @ W[N,DM]^T + bias.
// 128x128 CTA tile, BK=16, 256 threads = 8 warps (2 m-warps x 4 n-warps),
// warp tile 64x32 via m16n8k8 (4 mi x 4 ni). Operands split hi/lo in smem;
// 3 HMMAs (hi*hi, hi*lo, lo*hi) recover ~fp32 precision (err ~2^-22).
// HEADLAYOUT=1: write [B,H,S,DK]; 0: plain [t,n].
// ---------------------------------------------------------------------------
template<int HEADLAYOUT>
__device__ __forceinline__
void gemm_tf32_core(const float* __restrict__ A, const float* __restrict__ W,
                    const float* __restrict__ bias, float* __restrict__ C)
{
    __shared__ unsigned Ah[128][20];   // [m][k] tf32-hi (stride 20 = conflict-free)
    __shared__ unsigned Al[128][20];   // [m][k] tf32-lo
    __shared__ unsigned Bh[128][20];   // [n][k] tf32-hi
    __shared__ unsigned Bl[128][20];   // [n][k] tf32-lo

    const int tid  = threadIdx.x;
    const int lane = tid & 31;
    const int warp = tid >> 5;
    const int wm   = warp >> 2;        // 0..1 : 64-row slice
    const int wn   = warp & 3;         // 0..3 : 32-col slice
    const int gid  = lane >> 2;        // 0..7
    const int qid  = lane & 3;         // 0..3
    const int m0   = blockIdx.y << 7;
    const int n0   = blockIdx.x << 7;

    const int lm  = tid >> 1;          // 0..127
    const int lk8 = (tid & 1) << 3;    // 0 or 8

    const float* Ap = A + (size_t)(m0 + lm) * DM + lk8;
    const float* Wp = W + (size_t)(n0 + lm) * DM + lk8;

    float acc[4][4][4];
    #pragma unroll
    for (int mi = 0; mi < 4; mi++)
        #pragma unroll
        for (int ni = 0; ni < 4; ni++)
            #pragma unroll
            for (int r = 0; r < 4; r++) acc[mi][ni][r] = 0.f;

    for (int k0 = 0; k0 < DM; k0 += 16) {
        // ---- stage: load 8 floats of A and W, split to tf32 hi/lo ----
        float av[8], wv[8];
        {
            float4 t0 = *(const float4*)(Ap + k0);
            float4 t1 = *(const float4*)(Ap + k0 + 4);
            av[0]=t0.x; av[1]=t0.y; av[2]=t0.z; av[3]=t0.w;
            av[4]=t1.x; av[5]=t1.y; av[6]=t1.z; av[7]=t1.w;
            float4 u0 = *(const float4*)(Wp + k0);
            float4 u1 = *(const float4*)(Wp + k0 + 4);
            wv[0]=u0.x; wv[1]=u0.y; wv[2]=u0.z; wv[3]=u0.w;
            wv[4]=u1.x; wv[5]=u1.y; wv[6]=u1.z; wv[7]=u1.w;
        }
        unsigned ahv[8], alv[8], bhv[8], blv[8];
        #pragma unroll
        for (int j = 0; j < 8; j++) {
            unsigned h = f2tf(av[j]);
            ahv[j] = h;
            alv[j] = f2tf(av[j] - __uint_as_float(h));
            unsigned g = f2tf(wv[j]);
            bhv[j] = g;
            blv[j] = f2tf(wv[j] - __uint_as_float(g));
        }
        __syncthreads();   // prev iter's frag reads done before overwrite
        *(uint4*)&Ah[lm][lk8]     = make_uint4(ahv[0],ahv[1],ahv[2],ahv[3]);
        *(uint4*)&Ah[lm][lk8 + 4] = make_uint4(ahv[4],ahv[5],ahv[6],ahv[7]);
        *(uint4*)&Al[lm][lk8]     = make_uint4(alv[0],alv[1],alv[2],alv[3]);
        *(uint4*)&Al[lm][lk8 + 4] = make_uint4(alv[4],alv[5],alv[6],alv[7]);
        *(uint4*)&Bh[lm][lk8]     = make_uint4(bhv[0],bhv[1],bhv[2],bhv[3]);
        *(uint4*)&Bh[lm][lk8 + 4] = make_uint4(bhv[4],bhv[5],bhv[6],bhv[7]);
        *(uint4*)&Bl[lm][lk8]     = make_uint4(blv[0],blv[1],blv[2],blv[3]);
        *(uint4*)&Bl[lm][lk8 + 4] = make_uint4(blv[4],blv[5],blv[6],blv[7]);
        __syncthreads();

        // ---- compute: 2 k8-steps ----
        #pragma unroll
        for (int ks = 0; ks < 2; ks++) {
            unsigned afh[4][4], afl[4][4];
            #pragma unroll
            for (int mi = 0; mi < 4; mi++) {
                int row = wm*64 + mi*16 + gid;
                #pragma unroll
                for (int r = 0; r < 4; r++) {
                    int rr = row + ((r & 1) << 3);
                    int kk = (ks << 3) + qid + ((r >> 1) << 2);
                    afh[mi][r] = Ah[rr][kk];
                    afl[mi][r] = Al[rr][kk];
                }
            }
            #pragma unroll
            for (int ni = 0; ni < 4; ni++) {
                int col = wn*32 + ni*8 + gid;
                unsigned bfh[2], bfl[2];
                #pragma unroll
                for (int r = 0; r < 2; r++) {
                    int kk = (ks << 3) + qid + (r << 2);
                    bfh[r] = Bh[col][kk];
                    bfl[r] = Bl[col][kk];
                }
                #pragma unroll
                for (int mi = 0; mi < 4; mi++) {
                    mma8(acc[mi][ni], afh[mi], bfh);
                    mma8(acc[mi][ni], afh[mi], bfl);
                    mma8(acc[mi][ni], afl[mi], bfh);
                }
            }
        }
    }

    // ---- epilogue: bias + store (float2 per fragment half) ----
    #pragma unroll
    for (int mi = 0; mi < 4; mi++) {
        #pragma unroll
        for (int ni = 0; ni < 4; ni++) {
            int row = m0 + wm*64 + mi*16 + gid;
            int col = n0 + wn*32 + ni*8 + (qid << 1);
            float b0 = bias[col], b1 = bias[col + 1];
            float2 v0 = make_float2(acc[mi][ni][0] + b0, acc[mi][ni][1] + b1);
            float2 v1 = make_float2(acc[mi][ni][2] + b0, acc[mi][ni][3] + b1);
            if (HEADLAYOUT) {
                int h = col >> 6, d = col & 63;
                {
                    int t = row, bbx = t >> 11, s = t & (SEQ - 1);
                    *(float2*)&C[(size_t)(((bbx*NH + h)*SEQ) + s)*DK + d] = v0;
                }
                {
                    int t = row + 8, bbx = t >> 11, s = t & (SEQ - 1);
                    *(float2*)&C[(size_t)(((bbx*NH + h)*SEQ) + s)*DK + d] = v1;
                }
            } else {
                *(float2*)&C[(size_t)row       * DM + col] = v0;
                *(float2*)&C[(size_t)(row + 8) * DM + col] = v1;
            }
        }
    }
}

// Fused Q/K/V projections: blockIdx.z in {0,1,2} selects which projection.
__global__ __launch_bounds__(256)
void gemm_qkv(const float* __restrict__ q_in, const float* __restrict__ k_in,
              const float* __restrict__ v_in,
              const float* __restrict__ Wq, const float* __restrict__ bq,
              const float* __restrict__ Wk, const float* __restrict__ bk,
              const float* __restrict__ Wv, const float* __restrict__ bv,
              float* __restrict__ Qh, float* __restrict__ Kh,
              float* __restrict__ Vh)
{
    const int z = blockIdx.z;
    const float* A    = (z == 0) ? q_in : (z == 1) ? k_in : v_in;
    const float* W    = (z == 0) ? Wq   : (z == 1) ? Wk   : Wv;
    const float* bias = (z == 0) ? bq   : (z == 1) ? bk   : bv;
    float*       C    = (z == 0) ? Qh   : (z == 1) ? Kh   : Vh;
    gemm_tf32_core<1>(A, W, bias, C);
}

__global__ __launch_bounds__(256)
void gemm_out(const float* __restrict__ A, const float* __restrict__ W,
              const float* __restrict__ bias, float* __restrict__ C)
{
    gemm_tf32_core<0>(A, W, bias, C);
}

// ---------------------------------------------------------------------------
// Flash attention (unchanged from R5 -- known good): one block = (b, h,
// 128-query tile), 64-key tiles, 256 threads, 8q x 4k microtile.
// ---------------------------------------------------------------------------
__global__ __launch_bounds__(256)
void flash_kernel(const float* __restrict__ Qh, const float* __restrict__ Kh,
                  const float* __restrict__ Vh, const int* __restrict__ mask,
                  float* __restrict__ ctx)
{
    extern __shared__ float sm[];
    float* Qs  = sm;                     // [d][q]  64 x 132 (transposed)
    float* Ps  = sm + 64*132;            // [k][q]  64 x 132 (transposed)
    float* KVs = sm + 2*64*132;          // K: [d][k] / V: [k][d], 64 x 68

    const int tid = threadIdx.x;
    const int tx  = tid & 15;
    const int ty  = tid >> 4;
    const int q0  = blockIdx.x << 7;
    const int h   = blockIdx.y;
    const int b   = blockIdx.z;

    const float* Qg = Qh + (size_t)((b*NH + h)*SEQ + q0) * DK;
    const float* Kg = Kh + (size_t)((b*NH + h)*SEQ) * DK;
    const float* Vg = Vh + (size_t)((b*NH + h)*SEQ) * DK;
    const int*   mb = mask + b * SEQ;

    {
        const float sc = 0.125f;
        #pragma unroll
        for (int r = 0; r < 8; r++) {
            int q  = (tid >> 4) + r*16;
            int d4 = (tid & 15) << 2;
            float4 v = *(const float4*)(Qg + (size_t)q*DK + d4);
            Qs[(d4+0)*132 + q] = v.x * sc;
            Qs[(d4+1)*132 + q] = v.y * sc;
            Qs[(d4+2)*132 + q] = v.z * sc;
            Qs[(d4+3)*132 + q] = v.w * sc;
        }
    }

    float m_[8], l_[8], O[8][4];
    #pragma unroll
    for (int i = 0; i < 8; i++) {
        m_[i] = -1e30f; l_[i] = 0.f;
        #pragma unroll
        for (int j = 0; j < 4; j++) O[i][j] = 0.f;
    }

    for (int kt = 0; kt < SEQ/64; kt++) {
        const int k0 = kt << 6;
        __syncthreads();
        #pragma unroll
        for (int r = 0; r < 4; r++) {
            int k  = (tid >> 4) + r*16;
            int d4 = (tid & 15) << 2;
            float4 v = *(const float4*)(Kg + (size_t)(k0 + k)*DK + d4);
            KVs[(d4+0)*68 + k] = v.x;
            KVs[(d4+1)*68 + k] = v.y;
            KVs[(d4+2)*68 + k] = v.z;
            KVs[(d4+3)*68 + k] = v.w;
        }
        __syncthreads();

        float s[8][4];
        #pragma unroll
        for (int i = 0; i < 8; i++)
            #pragma unroll
            for (int j = 0; j < 4; j++) s[i][j] = 0.f;

        #pragma unroll 4
        for (int d = 0; d < 64; d++) {
            float4 qa = *(const float4*)&Qs[d*132 + (ty << 3)];
            float4 qb = *(const float4*)&Qs[d*132 + (ty << 3) + 4];
            float4 kp = *(const float4*)&KVs[d*68 + (tx << 2)];
            float qr[8] = {qa.x, qa.y, qa.z, qa.w, qb.x, qb.y, qb.z, qb.w};
            float kr[4] = {kp.x, kp.y, kp.z, kp.w};
            #pragma unroll
            for (int i = 0; i < 8; i++)
                #pragma unroll
                for (int j = 0; j < 4; j++)
                    s[i][j] = fmaf(qr[i], kr[j], s[i][j]);
        }

        int mk[4];
        #pragma unroll
        for (int j = 0; j < 4; j++) mk[j] = mb[k0 + (tx << 2) + j];
        #pragma unroll
        for (int i = 0; i < 8; i++)
            #pragma unroll
            for (int j = 0; j < 4; j++)
                if (mk[j] == 0) s[i][j] = -1.0e9f;

        #pragma unroll
        for (int i = 0; i < 8; i++) {
            float rm = fmaxf(fmaxf(s[i][0], s[i][1]), fmaxf(s[i][2], s[i][3]));
            #pragma unroll
            for (int off = 8; off >= 1; off >>= 1)
                rm = fmaxf(rm, __shfl_xor_sync(0xffffffffu, rm, off));
            float nm   = fmaxf(m_[i], rm);
            float corr = __expf(m_[i] - nm);
            float rs = 0.f;
            #pragma unroll
            for (int j = 0; j < 4; j++) {
                float p = __expf(s[i][j] - nm);
                s[i][j] = p;
                rs += p;
            }
            #pragma unroll
            for (int off = 8; off >= 1; off >>= 1)
                rs += __shfl_xor_sync(0xffffffffu, rs, off);
            l_[i] = l_[i] * corr + rs;
            m_[i] = nm;
            #pragma unroll
            for (int j = 0; j < 4; j++) O[i][j] *= corr;
        }

        #pragma unroll
        for (int j = 0; j < 4; j++)
            #pragma unroll
            for (int i = 0; i < 8; i++)
                Ps[((tx << 2) + j)*132 + (ty << 3) + i] = s[i][j];
        __syncthreads();

        #pragma unroll
        for (int r = 0; r < 4; r++) {
            int k  = (tid >> 4) + r*16;
            int d4 = (tid & 15) << 2;
            float4 v = *(const float4*)(Vg + (size_t)(k0 + k)*DK + d4);
            *(float4*)&KVs[k*68 + d4] = v;
        }
        __syncthreads();

        #pragma unroll 4
        for (int k = 0; k < 64; k++) {
            float4 pa = *(const float4*)&Ps[k*132 + (ty << 3)];
            float4 pb = *(const float4*)&Ps[k*132 + (ty << 3) + 4];
            float4 vp = *(const float4*)&KVs[k*68 + (tx << 2)];
            float pr[8] = {pa.x, pa.y, pa.z, pa.w, pb.x, pb.y, pb.z, pb.w};
            float vr[4] = {vp.x, vp.y, vp.z, vp.w};
            #pragma unroll
            for (int i = 0; i < 8; i++)
                #pragma unroll
                for (int j = 0; j < 4; j++)
                    O[i][j] = fmaf(pr[i], vr[j], O[i][j]);
        }
    }

    #pragma unroll
    for (int i = 0; i < 8; i++) {
        float inv = 1.0f / l_[i];
        int s = q0 + (ty << 3) + i;
        float4 r = make_float4(O[i][0]*inv, O[i][1]*inv, O[i][2]*inv, O[i][3]*inv);
        *(float4*)&ctx[(size_t)(b*SEQ + s)*DM + h*DK + (tx << 2)] = r;
    }
}

// ---------------------------------------------------------------------------
extern "C" void kernel_launch(void* const* d_in, const int* in_sizes, int n_in,
                              void* d_out, int out_size)
{
    (void)in_sizes; (void)n_in; (void)out_size;
    const float* query = (const float*)d_in[0];
    const float* key_  = (const float*)d_in[1];
    const float* value = (const float*)d_in[2];
    const int*   mask  = (const int*)  d_in[3];
    const float* Wq = (const float*)d_in[4];
    const float* bq = (const float*)d_in[5];
    const float* Wk = (const float*)d_in[6];
    const float* bk = (const float*)d_in[7];
    const float* Wv = (const float*)d_in[8];
    const float* bv = (const float*)d_in[9];
    const float* Wo = (const float*)d_in[10];
    const float* bo = (const float*)d_in[11];
    float* out = (float*)d_out;

    float *Qh, *Kh, *Vh, *ctx;
    cudaGetSymbolAddress((void**)&Qh,  g_Qh);
    cudaGetSymbolAddress((void**)&Kh,  g_Kh);
    cudaGetSymbolAddress((void**)&Vh,  g_Vh);
    cudaGetSymbolAddress((void**)&ctx, g_ctx);

    gemm_qkv<<<dim3(DM/128, TOK/128, 3), 256>>>(query, key_, value,
                                                Wq, bq, Wk, bk, Wv, bv,
                                                Qh, Kh, Vh);

    size_t shm = (size_t)(2*64*132 + 64*68) * sizeof(float);   // 84992 B
    cudaFuncSetAttribute(flash_kernel,
                         cudaFuncAttributeMaxDynamicSharedMemorySize, (int)shm);
    flash_kernel<<<dim3(SEQ/128, NH, BB), 256, shm>>>(Qh, Kh, Vh, mask, ctx);

    gemm_out<<<dim3(DM/128, TOK/128), 256>>>(ctx, Wo, bo, out);
}

// round 7
// speedup vs baseline: 1.9617x; 1.3562x over previous
#include <cuda_runtime.h>
#include <cuda_bf16.h>
#include <math.h>

#define DM   1024
#define NH   16
#define DK   64
#define SEQ  2048
#define BB   2
#define TOK  (BB*SEQ)   // 4096

// ---------------- scratch (__device__ globals; no allocation allowed) -------
__device__ float g_Qh[BB*NH*SEQ*DK];   // [B,H,S,DK]
__device__ float g_Kh[BB*NH*SEQ*DK];
__device__ float g_Vh[BB*NH*SEQ*DK];
__device__ float g_ctx[TOK*DM];        // [B,S,DM]

// bf16 hi/lo split scratch
__device__ __nv_bfloat16 g_Xh[3*TOK*DM];   // q,k,v inputs (hi)
__device__ __nv_bfloat16 g_Xl[3*TOK*DM];   // (lo)
__device__ __nv_bfloat16 g_WWh[4*DM*DM];   // Wq,Wk,Wv,Wo (hi)
__device__ __nv_bfloat16 g_WWl[4*DM*DM];   // (lo)
__device__ __nv_bfloat16 g_Ch[TOK*DM];     // ctx (hi)
__device__ __nv_bfloat16 g_Cl[TOK*DM];     // ctx (lo)

// ---------------------------------------------------------------------------
// Elementwise bf16 hi/lo split: hi = bf16(x), lo = bf16(x - float(hi)).
// ---------------------------------------------------------------------------
__global__ __launch_bounds__(256)
void split_bf16(const float* __restrict__ x,
                __nv_bfloat16* __restrict__ hi,
                __nv_bfloat16* __restrict__ lo, int n4)
{
    int i = blockIdx.x * blockDim.x + threadIdx.x;
    if (i >= n4) return;
    float4 v = ((const float4*)x)[i];
    float vv[4] = {v.x, v.y, v.z, v.w};
    __nv_bfloat16 h[4], l[4];
    #pragma unroll
    for (int j = 0; j < 4; j++) {
        h[j] = __float2bfloat16(vv[j]);
        l[j] = __float2bfloat16(vv[j] - __bfloat162float(h[j]));
    }
    ((__nv_bfloat162*)hi)[2*i]   = __halves2bfloat162(h[0], h[1]);
    ((__nv_bfloat162*)hi)[2*i+1] = __halves2bfloat162(h[2], h[3]);
    ((__nv_bfloat162*)lo)[2*i]   = __halves2bfloat162(l[0], l[1]);
    ((__nv_bfloat162*)lo)[2*i+1] = __halves2bfloat162(l[2], l[3]);
}

// ---- mma / cp.async helpers ------------------------------------------------
__device__ __forceinline__ void mma16(float d[4], const unsigned a[4],
                                      const unsigned b[2]) {
    asm("mma.sync.aligned.m16n8k16.row.col.f32.bf16.bf16.f32 "
        "{%0,%1,%2,%3}, {%4,%5,%6,%7}, {%8,%9}, {%0,%1,%2,%3};"
        : "+f"(d[0]), "+f"(d[1]), "+f"(d[2]), "+f"(d[3])
        : "r"(a[0]), "r"(a[1]), "r"(a[2]), "r"(a[3]), "r"(b[0]), "r"(b[1]));
}
__device__ __forceinline__ void cp16(unsigned dst, const void* src) {
    asm volatile("cp.async.ca.shared.global [%0], [%1], 16;" :: "r"(dst), "l"(src));
}
#define CP_COMMIT()  asm volatile("cp.async.commit_group;" ::: "memory")
#define CP_WAIT(n)   asm volatile("cp.async.wait_group %0;" :: "n"(n) : "memory")

// smem stage layout: 4 components, 128 rows x 32 bf16, row pitch 80B
// (40 bf16 = 20 words -> conflict-free fragment LDS for (gid,qid) pattern)
#define PITCH   80
#define OFF_AH  0
#define OFF_AL  10240
#define OFF_BH  20480
#define OFF_BL  30720
#define STAGEB  40960
#define BKB     32      // k per block (2 x k16)

__device__ __forceinline__
void stage_load(char* sbase, int lrow, int lchk,
                const __nv_bfloat16* __restrict__ Ah,
                const __nv_bfloat16* __restrict__ Al,
                const __nv_bfloat16* __restrict__ Bh,
                const __nv_bfloat16* __restrict__ Bl,
                int m0, int n0, int k0)
{
    #pragma unroll
    for (int r = 0; r < 2; r++) {
        int row = lrow + r*64;
        unsigned sa;
        sa = (unsigned)__cvta_generic_to_shared(sbase + OFF_AH + row*PITCH + lchk*2);
        cp16(sa, Ah + (size_t)(m0+row)*DM + k0 + lchk);
        sa = (unsigned)__cvta_generic_to_shared(sbase + OFF_AL + row*PITCH + lchk*2);
        cp16(sa, Al + (size_t)(m0+row)*DM + k0 + lchk);
        sa = (unsigned)__cvta_generic_to_shared(sbase + OFF_BH + row*PITCH + lchk*2);
        cp16(sa, Bh + (size_t)(n0+row)*DM + k0 + lchk);
        sa = (unsigned)__cvta_generic_to_shared(sbase + OFF_BL + row*PITCH + lchk*2);
        cp16(sa, Bl + (size_t)(n0+row)*DM + k0 + lchk);
    }
}

// ---------------------------------------------------------------------------
// 3xBF16 tensor-core GEMM: C = A[M,DM] @ W[N,DM]^T + bias.
// 128x128 CTA tile, BK=32, 256 threads = 8 warps (2 m x 4 n), warp tile 64x32
// via m16n8k16. Operands pre-split bf16 hi/lo in global; cp.async double
// buffer. 3 HMMAs per k16: hi*hi + hi*lo + lo*hi (err ~2^-16).
// HEADLAYOUT=1: write [B,H,S,DK]; 0: plain [t,n].
// ---------------------------------------------------------------------------
template<int HEADLAYOUT>
__device__ __forceinline__
void gemm_bf16_core(const __nv_bfloat16* __restrict__ Agh,
                    const __nv_bfloat16* __restrict__ Agl,
                    const __nv_bfloat16* __restrict__ Bgh,
                    const __nv_bfloat16* __restrict__ Bgl,
                    const float* __restrict__ bias, float* __restrict__ C)
{
    extern __shared__ char smem[];

    const int tid  = threadIdx.x;
    const int lane = tid & 31;
    const int warp = tid >> 5;
    const int wm   = warp >> 2;        // 0..1 : 64-row slice
    const int wn   = warp & 3;         // 0..3 : 32-col slice
    const int gid  = lane >> 2;        // 0..7
    const int qid  = lane & 3;         // 0..3
    const int m0   = blockIdx.y << 7;
    const int n0   = blockIdx.x << 7;

    const int lrow = tid >> 2;         // 0..63
    const int lchk = (tid & 3) << 3;   // 0,8,16,24 (bf16 elems; 16B chunks)

    float acc[4][4][4];
    #pragma unroll
    for (int mi = 0; mi < 4; mi++)
        #pragma unroll
        for (int ni = 0; ni < 4; ni++)
            #pragma unroll
            for (int r = 0; r < 4; r++) acc[mi][ni][r] = 0.f;

    const int NKB = DM / BKB;   // 32

    stage_load(smem, lrow, lchk, Agh, Agl, Bgh, Bgl, m0, n0, 0);
    CP_COMMIT();

    for (int kb = 0; kb < NKB; kb++) {
        if (kb + 1 < NKB) {
            stage_load(smem + ((kb+1)&1)*STAGEB, lrow, lchk,
                       Agh, Agl, Bgh, Bgl, m0, n0, (kb+1)*BKB);
            CP_COMMIT();
            CP_WAIT(1);
        } else {
            CP_WAIT(0);
        }
        __syncthreads();

        char* sb = smem + (kb & 1) * STAGEB;

        #pragma unroll
        for (int ks = 0; ks < 2; ks++) {
            unsigned afh[4][4], afl[4][4];
            #pragma unroll
            for (int mi = 0; mi < 4; mi++) {
                int row = wm*64 + mi*16 + gid;
                #pragma unroll
                for (int r = 0; r < 4; r++) {
                    int rr = row + ((r & 1) << 3);
                    int w  = ks*8 + qid + ((r >> 1) << 2);
                    afh[mi][r] = *(const unsigned*)(sb + OFF_AH + rr*PITCH + w*4);
                    afl[mi][r] = *(const unsigned*)(sb + OFF_AL + rr*PITCH + w*4);
                }
            }
            #pragma unroll
            for (int ni = 0; ni < 4; ni++) {
                int col = wn*32 + ni*8 + gid;
                unsigned bfh[2], bfl[2];
                #pragma unroll
                for (int r = 0; r < 2; r++) {
                    int w = ks*8 + qid + (r << 2);
                    bfh[r] = *(const unsigned*)(sb + OFF_BH + col*PITCH + w*4);
                    bfl[r] = *(const unsigned*)(sb + OFF_BL + col*PITCH + w*4);
                }
                #pragma unroll
                for (int mi = 0; mi < 4; mi++) {
                    mma16(acc[mi][ni], afh[mi], bfh);
                    mma16(acc[mi][ni], afh[mi], bfl);
                    mma16(acc[mi][ni], afl[mi], bfh);
                }
            }
        }
        __syncthreads();
    }

    // ---- epilogue: bias + store ----
    #pragma unroll
    for (int mi = 0; mi < 4; mi++) {
        #pragma unroll
        for (int ni = 0; ni < 4; ni++) {
            int row = m0 + wm*64 + mi*16 + gid;
            int col = n0 + wn*32 + ni*8 + (qid << 1);
            float b0 = bias[col], b1 = bias[col + 1];
            float2 v0 = make_float2(acc[mi][ni][0] + b0, acc[mi][ni][1] + b1);
            float2 v1 = make_float2(acc[mi][ni][2] + b0, acc[mi][ni][3] + b1);
            if (HEADLAYOUT) {
                int h = col >> 6, d = col & 63;
                {
                    int t = row, bbx = t >> 11, s = t & (SEQ - 1);
                    *(float2*)&C[(size_t)(((bbx*NH + h)*SEQ) + s)*DK + d] = v0;
                }
                {
                    int t = row + 8, bbx = t >> 11, s = t & (SEQ - 1);
                    *(float2*)&C[(size_t)(((bbx*NH + h)*SEQ) + s)*DK + d] = v1;
                }
            } else {
                *(float2*)&C[(size_t)row       * DM + col] = v0;
                *(float2*)&C[(size_t)(row + 8) * DM + col] = v1;
            }
        }
    }
}

// Fused Q/K/V projections (reads pre-split globals directly).
__global__ __launch_bounds__(256, 2)
void gemm_qkv_bf16(const float* __restrict__ bq, const float* __restrict__ bk,
                   const float* __restrict__ bv,
                   float* __restrict__ Qh, float* __restrict__ Kh,
                   float* __restrict__ Vh)
{
    const int z = blockIdx.z;
    const __nv_bfloat16* Agh = g_Xh  + (size_t)z * TOK * DM;
    const __nv_bfloat16* Agl = g_Xl  + (size_t)z * TOK * DM;
    const __nv_bfloat16* Wgh = g_WWh + (size_t)z * DM * DM;
    const __nv_bfloat16* Wgl = g_WWl + (size_t)z * DM * DM;
    const float* bias = (z == 0) ? bq : (z == 1) ? bk : bv;
    float*       Cc   = (z == 0) ? Qh : (z == 1) ? Kh : Vh;
    gemm_bf16_core<1>(Agh, Agl, Wgh, Wgl, bias, Cc);
}

__global__ __launch_bounds__(256, 2)
void gemm_out_bf16(const float* __restrict__ bo, float* __restrict__ out)
{
    gemm_bf16_core<0>(g_Ch, g_Cl,
                      g_WWh + (size_t)3 * DM * DM,
                      g_WWl + (size_t)3 * DM * DM, bo, out);
}

// ---------------------------------------------------------------------------
// Flash attention (unchanged, known-good): one block = (b, h, 128-query
// tile), 64-key tiles, 256 threads, 8q x 4k microtile.
// ---------------------------------------------------------------------------
__global__ __launch_bounds__(256)
void flash_kernel(const float* __restrict__ Qh, const float* __restrict__ Kh,
                  const float* __restrict__ Vh, const int* __restrict__ mask,
                  float* __restrict__ ctx)
{
    extern __shared__ float sm[];
    float* Qs  = sm;                     // [d][q]  64 x 132 (transposed)
    float* Ps  = sm + 64*132;            // [k][q]  64 x 132 (transposed)
    float* KVs = sm + 2*64*132;          // K: [d][k] / V: [k][d], 64 x 68

    const int tid = threadIdx.x;
    const int tx  = tid & 15;
    const int ty  = tid >> 4;
    const int q0  = blockIdx.x << 7;
    const int h   = blockIdx.y;
    const int b   = blockIdx.z;

    const float* Qg = Qh + (size_t)((b*NH + h)*SEQ + q0) * DK;
    const float* Kg = Kh + (size_t)((b*NH + h)*SEQ) * DK;
    const float* Vg = Vh + (size_t)((b*NH + h)*SEQ) * DK;
    const int*   mb = mask + b * SEQ;

    {
        const float sc = 0.125f;
        #pragma unroll
        for (int r = 0; r < 8; r++) {
            int q  = (tid >> 4) + r*16;
            int d4 = (tid & 15) << 2;
            float4 v = *(const float4*)(Qg + (size_t)q*DK + d4);
            Qs[(d4+0)*132 + q] = v.x * sc;
            Qs[(d4+1)*132 + q] = v.y * sc;
            Qs[(d4+2)*132 + q] = v.z * sc;
            Qs[(d4+3)*132 + q] = v.w * sc;
        }
    }

    float m_[8], l_[8], O[8][4];
    #pragma unroll
    for (int i = 0; i < 8; i++) {
        m_[i] = -1e30f; l_[i] = 0.f;
        #pragma unroll
        for (int j = 0; j < 4; j++) O[i][j] = 0.f;
    }

    for (int kt = 0; kt < SEQ/64; kt++) {
        const int k0 = kt << 6;
        __syncthreads();
        #pragma unroll
        for (int r = 0; r < 4; r++) {
            int k  = (tid >> 4) + r*16;
            int d4 = (tid & 15) << 2;
            float4 v = *(const float4*)(Kg + (size_t)(k0 + k)*DK + d4);
            KVs[(d4+0)*68 + k] = v.x;
            KVs[(d4+1)*68 + k] = v.y;
            KVs[(d4+2)*68 + k] = v.z;
            KVs[(d4+3)*68 + k] = v.w;
        }
        __syncthreads();

        float s[8][4];
        #pragma unroll
        for (int i = 0; i < 8; i++)
            #pragma unroll
            for (int j = 0; j < 4; j++) s[i][j] = 0.f;

        #pragma unroll 4
        for (int d = 0; d < 64; d++) {
            float4 qa = *(const float4*)&Qs[d*132 + (ty << 3)];
            float4 qb = *(const float4*)&Qs[d*132 + (ty << 3) + 4];
            float4 kp = *(const float4*)&KVs[d*68 + (tx << 2)];
            float qr[8] = {qa.x, qa.y, qa.z, qa.w, qb.x, qb.y, qb.z, qb.w};
            float kr[4] = {kp.x, kp.y, kp.z, kp.w};
            #pragma unroll
            for (int i = 0; i < 8; i++)
                #pragma unroll
                for (int j = 0; j < 4; j++)
                    s[i][j] = fmaf(qr[i], kr[j], s[i][j]);
        }

        int mk[4];
        #pragma unroll
        for (int j = 0; j < 4; j++) mk[j] = mb[k0 + (tx << 2) + j];
        #pragma unroll
        for (int i = 0; i < 8; i++)
            #pragma unroll
            for (int j = 0; j < 4; j++)
                if (mk[j] == 0) s[i][j] = -1.0e9f;

        #pragma unroll
        for (int i = 0; i < 8; i++) {
            float rm = fmaxf(fmaxf(s[i][0], s[i][1]), fmaxf(s[i][2], s[i][3]));
            #pragma unroll
            for (int off = 8; off >= 1; off >>= 1)
                rm = fmaxf(rm, __shfl_xor_sync(0xffffffffu, rm, off));
            float nm   = fmaxf(m_[i], rm);
            float corr = __expf(m_[i] - nm);
            float rs = 0.f;
            #pragma unroll
            for (int j = 0; j < 4; j++) {
                float p = __expf(s[i][j] - nm);
                s[i][j] = p;
                rs += p;
            }
            #pragma unroll
            for (int off = 8; off >= 1; off >>= 1)
                rs += __shfl_xor_sync(0xffffffffu, rs, off);
            l_[i] = l_[i] * corr + rs;
            m_[i] = nm;
            #pragma unroll
            for (int j = 0; j < 4; j++) O[i][j] *= corr;
        }

        #pragma unroll
        for (int j = 0; j < 4; j++)
            #pragma unroll
            for (int i = 0; i < 8; i++)
                Ps[((tx << 2) + j)*132 + (ty << 3) + i] = s[i][j];
        __syncthreads();

        #pragma unroll
        for (int r = 0; r < 4; r++) {
            int k  = (tid >> 4) + r*16;
            int d4 = (tid & 15) << 2;
            float4 v = *(const float4*)(Vg + (size_t)(k0 + k)*DK + d4);
            *(float4*)&KVs[k*68 + d4] = v;
        }
        __syncthreads();

        #pragma unroll 4
        for (int k = 0; k < 64; k++) {
            float4 pa = *(const float4*)&Ps[k*132 + (ty << 3)];
            float4 pb = *(const float4*)&Ps[k*132 + (ty << 3) + 4];
            float4 vp = *(const float4*)&KVs[k*68 + (tx << 2)];
            float pr[8] = {pa.x, pa.y, pa.z, pa.w, pb.x, pb.y, pb.z, pb.w};
            float vr[4] = {vp.x, vp.y, vp.z, vp.w};
            #pragma unroll
            for (int i = 0; i < 8; i++)
                #pragma unroll
                for (int j = 0; j < 4; j++)
                    O[i][j] = fmaf(pr[i], vr[j], O[i][j]);
        }
    }

    #pragma unroll
    for (int i = 0; i < 8; i++) {
        float inv = 1.0f / l_[i];
        int s = q0 + (ty << 3) + i;
        float4 r = make_float4(O[i][0]*inv, O[i][1]*inv, O[i][2]*inv, O[i][3]*inv);
        *(float4*)&ctx[(size_t)(b*SEQ + s)*DM + h*DK + (tx << 2)] = r;
    }
}

// ---------------------------------------------------------------------------
extern "C" void kernel_launch(void* const* d_in, const int* in_sizes, int n_in,
                              void* d_out, int out_size)
{
    (void)in_sizes; (void)n_in; (void)out_size;
    const float* query = (const float*)d_in[0];
    const float* key_  = (const float*)d_in[1];
    const float* value = (const float*)d_in[2];
    const int*   mask  = (const int*)  d_in[3];
    const float* bq = (const float*)d_in[5];
    const float* Wq = (const float*)d_in[4];
    const float* Wk = (const float*)d_in[6];
    const float* bk = (const float*)d_in[7];
    const float* Wv = (const float*)d_in[8];
    const float* bv = (const float*)d_in[9];
    const float* Wo = (const float*)d_in[10];
    const float* bo = (const float*)d_in[11];
    float* out = (float*)d_out;

    float *Qh, *Kh, *Vh, *ctx;
    __nv_bfloat16 *Xh, *Xl, *WWh, *WWl, *Ch, *Cl;
    cudaGetSymbolAddress((void**)&Qh,  g_Qh);
    cudaGetSymbolAddress((void**)&Kh,  g_Kh);
    cudaGetSymbolAddress((void**)&Vh,  g_Vh);
    cudaGetSymbolAddress((void**)&ctx, g_ctx);
    cudaGetSymbolAddress((void**)&Xh,  g_Xh);
    cudaGetSymbolAddress((void**)&Xl,  g_Xl);
    cudaGetSymbolAddress((void**)&WWh, g_WWh);
    cudaGetSymbolAddress((void**)&WWl, g_WWl);
    cudaGetSymbolAddress((void**)&Ch,  g_Ch);
    cudaGetSymbolAddress((void**)&Cl,  g_Cl);

    const int n4x = TOK * DM / 4;   // 1,048,576
    const int n4w = DM * DM / 4;    // 262,144

    // pre-split inputs + weights into bf16 hi/lo
    split_bf16<<<n4x/256, 256>>>(query, Xh,                 Xl,                 n4x);
    split_bf16<<<n4x/256, 256>>>(key_,  Xh + (size_t)TOK*DM,   Xl + (size_t)TOK*DM,   n4x);
    split_bf16<<<n4x/256, 256>>>(value, Xh + (size_t)2*TOK*DM, Xl + (size_t)2*TOK*DM, n4x);
    split_bf16<<<n4w/256, 256>>>(Wq, WWh,                    WWl,                    n4w);
    split_bf16<<<n4w/256, 256>>>(Wk, WWh + (size_t)DM*DM,    WWl + (size_t)DM*DM,    n4w);
    split_bf16<<<n4w/256, 256>>>(Wv, WWh + (size_t)2*DM*DM,  WWl + (size_t)2*DM*DM,  n4w);
    split_bf16<<<n4w/256, 256>>>(Wo, WWh + (size_t)3*DM*DM,  WWl + (size_t)3*DM*DM,  n4w);

    // QKV projections (tensor core, 3xBF16, double-buffered)
    cudaFuncSetAttribute(gemm_qkv_bf16,
                         cudaFuncAttributeMaxDynamicSharedMemorySize, 2*STAGEB);
    gemm_qkv_bf16<<<dim3(DM/128, TOK/128, 3), 256, 2*STAGEB>>>(bq, bk, bv,
                                                               Qh, Kh, Vh);

    // attention
    size_t shm = (size_t)(2*64*132 + 64*68) * sizeof(float);   // 84992 B
    cudaFuncSetAttribute(flash_kernel,
                         cudaFuncAttributeMaxDynamicSharedMemorySize, (int)shm);
    flash_kernel<<<dim3(SEQ/128, NH, BB), 256, shm>>>(Qh, Kh, Vh, mask, ctx);

    // split ctx, then output projection
    split_bf16<<<n4x/256, 256>>>(ctx, Ch, Cl, n4x);
    cudaFuncSetAttribute(gemm_out_bf16,
                         cudaFuncAttributeMaxDynamicSharedMemorySize, 2*STAGEB);
    gemm_out_bf16<<<dim3(DM/128, TOK/128), 256, 2*STAGEB>>>(bo, out);
}

// round 8
// speedup vs baseline: 3.5437x; 1.8064x over previous
#include <cuda_runtime.h>
#include <cuda_bf16.h>
#include <math.h>

#define DM   1024
#define NH   16
#define DK   64
#define SEQ  2048
#define BB   2
#define TOK  (BB*SEQ)   // 4096

// ---------------- scratch (__device__ globals; no allocation allowed) -------
// bf16 hi/lo split scratch
__device__ __nv_bfloat16 g_Xh[3*TOK*DM];      // q,k,v inputs (hi)
__device__ __nv_bfloat16 g_Xl[3*TOK*DM];      // (lo)
__device__ __nv_bfloat16 g_WWh[4*DM*DM];      // Wq,Wk,Wv,Wo (hi)
__device__ __nv_bfloat16 g_WWl[4*DM*DM];      // (lo)
// projected tensors, bf16 hi/lo
__device__ __nv_bfloat16 g_Qhh[BB*NH*SEQ*DK]; // Q [B,H,S,DK], pre-scaled 1/8
__device__ __nv_bfloat16 g_Qll[BB*NH*SEQ*DK];
__device__ __nv_bfloat16 g_Khh[BB*NH*SEQ*DK]; // K [B,H,S,DK]
__device__ __nv_bfloat16 g_Kll[BB*NH*SEQ*DK];
__device__ __nv_bfloat16 g_Vth[BB*NH*DK*SEQ]; // V transposed [B,H,DK,S]
__device__ __nv_bfloat16 g_Vtl[BB*NH*DK*SEQ];
// attention output (ctx) bf16 hi/lo [TOK, DM]
__device__ __nv_bfloat16 g_Ch[TOK*DM];
__device__ __nv_bfloat16 g_Cl[TOK*DM];

// ---- helpers ---------------------------------------------------------------
__device__ __forceinline__ __nv_bfloat16 bhi(float x) { return __float2bfloat16(x); }
__device__ __forceinline__ float bf2f(__nv_bfloat16 x) { return __bfloat162float(x); }
__device__ __forceinline__ __nv_bfloat16 blo(float x) {
    return __float2bfloat16(x - bf2f(__float2bfloat16(x)));
}
__device__ __forceinline__ unsigned packbf(float lo, float hi) {
    unsigned r; asm("cvt.rn.bf16x2.f32 %0, %1, %2;" : "=r"(r) : "f"(hi), "f"(lo));
    return r;
}
__device__ __forceinline__ void mma16(float d[4], const unsigned a[4],
                                      const unsigned b[2]) {
    asm("mma.sync.aligned.m16n8k16.row.col.f32.bf16.bf16.f32 "
        "{%0,%1,%2,%3}, {%4,%5,%6,%7}, {%8,%9}, {%0,%1,%2,%3};"
        : "+f"(d[0]), "+f"(d[1]), "+f"(d[2]), "+f"(d[3])
        : "r"(a[0]), "r"(a[1]), "r"(a[2]), "r"(a[3]), "r"(b[0]), "r"(b[1]));
}
__device__ __forceinline__ void cp16(void* dst, const void* src) {
    unsigned d = (unsigned)__cvta_generic_to_shared(dst);
    asm volatile("cp.async.ca.shared.global [%0], [%1], 16;" :: "r"(d), "l"(src));
}
#define CP_COMMIT()  asm volatile("cp.async.commit_group;" ::: "memory")
#define CP_WAIT(n)   asm volatile("cp.async.wait_group %0;" :: "n"(n) : "memory")
__device__ __forceinline__ unsigned ld32(const void* p) {
    return *(const unsigned*)p;
}

// ---------------------------------------------------------------------------
// Elementwise bf16 hi/lo split: hi = bf16(x), lo = bf16(x - float(hi)).
// ---------------------------------------------------------------------------
__global__ __launch_bounds__(256)
void split_bf16(const float* __restrict__ x,
                __nv_bfloat16* __restrict__ hi,
                __nv_bfloat16* __restrict__ lo, int n4)
{
    int i = blockIdx.x * blockDim.x + threadIdx.x;
    if (i >= n4) return;
    float4 v = ((const float4*)x)[i];
    float vv[4] = {v.x, v.y, v.z, v.w};
    __nv_bfloat16 h[4], l[4];
    #pragma unroll
    for (int j = 0; j < 4; j++) {
        h[j] = __float2bfloat16(vv[j]);
        l[j] = __float2bfloat16(vv[j] - __bfloat162float(h[j]));
    }
    ((__nv_bfloat162*)hi)[2*i]   = __halves2bfloat162(h[0], h[1]);
    ((__nv_bfloat162*)hi)[2*i+1] = __halves2bfloat162(h[2], h[3]);
    ((__nv_bfloat162*)lo)[2*i]   = __halves2bfloat162(l[0], l[1]);
    ((__nv_bfloat162*)lo)[2*i+1] = __halves2bfloat162(l[2], l[3]);
}

// ---- GEMM smem layout ------------------------------------------------------
#define PITCH   80
#define OFF_AH  0
#define OFF_AL  10240
#define OFF_BH  20480
#define OFF_BL  30720
#define STAGEB  40960
#define BKB     32

__device__ __forceinline__
void stage_load(char* sbase, int lrow, int lchk,
                const __nv_bfloat16* __restrict__ Ah,
                const __nv_bfloat16* __restrict__ Al,
                const __nv_bfloat16* __restrict__ Bh,
                const __nv_bfloat16* __restrict__ Bl,
                int m0, int n0, int k0)
{
    #pragma unroll
    for (int r = 0; r < 2; r++) {
        int row = lrow + r*64;
        cp16(sbase + OFF_AH + row*PITCH + lchk*2, Ah + (size_t)(m0+row)*DM + k0 + lchk);
        cp16(sbase + OFF_AL + row*PITCH + lchk*2, Al + (size_t)(m0+row)*DM + k0 + lchk);
        cp16(sbase + OFF_BH + row*PITCH + lchk*2, Bh + (size_t)(n0+row)*DM + k0 + lchk);
        cp16(sbase + OFF_BL + row*PITCH + lchk*2, Bl + (size_t)(n0+row)*DM + k0 + lchk);
    }
}

// ---------------------------------------------------------------------------
// 3xBF16 tensor-core GEMM mainloop (128x128 tile, BK=32, 8 warps 2x4,
// warp tile 64x32 via m16n8k16).  mode: 0=plain fp32 C
//                                       1=bf16 hi/lo head-layout (Q/K)
//                                       2=bf16 hi/lo transposed (V)
// ---------------------------------------------------------------------------
__device__ __forceinline__
void gemm_bf16_core(const __nv_bfloat16* __restrict__ Agh,
                    const __nv_bfloat16* __restrict__ Agl,
                    const __nv_bfloat16* __restrict__ Bgh,
                    const __nv_bfloat16* __restrict__ Bgl,
                    const float* __restrict__ bias,
                    int mode, float scale,
                    float* __restrict__ C,
                    __nv_bfloat16* __restrict__ Oh,
                    __nv_bfloat16* __restrict__ Ol)
{
    extern __shared__ char smem[];

    const int tid  = threadIdx.x;
    const int lane = tid & 31;
    const int warp = tid >> 5;
    const int wm   = warp >> 2;
    const int wn   = warp & 3;
    const int gid  = lane >> 2;
    const int qid  = lane & 3;
    const int m0   = blockIdx.y << 7;
    const int n0   = blockIdx.x << 7;

    const int lrow = tid >> 2;
    const int lchk = (tid & 3) << 3;

    float acc[4][4][4];
    #pragma unroll
    for (int mi = 0; mi < 4; mi++)
        #pragma unroll
        for (int ni = 0; ni < 4; ni++)
            #pragma unroll
            for (int r = 0; r < 4; r++) acc[mi][ni][r] = 0.f;

    const int NKB = DM / BKB;

    stage_load(smem, lrow, lchk, Agh, Agl, Bgh, Bgl, m0, n0, 0);
    CP_COMMIT();

    for (int kb = 0; kb < NKB; kb++) {
        if (kb + 1 < NKB) {
            stage_load(smem + ((kb+1)&1)*STAGEB, lrow, lchk,
                       Agh, Agl, Bgh, Bgl, m0, n0, (kb+1)*BKB);
            CP_COMMIT();
            CP_WAIT(1);
        } else {
            CP_WAIT(0);
        }
        __syncthreads();

        char* sb = smem + (kb & 1) * STAGEB;

        #pragma unroll
        for (int ks = 0; ks < 2; ks++) {
            unsigned afh[4][4], afl[4][4];
            #pragma unroll
            for (int mi = 0; mi < 4; mi++) {
                int row = wm*64 + mi*16 + gid;
                #pragma unroll
                for (int r = 0; r < 4; r++) {
                    int rr = row + ((r & 1) << 3);
                    int w  = ks*8 + qid + ((r >> 1) << 2);
                    afh[mi][r] = ld32(sb + OFF_AH + rr*PITCH + w*4);
                    afl[mi][r] = ld32(sb + OFF_AL + rr*PITCH + w*4);
                }
            }
            #pragma unroll
            for (int ni = 0; ni < 4; ni++) {
                int col = wn*32 + ni*8 + gid;
                unsigned bfh[2], bfl[2];
                #pragma unroll
                for (int r = 0; r < 2; r++) {
                    int w = ks*8 + qid + (r << 2);
                    bfh[r] = ld32(sb + OFF_BH + col*PITCH + w*4);
                    bfl[r] = ld32(sb + OFF_BL + col*PITCH + w*4);
                }
                #pragma unroll
                for (int mi = 0; mi < 4; mi++) {
                    mma16(acc[mi][ni], afh[mi], bfh);
                    mma16(acc[mi][ni], afh[mi], bfl);
                    mma16(acc[mi][ni], afl[mi], bfh);
                }
            }
        }
        __syncthreads();
    }

    // ---- epilogue ----
    #pragma unroll
    for (int mi = 0; mi < 4; mi++) {
        #pragma unroll
        for (int ni = 0; ni < 4; ni++) {
            int row = m0 + wm*64 + mi*16 + gid;
            int col = n0 + wn*32 + ni*8 + (qid << 1);
            float b0 = bias[col], b1 = bias[col + 1];
            float v00 = (acc[mi][ni][0] + b0) * scale;
            float v01 = (acc[mi][ni][1] + b1) * scale;
            float v10 = (acc[mi][ni][2] + b0) * scale;
            float v11 = (acc[mi][ni][3] + b1) * scale;
            if (mode == 0) {
                *(float2*)&C[(size_t)row       * DM + col] = make_float2(v00, v01);
                *(float2*)&C[(size_t)(row + 8) * DM + col] = make_float2(v10, v11);
            } else if (mode == 1) {
                int h = col >> 6, d = col & 63;
                {
                    int t = row, bbx = t >> 11, s = t & (SEQ - 1);
                    size_t off = ((size_t)((bbx*NH + h)*SEQ) + s)*DK + d;
                    *(__nv_bfloat162*)&Oh[off] = __halves2bfloat162(bhi(v00), bhi(v01));
                    *(__nv_bfloat162*)&Ol[off] = __halves2bfloat162(blo(v00), blo(v01));
                }
                {
                    int t = row + 8, bbx = t >> 11, s = t & (SEQ - 1);
                    size_t off = ((size_t)((bbx*NH + h)*SEQ) + s)*DK + d;
                    *(__nv_bfloat162*)&Oh[off] = __halves2bfloat162(bhi(v10), bhi(v11));
                    *(__nv_bfloat162*)&Ol[off] = __halves2bfloat162(blo(v10), blo(v11));
                }
            } else {
                // V transposed: [B,H,DK,SEQ]
                int h = col >> 6, d = col & 63;
                int bbx = row >> 11, s = row & (SEQ - 1);
                size_t base = (size_t)(bbx*NH + h) * DK;
                Oh[(base + d    )*SEQ + s    ] = bhi(v00);
                Oh[(base + d + 1)*SEQ + s    ] = bhi(v01);
                Oh[(base + d    )*SEQ + s + 8] = bhi(v10);
                Oh[(base + d + 1)*SEQ + s + 8] = bhi(v11);
                Ol[(base + d    )*SEQ + s    ] = blo(v00);
                Ol[(base + d + 1)*SEQ + s    ] = blo(v01);
                Ol[(base + d    )*SEQ + s + 8] = blo(v10);
                Ol[(base + d + 1)*SEQ + s + 8] = blo(v11);
            }
        }
    }
}

// Fused Q/K/V projections -> bf16 hi/lo outputs (Q scaled by 1/8; V transposed)
__global__ __launch_bounds__(256, 2)
void gemm_qkv_bf16(const float* __restrict__ bq, const float* __restrict__ bk,
                   const float* __restrict__ bv)
{
    const int z = blockIdx.z;
    const __nv_bfloat16* Agh = g_Xh  + (size_t)z * TOK * DM;
    const __nv_bfloat16* Agl = g_Xl  + (size_t)z * TOK * DM;
    const __nv_bfloat16* Wgh = g_WWh + (size_t)z * DM * DM;
    const __nv_bfloat16* Wgl = g_WWl + (size_t)z * DM * DM;
    const float* bias = (z == 0) ? bq : (z == 1) ? bk : bv;
    float scale = (z == 0) ? 0.125f : 1.0f;
    int   mode  = (z == 2) ? 2 : 1;
    __nv_bfloat16* Oh = (z == 0) ? g_Qhh : (z == 1) ? g_Khh : g_Vth;
    __nv_bfloat16* Ol = (z == 0) ? g_Qll : (z == 1) ? g_Kll : g_Vtl;
    gemm_bf16_core(Agh, Agl, Wgh, Wgl, bias, mode, scale, nullptr, Oh, Ol);
}

__global__ __launch_bounds__(256, 2)
void gemm_out_bf16(const float* __restrict__ bo, float* __restrict__ out)
{
    gemm_bf16_core(g_Ch, g_Cl,
                   g_WWh + (size_t)3 * DM * DM,
                   g_WWl + (size_t)3 * DM * DM,
                   bo, 0, 1.0f, out, nullptr, nullptr);
}

// ---------------------------------------------------------------------------
// Tensor-core flash attention.
// Block = (128-query tile, h, b), 256 thr = 8 warps; each warp: 16 queries x
// full 64-key tile (softmax intra-warp). QK^T and PV via m16n8k16 bf16,
// 3 MMAs per k16 (hi*hi + hi*lo + lo*hi). P stays in registers.
// Writes ctx directly as bf16 hi/lo.
// ---------------------------------------------------------------------------
#define QP      144                 // bytes per 64-elem bf16 row (72 elems)
#define Q_H     0
#define Q_L     (128*QP)            // 18432
#define QTOT    (2*128*QP)          // 36864
#define KV_KH   0
#define KV_KL   (64*QP)             // 9216
#define KV_VH   (2*64*QP)
#define KV_VL   (3*64*QP)
#define KV_MK   (4*64*QP)           // 36864
#define KV_SZ   (4*64*QP + 256)     // 37120
#define FL_SMEM (QTOT + 2*KV_SZ)    // 111104

__device__ __forceinline__
void stage_kv(char* sb, int tid,
              const __nv_bfloat16* __restrict__ Khg,
              const __nv_bfloat16* __restrict__ Klg,
              const __nv_bfloat16* __restrict__ Vhg,
              const __nv_bfloat16* __restrict__ Vlg,
              const int* __restrict__ mb, int k0)
{
    #pragma unroll
    for (int it = 0; it < 2; it++) {
        int idx = tid + it*256;
        int row = idx >> 3, ch = idx & 7;
        cp16(sb + KV_KH + row*QP + ch*16, Khg + (size_t)(k0 + row)*DK + ch*8);
        cp16(sb + KV_KL + row*QP + ch*16, Klg + (size_t)(k0 + row)*DK + ch*8);
        cp16(sb + KV_VH + row*QP + ch*16, Vhg + (size_t)row*SEQ + k0 + ch*8);
        cp16(sb + KV_VL + row*QP + ch*16, Vlg + (size_t)row*SEQ + k0 + ch*8);
    }
    if (tid < 16) cp16(sb + KV_MK + tid*16, mb + k0 + tid*4);
}

__global__ __launch_bounds__(256, 2)
void flash_mma(const int* __restrict__ mask)
{
    extern __shared__ char sm[];
    const int tid  = threadIdx.x;
    const int lane = tid & 31;
    const int warp = tid >> 5;
    const int gid  = lane >> 2;
    const int qid  = lane & 3;
    const int q0   = blockIdx.x << 7;
    const int h    = blockIdx.y;
    const int b    = blockIdx.z;

    const __nv_bfloat16* Qhg = g_Qhh + ((size_t)((b*NH + h)*SEQ) + q0)*DK;
    const __nv_bfloat16* Qlg = g_Qll + ((size_t)((b*NH + h)*SEQ) + q0)*DK;
    const __nv_bfloat16* Khg = g_Khh + (size_t)(b*NH + h)*SEQ*DK;
    const __nv_bfloat16* Klg = g_Kll + (size_t)(b*NH + h)*SEQ*DK;
    const __nv_bfloat16* Vhg = g_Vth + (size_t)(b*NH + h)*DK*SEQ;
    const __nv_bfloat16* Vlg = g_Vtl + (size_t)(b*NH + h)*DK*SEQ;
    const int* mb = mask + b * SEQ;

    // stage Q (128 rows x 128B, hi + lo)
    #pragma unroll
    for (int it = 0; it < 4; it++) {
        int idx = tid + it*256;
        int row = idx >> 3, ch = idx & 7;
        cp16(sm + Q_H + row*QP + ch*16, Qhg + (size_t)row*DK + ch*8);
        cp16(sm + Q_L + row*QP + ch*16, Qlg + (size_t)row*DK + ch*8);
    }
    stage_kv(sm + QTOT, tid, Khg, Klg, Vhg, Vlg, mb, 0);
    CP_COMMIT();

    float O[8][4];
    #pragma unroll
    for (int ni = 0; ni < 8; ni++)
        #pragma unroll
        for (int r = 0; r < 4; r++) O[ni][r] = 0.f;
    float m_[2] = {-1e30f, -1e30f}, l_[2] = {0.f, 0.f};

    const int row0 = warp*16 + gid;

    for (int kt = 0; kt < SEQ/64; kt++) {
        char* sb = sm + QTOT + (kt & 1)*KV_SZ;
        if (kt + 1 < SEQ/64) {
            stage_kv(sm + QTOT + ((kt+1) & 1)*KV_SZ, tid,
                     Khg, Klg, Vhg, Vlg, mb, (kt+1) << 6);
            CP_COMMIT();
            CP_WAIT(1);
        } else {
            CP_WAIT(0);
        }
        __syncthreads();

        // ---- QK^T ----
        float c[8][4];
        #pragma unroll
        for (int ni = 0; ni < 8; ni++)
            #pragma unroll
            for (int r = 0; r < 4; r++) c[ni][r] = 0.f;

        #pragma unroll
        for (int ks = 0; ks < 4; ks++) {
            int w0 = (ks*8 + qid)*4;
            unsigned ah[4], al[4];
            ah[0] = ld32(sm + Q_H + row0*QP + w0);
            ah[1] = ld32(sm + Q_H + (row0+8)*QP + w0);
            ah[2] = ld32(sm + Q_H + row0*QP + w0 + 16);
            ah[3] = ld32(sm + Q_H + (row0+8)*QP + w0 + 16);
            al[0] = ld32(sm + Q_L + row0*QP + w0);
            al[1] = ld32(sm + Q_L + (row0+8)*QP + w0);
            al[2] = ld32(sm + Q_L + row0*QP + w0 + 16);
            al[3] = ld32(sm + Q_L + (row0+8)*QP + w0 + 16);
            #pragma unroll
            for (int ni = 0; ni < 8; ni++) {
                int kr = ni*8 + gid;
                unsigned bh[2], bl[2];
                bh[0] = ld32(sb + KV_KH + kr*QP + w0);
                bh[1] = ld32(sb + KV_KH + kr*QP + w0 + 16);
                bl[0] = ld32(sb + KV_KL + kr*QP + w0);
                bl[1] = ld32(sb + KV_KL + kr*QP + w0 + 16);
                mma16(c[ni], ah, bh);
                mma16(c[ni], ah, bl);
                mma16(c[ni], al, bh);
            }
        }

        // ---- mask (key-only) ----
        const int* mks = (const int*)(sb + KV_MK);
        #pragma unroll
        for (int ni = 0; ni < 8; ni++) {
            int c0 = ni*8 + qid*2;
            if (mks[c0]     == 0) { c[ni][0] = -1.0e9f; c[ni][2] = -1.0e9f; }
            if (mks[c0 + 1] == 0) { c[ni][1] = -1.0e9f; c[ni][3] = -1.0e9f; }
        }

        // ---- online softmax (2 rows per lane) ----
        #pragma unroll
        for (int r = 0; r < 2; r++) {
            const int bx = r*2;
            float rm = -1e30f;
            #pragma unroll
            for (int ni = 0; ni < 8; ni++)
                rm = fmaxf(rm, fmaxf(c[ni][bx], c[ni][bx+1]));
            rm = fmaxf(rm, __shfl_xor_sync(0xffffffffu, rm, 1));
            rm = fmaxf(rm, __shfl_xor_sync(0xffffffffu, rm, 2));
            float nm   = fmaxf(m_[r], rm);
            float corr = __expf(m_[r] - nm);
            float rs = 0.f;
            #pragma unroll
            for (int ni = 0; ni < 8; ni++) {
                float p0 = __expf(c[ni][bx]   - nm);
                float p1 = __expf(c[ni][bx+1] - nm);
                c[ni][bx] = p0; c[ni][bx+1] = p1;
                rs += p0 + p1;
            }
            rs += __shfl_xor_sync(0xffffffffu, rs, 1);
            rs += __shfl_xor_sync(0xffffffffu, rs, 2);
            l_[r] = l_[r] * corr + rs;
            m_[r] = nm;
            #pragma unroll
            for (int ni = 0; ni < 8; ni++) {
                O[ni][bx]   *= corr;
                O[ni][bx+1] *= corr;
            }
        }

        // ---- PV: P (registers) x V (smem, transposed) ----
        #pragma unroll
        for (int ks = 0; ks < 4; ks++) {
            float p[8] = {c[2*ks][0],   c[2*ks][1],   c[2*ks][2],   c[2*ks][3],
                          c[2*ks+1][0], c[2*ks+1][1], c[2*ks+1][2], c[2*ks+1][3]};
            unsigned pah[4], pal[4];
            pah[0] = packbf(p[0], p[1]);
            pah[1] = packbf(p[2], p[3]);
            pah[2] = packbf(p[4], p[5]);
            pah[3] = packbf(p[6], p[7]);
            float e[8];
            #pragma unroll
            for (int i = 0; i < 8; i++)
                e[i] = p[i] - bf2f(__float2bfloat16(p[i]));
            pal[0] = packbf(e[0], e[1]);
            pal[1] = packbf(e[2], e[3]);
            pal[2] = packbf(e[4], e[5]);
            pal[3] = packbf(e[6], e[7]);

            int w0 = (ks*8 + qid)*4;
            #pragma unroll
            for (int ni = 0; ni < 8; ni++) {
                int dr = ni*8 + gid;
                unsigned vh[2], vl[2];
                vh[0] = ld32(sb + KV_VH + dr*QP + w0);
                vh[1] = ld32(sb + KV_VH + dr*QP + w0 + 16);
                vl[0] = ld32(sb + KV_VL + dr*QP + w0);
                vl[1] = ld32(sb + KV_VL + dr*QP + w0 + 16);
                mma16(O[ni], pah, vh);
                mma16(O[ni], pah, vl);
                mma16(O[ni], pal, vh);
            }
        }
        __syncthreads();
    }

    // ---- epilogue: normalize, split bf16 hi/lo, write ctx ----
    float inv0 = 1.0f / l_[0], inv1 = 1.0f / l_[1];
    int s = q0 + warp*16 + gid;
    size_t t0 = (size_t)(b*SEQ + s)*DM + h*DK;
    size_t t1 = t0 + (size_t)8*DM;
    #pragma unroll
    for (int ni = 0; ni < 8; ni++) {
        int d = ni*8 + (qid << 1);
        float x0 = O[ni][0]*inv0, x1 = O[ni][1]*inv0;
        float y0 = O[ni][2]*inv1, y1 = O[ni][3]*inv1;
        *(__nv_bfloat162*)&g_Ch[t0 + d] = __halves2bfloat162(bhi(x0), bhi(x1));
        *(__nv_bfloat162*)&g_Cl[t0 + d] = __halves2bfloat162(blo(x0), blo(x1));
        *(__nv_bfloat162*)&g_Ch[t1 + d] = __halves2bfloat162(bhi(y0), bhi(y1));
        *(__nv_bfloat162*)&g_Cl[t1 + d] = __halves2bfloat162(blo(y0), blo(y1));
    }
}

// ---------------------------------------------------------------------------
extern "C" void kernel_launch(void* const* d_in, const int* in_sizes, int n_in,
                              void* d_out, int out_size)
{
    (void)in_sizes; (void)n_in; (void)out_size;
    const float* query = (const float*)d_in[0];
    const float* key_  = (const float*)d_in[1];
    const float* value = (const float*)d_in[2];
    const int*   mask  = (const int*)  d_in[3];
    const float* Wq = (const float*)d_in[4];
    const float* bq = (const float*)d_in[5];
    const float* Wk = (const float*)d_in[6];
    const float* bk = (const float*)d_in[7];
    const float* Wv = (const float*)d_in[8];
    const float* bv = (const float*)d_in[9];
    const float* Wo = (const float*)d_in[10];
    const float* bo = (const float*)d_in[11];
    float* out = (float*)d_out;

    __nv_bfloat16 *Xh, *Xl, *WWh, *WWl;
    cudaGetSymbolAddress((void**)&Xh,  g_Xh);
    cudaGetSymbolAddress((void**)&Xl,  g_Xl);
    cudaGetSymbolAddress((void**)&WWh, g_WWh);
    cudaGetSymbolAddress((void**)&WWl, g_WWl);

    const int n4x = TOK * DM / 4;
    const int n4w = DM * DM / 4;

    // pre-split inputs + weights into bf16 hi/lo
    split_bf16<<<n4x/256, 256>>>(query, Xh,                    Xl,                    n4x);
    split_bf16<<<n4x/256, 256>>>(key_,  Xh + (size_t)TOK*DM,   Xl + (size_t)TOK*DM,   n4x);
    split_bf16<<<n4x/256, 256>>>(value, Xh + (size_t)2*TOK*DM, Xl + (size_t)2*TOK*DM, n4x);
    split_bf16<<<n4w/256, 256>>>(Wq, WWh,                      WWl,                   n4w);
    split_bf16<<<n4w/256, 256>>>(Wk, WWh + (size_t)DM*DM,      WWl + (size_t)DM*DM,   n4w);
    split_bf16<<<n4w/256, 256>>>(Wv, WWh + (size_t)2*DM*DM,    WWl + (size_t)2*DM*DM, n4w);
    split_bf16<<<n4w/256, 256>>>(Wo, WWh + (size_t)3*DM*DM,    WWl + (size_t)3*DM*DM, n4w);

    // QKV projections -> bf16 hi/lo (Q scaled, V transposed)
    cudaFuncSetAttribute(gemm_qkv_bf16,
                         cudaFuncAttributeMaxDynamicSharedMemorySize, 2*STAGEB);
    gemm_qkv_bf16<<<dim3(DM/128, TOK/128, 3), 256, 2*STAGEB>>>(bq, bk, bv);

    // tensor-core flash attention -> ctx bf16 hi/lo
    cudaFuncSetAttribute(flash_mma,
                         cudaFuncAttributeMaxDynamicSharedMemorySize, FL_SMEM);
    flash_mma<<<dim3(SEQ/128, NH, BB), 256, FL_SMEM>>>(mask);

    // output projection
    cudaFuncSetAttribute(gemm_out_bf16,
                         cudaFuncAttributeMaxDynamicSharedMemorySize, 2*STAGEB);
    gemm_out_bf16<<<dim3(DM/128, TOK/128), 256, 2*STAGEB>>>(bo, out);
}

// round 10
// speedup vs baseline: 5.3378x; 1.5063x over previous
#include <cuda_runtime.h>
#include <cuda_bf16.h>
#include <math.h>

#define DM   1024
#define NH   16
#define DK   64
#define SEQ  2048
#define BB   2
#define TOK  (BB*SEQ)   // 4096

// ---------------- scratch (__device__ globals; no allocation allowed) -------
__device__ __nv_bfloat16 g_Xh[3*TOK*DM];      // q,kC,vC inputs (hi)
__device__ __nv_bfloat16 g_Xl[3*TOK*DM];      // (lo)
__device__ __nv_bfloat16 g_WWh[4*DM*DM];      // Wq,Wk,Wv,Wo (hi)
__device__ __nv_bfloat16 g_WWl[4*DM*DM];      // (lo)
__device__ __nv_bfloat16 g_Qhh[BB*NH*SEQ*DK]; // Q [B,H,S,DK], pre-scaled 1/8
__device__ __nv_bfloat16 g_Qll[BB*NH*SEQ*DK];
__device__ __nv_bfloat16 g_Khh[BB*NH*SEQ*DK]; // K compacted [B,H,j,DK]
__device__ __nv_bfloat16 g_Kll[BB*NH*SEQ*DK];
__device__ __nv_bfloat16 g_Vth[BB*NH*DK*SEQ]; // V compacted transposed [B,H,DK,j]
__device__ __nv_bfloat16 g_Vtl[BB*NH*DK*SEQ];
__device__ __nv_bfloat16 g_Ch[TOK*DM];        // ctx hi
__device__ __nv_bfloat16 g_Cl[TOK*DM];        // ctx lo
// mask compaction state
__device__ int g_cidx[BB*SEQ];                // compacted j -> original s
__device__ int g_cmask[BB*SEQ];               // 1 for j < cnt, else 0
__device__ int g_cntp[BB];                    // cnt padded to 128 (min 128)

// ---- helpers ---------------------------------------------------------------
__device__ __forceinline__ __nv_bfloat16 bhi(float x) { return __float2bfloat16(x); }
__device__ __forceinline__ float bf2f(__nv_bfloat16 x) { return __bfloat162float(x); }
__device__ __forceinline__ __nv_bfloat16 blo(float x) {
    return __float2bfloat16(x - bf2f(__float2bfloat16(x)));
}
__device__ __forceinline__ unsigned packbf(float lo, float hi) {
    unsigned r; asm("cvt.rn.bf16x2.f32 %0, %1, %2;" : "=r"(r) : "f"(hi), "f"(lo));
    return r;
}
__device__ __forceinline__ void mma16(float d[4], const unsigned a[4],
                                      const unsigned b[2]) {
    asm("mma.sync.aligned.m16n8k16.row.col.f32.bf16.bf16.f32 "
        "{%0,%1,%2,%3}, {%4,%5,%6,%7}, {%8,%9}, {%0,%1,%2,%3};"
        : "+f"(d[0]), "+f"(d[1]), "+f"(d[2]), "+f"(d[3])
        : "r"(a[0]), "r"(a[1]), "r"(a[2]), "r"(a[3]), "r"(b[0]), "r"(b[1]));
}
__device__ __forceinline__ void cp16(void* dst, const void* src) {
    unsigned d = (unsigned)__cvta_generic_to_shared(dst);
    asm volatile("cp.async.ca.shared.global [%0], [%1], 16;" :: "r"(d), "l"(src));
}
#define CP_COMMIT()  asm volatile("cp.async.commit_group;" ::: "memory")
#define CP_WAIT(n)   asm volatile("cp.async.wait_group %0;" :: "n"(n) : "memory")
__device__ __forceinline__ unsigned ld32(const void* p) { return *(const unsigned*)p; }

// ---------------------------------------------------------------------------
// Mask compaction: per batch, prefix-scan mask -> index list + padded count.
// ---------------------------------------------------------------------------
__global__ __launch_bounds__(1024)
void build_compact(const int* __restrict__ mask)
{
    __shared__ int wsum[32];
    const int b = blockIdx.x, t = threadIdx.x;
    const int lane = t & 31, warp = t >> 5;
    const int* mb = mask + b * SEQ;
    int m0 = mb[2*t], m1 = mb[2*t + 1];
    int loc = m0 + m1;
    int v = loc;
    #pragma unroll
    for (int o = 1; o < 32; o <<= 1) {
        int u = __shfl_up_sync(0xffffffffu, v, o);
        if (lane >= o) v += u;
    }
    if (lane == 31) wsum[warp] = v;
    __syncthreads();
    if (warp == 0) {
        int w = wsum[lane];
        #pragma unroll
        for (int o = 1; o < 32; o <<= 1) {
            int u = __shfl_up_sync(0xffffffffu, w, o);
            if (lane >= o) w += u;
        }
        wsum[lane] = w;
    }
    __syncthreads();
    const int base = (warp ? wsum[warp - 1] : 0) + v - loc;  // exclusive prefix
    const int tot  = wsum[31];
    if (m0) g_cidx[b*SEQ + base]      = 2*t;
    if (m1) g_cidx[b*SEQ + base + m0] = 2*t + 1;
    if (2*t     >= tot) g_cidx[b*SEQ + 2*t]     = 0;
    if (2*t + 1 >= tot) g_cidx[b*SEQ + 2*t + 1] = 0;
    g_cmask[b*SEQ + 2*t]     = (2*t     < tot) ? 1 : 0;
    g_cmask[b*SEQ + 2*t + 1] = (2*t + 1 < tot) ? 1 : 0;
    if (t == 0) {
        int totp = (tot + 127) & ~127;
        if (totp == 0) totp = 128;
        g_cntp[b] = totp;
    }
}

// ---------------------------------------------------------------------------
// Elementwise bf16 hi/lo split (plain, and gather-compacted variant).
// ---------------------------------------------------------------------------
__global__ __launch_bounds__(256)
void split_bf16(const float* __restrict__ x,
                __nv_bfloat16* __restrict__ hi,
                __nv_bfloat16* __restrict__ lo, int n4)
{
    int i = blockIdx.x * blockDim.x + threadIdx.x;
    if (i >= n4) return;
    float4 v = ((const float4*)x)[i];
    float vv[4] = {v.x, v.y, v.z, v.w};
    __nv_bfloat16 h[4], l[4];
    #pragma unroll
    for (int j = 0; j < 4; j++) {
        h[j] = __float2bfloat16(vv[j]);
        l[j] = __float2bfloat16(vv[j] - __bfloat162float(h[j]));
    }
    ((__nv_bfloat162*)hi)[2*i]   = __halves2bfloat162(h[0], h[1]);
    ((__nv_bfloat162*)hi)[2*i+1] = __halves2bfloat162(h[2], h[3]);
    ((__nv_bfloat162*)lo)[2*i]   = __halves2bfloat162(l[0], l[1]);
    ((__nv_bfloat162*)lo)[2*i+1] = __halves2bfloat162(l[2], l[3]);
}

// Row-gathered split: output row (b, j) reads input row (b, g_cidx[b][j]).
__global__ __launch_bounds__(256)
void split_gather_bf16(const float* __restrict__ x,
                       __nv_bfloat16* __restrict__ hi,
                       __nv_bfloat16* __restrict__ lo)
{
    int i = blockIdx.x * blockDim.x + threadIdx.x;   // float4 units
    int row  = i >> 8;            // DM/4 = 256 float4 per row
    int col4 = i & 255;
    int b = row >> 11, j = row & (SEQ - 1);
    int src = g_cidx[b*SEQ + j];
    float4 v = ((const float4*)x)[(size_t)(b*SEQ + src) * 256 + col4];
    float vv[4] = {v.x, v.y, v.z, v.w};
    __nv_bfloat16 h[4], l[4];
    #pragma unroll
    for (int k = 0; k < 4; k++) {
        h[k] = __float2bfloat16(vv[k]);
        l[k] = __float2bfloat16(vv[k] - __bfloat162float(h[k]));
    }
    ((__nv_bfloat162*)hi)[2*i]   = __halves2bfloat162(h[0], h[1]);
    ((__nv_bfloat162*)hi)[2*i+1] = __halves2bfloat162(h[2], h[3]);
    ((__nv_bfloat162*)lo)[2*i]   = __halves2bfloat162(l[0], l[1]);
    ((__nv_bfloat162*)lo)[2*i+1] = __halves2bfloat162(l[2], l[3]);
}

// ---- GEMM smem layout ------------------------------------------------------
#define PITCH   80
#define OFF_AH  0
#define OFF_AL  10240
#define OFF_BH  20480
#define OFF_BL  30720
#define STAGEB  40960
#define BKB     32

__device__ __forceinline__
void stage_load(char* sbase, int lrow, int lchk,
                const __nv_bfloat16* __restrict__ Ah,
                const __nv_bfloat16* __restrict__ Al,
                const __nv_bfloat16* __restrict__ Bh,
                const __nv_bfloat16* __restrict__ Bl,
                int m0, int n0, int k0)
{
    #pragma unroll
    for (int r = 0; r < 2; r++) {
        int row = lrow + r*64;
        cp16(sbase + OFF_AH + row*PITCH + lchk*2, Ah + (size_t)(m0+row)*DM + k0 + lchk);
        cp16(sbase + OFF_AL + row*PITCH + lchk*2, Al + (size_t)(m0+row)*DM + k0 + lchk);
        cp16(sbase + OFF_BH + row*PITCH + lchk*2, Bh + (size_t)(n0+row)*DM + k0 + lchk);
        cp16(sbase + OFF_BL + row*PITCH + lchk*2, Bl + (size_t)(n0+row)*DM + k0 + lchk);
    }
}

// ---------------------------------------------------------------------------
// 3xBF16 tensor-core GEMM mainloop (128x128 tile, BK=32, 8 warps 2x4,
// warp tile 64x32 via m16n8k16).  mode: 0=plain fp32 C
//                                       1=bf16 hi/lo head-layout (Q/K)
//                                       2=bf16 hi/lo transposed (V)
// ---------------------------------------------------------------------------
__device__ __forceinline__
void gemm_bf16_core(const __nv_bfloat16* __restrict__ Agh,
                    const __nv_bfloat16* __restrict__ Agl,
                    const __nv_bfloat16* __restrict__ Bgh,
                    const __nv_bfloat16* __restrict__ Bgl,
                    const float* __restrict__ bias,
                    int mode, float scale,
                    float* __restrict__ C,
                    __nv_bfloat16* __restrict__ Oh,
                    __nv_bfloat16* __restrict__ Ol)
{
    extern __shared__ char smem[];

    const int tid  = threadIdx.x;
    const int lane = tid & 31;
    const int warp = tid >> 5;
    const int wm   = warp >> 2;
    const int wn   = warp & 3;
    const int gid  = lane >> 2;
    const int qid  = lane & 3;
    const int m0   = blockIdx.y << 7;
    const int n0   = blockIdx.x << 7;

    const int lrow = tid >> 2;
    const int lchk = (tid & 3) << 3;

    float acc[4][4][4];
    #pragma unroll
    for (int mi = 0; mi < 4; mi++)
        #pragma unroll
        for (int ni = 0; ni < 4; ni++)
            #pragma unroll
            for (int r = 0; r < 4; r++) acc[mi][ni][r] = 0.f;

    const int NKB = DM / BKB;

    stage_load(smem, lrow, lchk, Agh, Agl, Bgh, Bgl, m0, n0, 0);
    CP_COMMIT();

    for (int kb = 0; kb < NKB; kb++) {
        if (kb + 1 < NKB) {
            stage_load(smem + ((kb+1)&1)*STAGEB, lrow, lchk,
                       Agh, Agl, Bgh, Bgl, m0, n0, (kb+1)*BKB);
            CP_COMMIT();
            CP_WAIT(1);
        } else {
            CP_WAIT(0);
        }
        __syncthreads();

        char* sb = smem + (kb & 1) * STAGEB;

        #pragma unroll
        for (int ks = 0; ks < 2; ks++) {
            unsigned afh[4][4], afl[4][4];
            #pragma unroll
            for (int mi = 0; mi < 4; mi++) {
                int row = wm*64 + mi*16 + gid;
                #pragma unroll
                for (int r = 0; r < 4; r++) {
                    int rr = row + ((r & 1) << 3);
                    int w  = ks*8 + qid + ((r >> 1) << 2);
                    afh[mi][r] = ld32(sb + OFF_AH + rr*PITCH + w*4);
                    afl[mi][r] = ld32(sb + OFF_AL + rr*PITCH + w*4);
                }
            }
            #pragma unroll
            for (int ni = 0; ni < 4; ni++) {
                int col = wn*32 + ni*8 + gid;
                unsigned bfh[2], bfl[2];
                #pragma unroll
                for (int r = 0; r < 2; r++) {
                    int w = ks*8 + qid + (r << 2);
                    bfh[r] = ld32(sb + OFF_BH + col*PITCH + w*4);
                    bfl[r] = ld32(sb + OFF_BL + col*PITCH + w*4);
                }
                #pragma unroll
                for (int mi = 0; mi < 4; mi++) {
                    mma16(acc[mi][ni], afh[mi], bfh);
                    mma16(acc[mi][ni], afh[mi], bfl);
                    mma16(acc[mi][ni], afl[mi], bfh);
                }
            }
        }
        __syncthreads();
    }

    // ---- epilogue ----
    #pragma unroll
    for (int mi = 0; mi < 4; mi++) {
        #pragma unroll
        for (int ni = 0; ni < 4; ni++) {
            int row = m0 + wm*64 + mi*16 + gid;
            int col = n0 + wn*32 + ni*8 + (qid << 1);
            float b0 = bias[col], b1 = bias[col + 1];
            float v00 = (acc[mi][ni][0] + b0) * scale;
            float v01 = (acc[mi][ni][1] + b1) * scale;
            float v10 = (acc[mi][ni][2] + b0) * scale;
            float v11 = (acc[mi][ni][3] + b1) * scale;
            if (mode == 0) {
                *(float2*)&C[(size_t)row       * DM + col] = make_float2(v00, v01);
                *(float2*)&C[(size_t)(row + 8) * DM + col] = make_float2(v10, v11);
            } else if (mode == 1) {
                int h = col >> 6, d = col & 63;
                {
                    int t = row, bbx = t >> 11, s = t & (SEQ - 1);
                    size_t off = ((size_t)((bbx*NH + h)*SEQ) + s)*DK + d;
                    *(__nv_bfloat162*)&Oh[off] = __halves2bfloat162(bhi(v00), bhi(v01));
                    *(__nv_bfloat162*)&Ol[off] = __halves2bfloat162(blo(v00), blo(v01));
                }
                {
                    int t = row + 8, bbx = t >> 11, s = t & (SEQ - 1);
                    size_t off = ((size_t)((bbx*NH + h)*SEQ) + s)*DK + d;
                    *(__nv_bfloat162*)&Oh[off] = __halves2bfloat162(bhi(v10), bhi(v11));
                    *(__nv_bfloat162*)&Ol[off] = __halves2bfloat162(blo(v10), blo(v11));
                }
            } else {
                // V transposed: [B,H,DK,SEQ]
                int h = col >> 6, d = col & 63;
                int bbx = row >> 11, s = row & (SEQ - 1);
                size_t base = (size_t)(bbx*NH + h) * DK;
                Oh[(base + d    )*SEQ + s    ] = bhi(v00);
                Oh[(base + d + 1)*SEQ + s    ] = bhi(v01);
                Oh[(base + d    )*SEQ + s + 8] = bhi(v10);
                Oh[(base + d + 1)*SEQ + s + 8] = bhi(v11);
                Ol[(base + d    )*SEQ + s    ] = blo(v00);
                Ol[(base + d + 1)*SEQ + s    ] = blo(v01);
                Ol[(base + d    )*SEQ + s + 8] = blo(v10);
                Ol[(base + d + 1)*SEQ + s + 8] = blo(v11);
            }
        }
    }
}

// Fused Q/K/V projections. K/V read compacted inputs; tiles in the padding
// region of a batch early-exit (their outputs are never consumed).
__global__ __launch_bounds__(256, 2)
void gemm_qkv_bf16(const float* __restrict__ bq, const float* __restrict__ bk,
                   const float* __restrict__ bv)
{
    const int z = blockIdx.z;
    if (z >= 1) {
        int m0i = blockIdx.y << 7;
        if ((m0i & (SEQ - 1)) >= g_cntp[m0i >> 11]) return;
    }
    const __nv_bfloat16* Agh = g_Xh  + (size_t)z * TOK * DM;
    const __nv_bfloat16* Agl = g_Xl  + (size_t)z * TOK * DM;
    const __nv_bfloat16* Wgh = g_WWh + (size_t)z * DM * DM;
    const __nv_bfloat16* Wgl = g_WWl + (size_t)z * DM * DM;
    if (z == 0)
        gemm_bf16_core(Agh, Agl, Wgh, Wgl, bq, 1, 0.125f, nullptr, g_Qhh, g_Qll);
    else if (z == 1)
        gemm_bf16_core(Agh, Agl, Wgh, Wgl, bk, 1, 1.0f, nullptr, g_Khh, g_Kll);
    else
        gemm_bf16_core(Agh, Agl, Wgh, Wgl, bv, 2, 1.0f, nullptr, g_Vth, g_Vtl);
}

__global__ __launch_bounds__(256, 2)
void gemm_out_bf16(const float* __restrict__ bo, float* __restrict__ out)
{
    gemm_bf16_core(g_Ch, g_Cl,
                   g_WWh + (size_t)3 * DM * DM,
                   g_WWl + (size_t)3 * DM * DM,
                   bo, 0, 1.0f, out, nullptr, nullptr);
}

// ---------------------------------------------------------------------------
// Tensor-core flash attention over COMPACTED keys (cntp per batch).
// ---------------------------------------------------------------------------
#define QP      144
#define Q_H     0
#define Q_L     (128*QP)
#define QTOT    (2*128*QP)
#define KV_KH   0
#define KV_KL   (64*QP)
#define KV_VH   (2*64*QP)
#define KV_VL   (3*64*QP)
#define KV_MK   (4*64*QP)
#define KV_SZ   (4*64*QP + 256)
#define FL_SMEM (QTOT + 2*KV_SZ)

__device__ __forceinline__
void stage_kv(char* sb, int tid,
              const __nv_bfloat16* __restrict__ Khg,
              const __nv_bfloat16* __restrict__ Klg,
              const __nv_bfloat16* __restrict__ Vhg,
              const __nv_bfloat16* __restrict__ Vlg,
              const int* __restrict__ mb, int k0)
{
    #pragma unroll
    for (int it = 0; it < 2; it++) {
        int idx = tid + it*256;
        int row = idx >> 3, ch = idx & 7;
        cp16(sb + KV_KH + row*QP + ch*16, Khg + (size_t)(k0 + row)*DK + ch*8);
        cp16(sb + KV_KL + row*QP + ch*16, Klg + (size_t)(k0 + row)*DK + ch*8);
        cp16(sb + KV_VH + row*QP + ch*16, Vhg + (size_t)row*SEQ + k0 + ch*8);
        cp16(sb + KV_VL + row*QP + ch*16, Vlg + (size_t)row*SEQ + k0 + ch*8);
    }
    if (tid < 16) cp16(sb + KV_MK + tid*16, mb + k0 + tid*4);
}

__global__ __launch_bounds__(256, 2)
void flash_mma()
{
    extern __shared__ char sm[];
    const int tid  = threadIdx.x;
    const int lane = tid & 31;
    const int warp = tid >> 5;
    const int gid  = lane >> 2;
    const int qid  = lane & 3;
    const int q0   = blockIdx.x << 7;
    const int h    = blockIdx.y;
    const int b    = blockIdx.z;

    const __nv_bfloat16* Qhg = g_Qhh + ((size_t)((b*NH + h)*SEQ) + q0)*DK;
    const __nv_bfloat16* Qlg = g_Qll + ((size_t)((b*NH + h)*SEQ) + q0)*DK;
    const __nv_bfloat16* Khg = g_Khh + (size_t)(b*NH + h)*SEQ*DK;
    const __nv_bfloat16* Klg = g_Kll + (size_t)(b*NH + h)*SEQ*DK;
    const __nv_bfloat16* Vhg = g_Vth + (size_t)(b*NH + h)*DK*SEQ;
    const __nv_bfloat16* Vlg = g_Vtl + (size_t)(b*NH + h)*DK*SEQ;
    const int* mb = g_cmask + b * SEQ;
    const int ktmax = g_cntp[b] >> 6;

    #pragma unroll
    for (int it = 0; it < 4; it++) {
        int idx = tid + it*256;
        int row = idx >> 3, ch = idx & 7;
        cp16(sm + Q_H + row*QP + ch*16, Qhg + (size_t)row*DK + ch*8);
        cp16(sm + Q_L + row*QP + ch*16, Qlg + (size_t)row*DK + ch*8);
    }
    stage_kv(sm + QTOT, tid, Khg, Klg, Vhg, Vlg, mb, 0);
    CP_COMMIT();

    float O[8][4];
    #pragma unroll
    for (int ni = 0; ni < 8; ni++)
        #pragma unroll
        for (int r = 0; r < 4; r++) O[ni][r] = 0.f;
    float m_[2] = {-1e30f, -1e30f}, l_[2] = {0.f, 0.f};

    const int row0 = warp*16 + gid;

    for (int kt = 0; kt < ktmax; kt++) {
        char* sb = sm + QTOT + (kt & 1)*KV_SZ;
        if (kt + 1 < ktmax) {
            stage_kv(sm + QTOT + ((kt+1) & 1)*KV_SZ, tid,
                     Khg, Klg, Vhg, Vlg, mb, (kt+1) << 6);
            CP_COMMIT();
            CP_WAIT(1);
        } else {
            CP_WAIT(0);
        }
        __syncthreads();

        float c[8][4];
        #pragma unroll
        for (int ni = 0; ni < 8; ni++)
            #pragma unroll
            for (int r = 0; r < 4; r++) c[ni][r] = 0.f;

        #pragma unroll
        for (int ks = 0; ks < 4; ks++) {
            int w0 = (ks*8 + qid)*4;
            unsigned ah[4], al[4];
            ah[0] = ld32(sm + Q_H + row0*QP + w0);
            ah[1] = ld32(sm + Q_H + (row0+8)*QP + w0);
            ah[2] = ld32(sm + Q_H + row0*QP + w0 + 16);
            ah[3] = ld32(sm + Q_H + (row0+8)*QP + w0 + 16);
            al[0] = ld32(sm + Q_L + row0*QP + w0);
            al[1] = ld32(sm + Q_L + (row0+8)*QP + w0);
            al[2] = ld32(sm + Q_L + row0*QP + w0 + 16);
            al[3] = ld32(sm + Q_L + (row0+8)*QP + w0 + 16);
            #pragma unroll
            for (int ni = 0; ni < 8; ni++) {
                int kr = ni*8 + gid;
                unsigned bh[2], bl[2];
                bh[0] = ld32(sb + KV_KH + kr*QP + w0);
                bh[1] = ld32(sb + KV_KH + kr*QP + w0 + 16);
                bl[0] = ld32(sb + KV_KL + kr*QP + w0);
                bl[1] = ld32(sb + KV_KL + kr*QP + w0 + 16);
                mma16(c[ni], ah, bh);
                mma16(c[ni], ah, bl);
                mma16(c[ni], al, bh);
            }
        }

        const int* mks = (const int*)(sb + KV_MK);
        #pragma unroll
        for (int ni = 0; ni < 8; ni++) {
            int c0 = ni*8 + qid*2;
            if (mks[c0]     == 0) { c[ni][0] = -1.0e9f; c[ni][2] = -1.0e9f; }
            if (mks[c0 + 1] == 0) { c[ni][1] = -1.0e9f; c[ni][3] = -1.0e9f; }
        }

        #pragma unroll
        for (int r = 0; r < 2; r++) {
            const int bx = r*2;
            float rm = -1e30f;
            #pragma unroll
            for (int ni = 0; ni < 8; ni++)
                rm = fmaxf(rm, fmaxf(c[ni][bx], c[ni][bx+1]));
            rm = fmaxf(rm, __shfl_xor_sync(0xffffffffu, rm, 1));
            rm = fmaxf(rm, __shfl_xor_sync(0xffffffffu, rm, 2));
            float nm   = fmaxf(m_[r], rm);
            float corr = __expf(m_[r] - nm);
            float rs = 0.f;
            #pragma unroll
            for (int ni = 0; ni < 8; ni++) {
                float p0 = __expf(c[ni][bx]   - nm);
                float p1 = __expf(c[ni][bx+1] - nm);
                c[ni][bx] = p0; c[ni][bx+1] = p1;
                rs += p0 + p1;
            }
            rs += __shfl_xor_sync(0xffffffffu, rs, 1);
            rs += __shfl_xor_sync(0xffffffffu, rs, 2);
            l_[r] = l_[r] * corr + rs;
            m_[r] = nm;
            #pragma unroll
            for (int ni = 0; ni < 8; ni++) {
                O[ni][bx]   *= corr;
                O[ni][bx+1] *= corr;
            }
        }

        #pragma unroll
        for (int ks = 0; ks < 4; ks++) {
            float p[8] = {c[2*ks][0],   c[2*ks][1],   c[2*ks][2],   c[2*ks][3],
                          c[2*ks+1][0], c[2*ks+1][1], c[2*ks+1][2], c[2*ks+1][3]};
            unsigned pah[4], pal[4];
            pah[0] = packbf(p[0], p[1]);
            pah[1] = packbf(p[2], p[3]);
            pah[2] = packbf(p[4], p[5]);
            pah[3] = packbf(p[6], p[7]);
            float e[8];
            #pragma unroll
            for (int i = 0; i < 8; i++)
                e[i] = p[i] - bf2f(__float2bfloat16(p[i]));
            pal[0] = packbf(e[0], e[1]);
            pal[1] = packbf(e[2], e[3]);
            pal[2] = packbf(e[4], e[5]);
            pal[3] = packbf(e[6], e[7]);

            int w0 = (ks*8 + qid)*4;
            #pragma unroll
            for (int ni = 0; ni < 8; ni++) {
                int dr = ni*8 + gid;
                unsigned vh[2], vl[2];
                vh[0] = ld32(sb + KV_VH + dr*QP + w0);
                vh[1] = ld32(sb + KV_VH + dr*QP + w0 + 16);
                vl[0] = ld32(sb + KV_VL + dr*QP + w0);
                vl[1] = ld32(sb + KV_VL + dr*QP + w0 + 16);
                mma16(O[ni], pah, vh);
                mma16(O[ni], pah, vl);
                mma16(O[ni], pal, vh);
            }
        }
        __syncthreads();
    }

    float inv0 = 1.0f / l_[0], inv1 = 1.0f / l_[1];
    int s = q0 + warp*16 + gid;
    size_t t0 = (size_t)(b*SEQ + s)*DM + h*DK;
    size_t t1 = t0 + (size_t)8*DM;
    #pragma unroll
    for (int ni = 0; ni < 8; ni++) {
        int d = ni*8 + (qid << 1);
        float x0 = O[ni][0]*inv0, x1 = O[ni][1]*inv0;
        float y0 = O[ni][2]*inv1, y1 = O[ni][3]*inv1;
        *(__nv_bfloat162*)&g_Ch[t0 + d] = __halves2bfloat162(bhi(x0), bhi(x1));
        *(__nv_bfloat162*)&g_Cl[t0 + d] = __halves2bfloat162(blo(x0), blo(x1));
        *(__nv_bfloat162*)&g_Ch[t1 + d] = __halves2bfloat162(bhi(y0), bhi(y1));
        *(__nv_bfloat162*)&g_Cl[t1 + d] = __halves2bfloat162(blo(y0), blo(y1));
    }
}

// ---------------------------------------------------------------------------
extern "C" void kernel_launch(void* const* d_in, const int* in_sizes, int n_in,
                              void* d_out, int out_size)
{
    (void)in_sizes; (void)n_in; (void)out_size;
    const float* query = (const float*)d_in[0];
    const float* key_  = (const float*)d_in[1];
    const float* value = (const float*)d_in[2];
    const int*   mask  = (const int*)  d_in[3];
    const float* Wq = (const float*)d_in[4];
    const float* bq = (const float*)d_in[5];
    const float* Wk = (const float*)d_in[6];
    const float* bk = (const float*)d_in[7];
    const float* Wv = (const float*)d_in[8];
    const float* bv = (const float*)d_in[9];
    const float* Wo = (const float*)d_in[10];
    const float* bo = (const float*)d_in[11];
    float* out = (float*)d_out;

    __nv_bfloat16 *Xh, *Xl, *WWh, *WWl;
    cudaGetSymbolAddress((void**)&Xh,  g_Xh);
    cudaGetSymbolAddress((void**)&Xl,  g_Xl);
    cudaGetSymbolAddress((void**)&WWh, g_WWh);
    cudaGetSymbolAddress((void**)&WWl, g_WWl);

    const int n4x = TOK * DM / 4;
    const int n4w = DM * DM / 4;

    // mask compaction first (prefix scan per batch)
    build_compact<<<BB, 1024>>>(mask);

    // pre-split inputs + weights into bf16 hi/lo (key/value row-gathered)
    split_bf16<<<n4x/256, 256>>>(query, Xh, Xl, n4x);
    split_gather_bf16<<<n4x/256, 256>>>(key_,  Xh + (size_t)TOK*DM,
                                               Xl + (size_t)TOK*DM);
    split_gather_bf16<<<n4x/256, 256>>>(value, Xh + (size_t)2*TOK*DM,
                                               Xl + (size_t)2*TOK*DM);
    split_bf16<<<n4w/256, 256>>>(Wq, WWh,                     WWl,                   n4w);
    split_bf16<<<n4w/256, 256>>>(Wk, WWh + (size_t)DM*DM,     WWl + (size_t)DM*DM,   n4w);
    split_bf16<<<n4w/256, 256>>>(Wv, WWh + (size_t)2*DM*DM,   WWl + (size_t)2*DM*DM, n4w);
    split_bf16<<<n4w/256, 256>>>(Wo, WWh + (size_t)3*DM*DM,   WWl + (size_t)3*DM*DM, n4w);

    // QKV projections (K/V compacted; padding tiles early-exit)
    cudaFuncSetAttribute(gemm_qkv_bf16,
                         cudaFuncAttributeMaxDynamicSharedMemorySize, 2*STAGEB);
    gemm_qkv_bf16<<<dim3(DM/128, TOK/128, 3), 256, 2*STAGEB>>>(bq, bk, bv);

    // tensor-core flash attention over compacted keys
    cudaFuncSetAttribute(flash_mma,
                         cudaFuncAttributeMaxDynamicSharedMemorySize, FL_SMEM);
    flash_mma<<<dim3(SEQ/128, NH, BB), 256, FL_SMEM>>>();

    // output projection
    cudaFuncSetAttribute(gemm_out_bf16,
                         cudaFuncAttributeMaxDynamicSharedMemorySize, 2*STAGEB);
    gemm_out_bf16<<<dim3(DM/128, TOK/128), 256, 2*STAGEB>>>(bo, out);
}

// round 12
// speedup vs baseline: 7.4978x; 1.4046x over previous
#include <cuda_runtime.h>
#include <cuda_fp16.h>
#include <math.h>

#define DM   1024
#define NH   16
#define DK   64
#define SEQ  2048
#define BB   2
#define TOK  (BB*SEQ)   // 4096

// ---------------- scratch (__device__ globals; no allocation allowed) -------
__device__ __half g_Xh[3*TOK*DM];      // q,kC,vC activations (fp16 hi only)
__device__ __half g_WWh[4*DM*DM];      // Wq,Wk,Wv,Wo hi
__device__ __half g_WWl[4*DM*DM];      // lo
__device__ __half g_Qhh[BB*NH*SEQ*DK]; // Q [B,H,S,DK], pre-scaled 1/8 (hi only)
__device__ __half g_Khh[BB*NH*SEQ*DK]; // K compacted hi
__device__ __half g_Kll[BB*NH*SEQ*DK]; // K lo
__device__ __half g_Vth[BB*NH*DK*SEQ]; // V compacted transposed hi
__device__ __half g_Vtl[BB*NH*DK*SEQ]; // V lo
__device__ __half g_Ch[TOK*DM];        // ctx (hi only)
// mask compaction state
__device__ int g_cidx[BB*SEQ];
__device__ int g_cmask[BB*SEQ];
__device__ int g_cntp[BB];

// ---- helpers ---------------------------------------------------------------
__device__ __forceinline__ __half hhi(float x) { return __float2half(x); }
__device__ __forceinline__ __half hlo(float x) {
    return __float2half(x - __half2float(__float2half(x)));
}
__device__ __forceinline__ unsigned packh(float lo, float hi) {
    __half2 t = __floats2half2_rn(lo, hi);
    return *(unsigned*)&t;
}
__device__ __forceinline__ void mma16h(float d[4], const unsigned a[4],
                                       const unsigned b[2]) {
    asm("mma.sync.aligned.m16n8k16.row.col.f32.f16.f16.f32 "
        "{%0,%1,%2,%3}, {%4,%5,%6,%7}, {%8,%9}, {%0,%1,%2,%3};"
        : "+f"(d[0]), "+f"(d[1]), "+f"(d[2]), "+f"(d[3])
        : "r"(a[0]), "r"(a[1]), "r"(a[2]), "r"(a[3]), "r"(b[0]), "r"(b[1]));
}
__device__ __forceinline__ void cp16(void* dst, const void* src) {
    unsigned d = (unsigned)__cvta_generic_to_shared(dst);
    asm volatile("cp.async.ca.shared.global [%0], [%1], 16;" :: "r"(d), "l"(src));
}
#define CP_COMMIT()  asm volatile("cp.async.commit_group;" ::: "memory")
#define CP_WAIT(n)   asm volatile("cp.async.wait_group %0;" :: "n"(n) : "memory")
__device__ __forceinline__ unsigned ld32(const void* p) { return *(const unsigned*)p; }

// ---------------------------------------------------------------------------
// Mask compaction (prefix scan per batch).
// ---------------------------------------------------------------------------
__global__ __launch_bounds__(1024)
void build_compact(const int* __restrict__ mask)
{
    __shared__ int wsum[32];
    const int b = blockIdx.x, t = threadIdx.x;
    const int lane = t & 31, warp = t >> 5;
    const int* mb = mask + b * SEQ;
    int m0 = mb[2*t], m1 = mb[2*t + 1];
    int loc = m0 + m1;
    int v = loc;
    #pragma unroll
    for (int o = 1; o < 32; o <<= 1) {
        int u = __shfl_up_sync(0xffffffffu, v, o);
        if (lane >= o) v += u;
    }
    if (lane == 31) wsum[warp] = v;
    __syncthreads();
    if (warp == 0) {
        int w = wsum[lane];
        #pragma unroll
        for (int o = 1; o < 32; o <<= 1) {
            int u = __shfl_up_sync(0xffffffffu, w, o);
            if (lane >= o) w += u;
        }
        wsum[lane] = w;
    }
    __syncthreads();
    const int base = (warp ? wsum[warp - 1] : 0) + v - loc;
    const int tot  = wsum[31];
    if (m0) g_cidx[b*SEQ + base]      = 2*t;
    if (m1) g_cidx[b*SEQ + base + m0] = 2*t + 1;
    if (2*t     >= tot) g_cidx[b*SEQ + 2*t]     = 0;
    if (2*t + 1 >= tot) g_cidx[b*SEQ + 2*t + 1] = 0;
    g_cmask[b*SEQ + 2*t]     = (2*t     < tot) ? 1 : 0;
    g_cmask[b*SEQ + 2*t + 1] = (2*t + 1 < tot) ? 1 : 0;
    if (t == 0) {
        int totp = (tot + 127) & ~127;
        if (totp == 0) totp = 128;
        g_cntp[b] = totp;
    }
}

// ---------------------------------------------------------------------------
// Split / cast kernels.
// ---------------------------------------------------------------------------
__global__ __launch_bounds__(256)
void cast_half(const float* __restrict__ x, __half* __restrict__ hi, int n4)
{
    int i = blockIdx.x * blockDim.x + threadIdx.x;
    if (i >= n4) return;
    float4 v = ((const float4*)x)[i];
    ((__half2*)hi)[2*i]   = __floats2half2_rn(v.x, v.y);
    ((__half2*)hi)[2*i+1] = __floats2half2_rn(v.z, v.w);
}

// Row-gathered cast for key/value activations (z selects input).
__global__ __launch_bounds__(256)
void gather_cast_half(const float* __restrict__ k_in,
                      const float* __restrict__ v_in)
{
    const int z = blockIdx.y;
    const float* x = z ? v_in : k_in;
    __half* hi = g_Xh + (size_t)(1 + z) * TOK * DM;
    int i = blockIdx.x * blockDim.x + threadIdx.x;
    int row = i >> 8, col4 = i & 255;
    int b = row >> 11, j = row & (SEQ - 1);
    int src = g_cidx[b*SEQ + j];
    float4 v = ((const float4*)x)[(size_t)(b*SEQ + src) * 256 + col4];
    ((__half2*)hi)[2*i]   = __floats2half2_rn(v.x, v.y);
    ((__half2*)hi)[2*i+1] = __floats2half2_rn(v.z, v.w);
}

// Weight hi/lo split, z selects matrix.
__global__ __launch_bounds__(256)
void split_w(const float* __restrict__ Wq, const float* __restrict__ Wk,
             const float* __restrict__ Wv, const float* __restrict__ Wo)
{
    const int z = blockIdx.y;
    const float* w = (z == 0) ? Wq : (z == 1) ? Wk : (z == 2) ? Wv : Wo;
    __half* hi = g_WWh + (size_t)z * DM * DM;
    __half* lo = g_WWl + (size_t)z * DM * DM;
    int i = blockIdx.x * blockDim.x + threadIdx.x;
    float4 v = ((const float4*)w)[i];
    float vv[4] = {v.x, v.y, v.z, v.w};
    __half h[4], l[4];
    #pragma unroll
    for (int j = 0; j < 4; j++) {
        h[j] = __float2half(vv[j]);
        l[j] = __float2half(vv[j] - __half2float(h[j]));
    }
    ((__half2*)hi)[2*i]   = __halves2half2(h[0], h[1]);
    ((__half2*)hi)[2*i+1] = __halves2half2(h[2], h[3]);
    ((__half2*)lo)[2*i]   = __halves2half2(l[0], l[1]);
    ((__half2*)lo)[2*i+1] = __halves2half2(l[2], l[3]);
}

// ---- GEMM smem layout ------------------------------------------------------
#define PITCH   80
#define OFF_AH  0
#define OFF_BH  10240
#define OFF_BL  20480
#define STAGEB  30720
#define BKB     32

__device__ __forceinline__
void stage_load(char* sbase, int lrow, int lchk,
                const __half* __restrict__ Ah,
                const __half* __restrict__ Bh,
                const __half* __restrict__ Bl,
                int m0, int n0, int k0)
{
    #pragma unroll
    for (int r = 0; r < 2; r++) {
        int row = lrow + r*64;
        cp16(sbase + OFF_AH + row*PITCH + lchk*2, Ah + (size_t)(m0+row)*DM + k0 + lchk);
        cp16(sbase + OFF_BH + row*PITCH + lchk*2, Bh + (size_t)(n0+row)*DM + k0 + lchk);
        cp16(sbase + OFF_BL + row*PITCH + lchk*2, Bl + (size_t)(n0+row)*DM + k0 + lchk);
    }
}

// ---------------------------------------------------------------------------
// 2-term fp16 tensor-core GEMM: C = A_h @ (W_h + W_l)^T + bias.
// 128x128 tile, BK=32, 8 warps (2m x 4n), warp tile 64x32, m16n8k16.
// mode: 0=fp32 C; 1=head-layout hi+lo (K); 2=transposed hi+lo (V);
//       3=head-layout hi only (Q, scaled).
// ---------------------------------------------------------------------------
__device__ __forceinline__
void gemm_fp16_core(const __half* __restrict__ Agh,
                    const __half* __restrict__ Bgh,
                    const __half* __restrict__ Bgl,
                    const float* __restrict__ bias,
                    int mode, float scale,
                    float* __restrict__ C,
                    __half* __restrict__ Oh,
                    __half* __restrict__ Ol)
{
    extern __shared__ char smem[];

    const int tid  = threadIdx.x;
    const int lane = tid & 31;
    const int warp = tid >> 5;
    const int wm   = warp >> 2;
    const int wn   = warp & 3;
    const int gid  = lane >> 2;
    const int qid  = lane & 3;
    const int m0   = blockIdx.y << 7;
    const int n0   = blockIdx.x << 7;

    const int lrow = tid >> 2;
    const int lchk = (tid & 3) << 3;

    float acc[4][4][4];
    #pragma unroll
    for (int mi = 0; mi < 4; mi++)
        #pragma unroll
        for (int ni = 0; ni < 4; ni++)
            #pragma unroll
            for (int r = 0; r < 4; r++) acc[mi][ni][r] = 0.f;

    const int NKB = DM / BKB;

    stage_load(smem, lrow, lchk, Agh, Bgh, Bgl, m0, n0, 0);
    CP_COMMIT();

    for (int kb = 0; kb < NKB; kb++) {
        if (kb + 1 < NKB) {
            stage_load(smem + ((kb+1)&1)*STAGEB, lrow, lchk,
                       Agh, Bgh, Bgl, m0, n0, (kb+1)*BKB);
            CP_COMMIT();
            CP_WAIT(1);
        } else {
            CP_WAIT(0);
        }
        __syncthreads();

        char* sb = smem + (kb & 1) * STAGEB;

        #pragma unroll
        for (int ks = 0; ks < 2; ks++) {
            unsigned afh[4][4];
            #pragma unroll
            for (int mi = 0; mi < 4; mi++) {
                int row = wm*64 + mi*16 + gid;
                #pragma unroll
                for (int r = 0; r < 4; r++) {
                    int rr = row + ((r & 1) << 3);
                    int w  = ks*8 + qid + ((r >> 1) << 2);
                    afh[mi][r] = ld32(sb + OFF_AH + rr*PITCH + w*4);
                }
            }
            #pragma unroll
            for (int ni = 0; ni < 4; ni++) {
                int col = wn*32 + ni*8 + gid;
                unsigned bfh[2], bfl[2];
                #pragma unroll
                for (int r = 0; r < 2; r++) {
                    int w = ks*8 + qid + (r << 2);
                    bfh[r] = ld32(sb + OFF_BH + col*PITCH + w*4);
                    bfl[r] = ld32(sb + OFF_BL + col*PITCH + w*4);
                }
                #pragma unroll
                for (int mi = 0; mi < 4; mi++) {
                    mma16h(acc[mi][ni], afh[mi], bfh);
                    mma16h(acc[mi][ni], afh[mi], bfl);
                }
            }
        }
        __syncthreads();
    }

    // ---- epilogue ----
    #pragma unroll
    for (int mi = 0; mi < 4; mi++) {
        #pragma unroll
        for (int ni = 0; ni < 4; ni++) {
            int row = m0 + wm*64 + mi*16 + gid;
            int col = n0 + wn*32 + ni*8 + (qid << 1);
            float b0 = bias[col], b1 = bias[col + 1];
            float v00 = (acc[mi][ni][0] + b0) * scale;
            float v01 = (acc[mi][ni][1] + b1) * scale;
            float v10 = (acc[mi][ni][2] + b0) * scale;
            float v11 = (acc[mi][ni][3] + b1) * scale;
            if (mode == 0) {
                *(float2*)&C[(size_t)row       * DM + col] = make_float2(v00, v01);
                *(float2*)&C[(size_t)(row + 8) * DM + col] = make_float2(v10, v11);
            } else if (mode == 1 || mode == 3) {
                int h = col >> 6, d = col & 63;
                {
                    int t = row, bbx = t >> 11, s = t & (SEQ - 1);
                    size_t off = ((size_t)((bbx*NH + h)*SEQ) + s)*DK + d;
                    *(__half2*)&Oh[off] = __halves2half2(hhi(v00), hhi(v01));
                    if (mode == 1)
                        *(__half2*)&Ol[off] = __halves2half2(hlo(v00), hlo(v01));
                }
                {
                    int t = row + 8, bbx = t >> 11, s = t & (SEQ - 1);
                    size_t off = ((size_t)((bbx*NH + h)*SEQ) + s)*DK + d;
                    *(__half2*)&Oh[off] = __halves2half2(hhi(v10), hhi(v11));
                    if (mode == 1)
                        *(__half2*)&Ol[off] = __halves2half2(hlo(v10), hlo(v11));
                }
            } else {
                int h = col >> 6, d = col & 63;
                int bbx = row >> 11, s = row & (SEQ - 1);
                size_t base = (size_t)(bbx*NH + h) * DK;
                Oh[(base + d    )*SEQ + s    ] = hhi(v00);
                Oh[(base + d + 1)*SEQ + s    ] = hhi(v01);
                Oh[(base + d    )*SEQ + s + 8] = hhi(v10);
                Oh[(base + d + 1)*SEQ + s + 8] = hhi(v11);
                Ol[(base + d    )*SEQ + s    ] = hlo(v00);
                Ol[(base + d + 1)*SEQ + s    ] = hlo(v01);
                Ol[(base + d    )*SEQ + s + 8] = hlo(v10);
                Ol[(base + d + 1)*SEQ + s + 8] = hlo(v11);
            }
        }
    }
}

__global__ __launch_bounds__(256, 2)
void gemm_qkv_fp16(const float* __restrict__ bq, const float* __restrict__ bk,
                   const float* __restrict__ bv)
{
    const int z = blockIdx.z;
    if (z >= 1) {
        int m0i = blockIdx.y << 7;
        if ((m0i & (SEQ - 1)) >= g_cntp[m0i >> 11]) return;
    }
    const __half* Agh = g_Xh  + (size_t)z * TOK * DM;
    const __half* Wgh = g_WWh + (size_t)z * DM * DM;
    const __half* Wgl = g_WWl + (size_t)z * DM * DM;
    if (z == 0)
        gemm_fp16_core(Agh, Wgh, Wgl, bq, 3, 0.125f, nullptr, g_Qhh, nullptr);
    else if (z == 1)
        gemm_fp16_core(Agh, Wgh, Wgl, bk, 1, 1.0f, nullptr, g_Khh, g_Kll);
    else
        gemm_fp16_core(Agh, Wgh, Wgl, bv, 2, 1.0f, nullptr, g_Vth, g_Vtl);
}

__global__ __launch_bounds__(256, 2)
void gemm_out_fp16(const float* __restrict__ bo, float* __restrict__ out)
{
    gemm_fp16_core(g_Ch,
                   g_WWh + (size_t)3 * DM * DM,
                   g_WWl + (size_t)3 * DM * DM,
                   bo, 0, 1.0f, out, nullptr, nullptr);
}

// ---------------------------------------------------------------------------
// fp16 2-term flash attention over compacted keys.
// ---------------------------------------------------------------------------
#define QP      144
#define Q_H     0
#define QTOT    (128*QP)            // 18432 (Q hi only)
#define KV_KH   0
#define KV_KL   (64*QP)
#define KV_VH   (2*64*QP)
#define KV_VL   (3*64*QP)
#define KV_MK   (4*64*QP)
#define KV_SZ   (4*64*QP + 256)
#define FL_SMEM (QTOT + 2*KV_SZ)    // 92672

__device__ __forceinline__
void stage_kv(char* sb, int tid,
              const __half* __restrict__ Khg, const __half* __restrict__ Klg,
              const __half* __restrict__ Vhg, const __half* __restrict__ Vlg,
              const int* __restrict__ mb, int k0)
{
    #pragma unroll
    for (int it = 0; it < 2; it++) {
        int idx = tid + it*256;
        int row = idx >> 3, ch = idx & 7;
        cp16(sb + KV_KH + row*QP + ch*16, Khg + (size_t)(k0 + row)*DK + ch*8);
        cp16(sb + KV_KL + row*QP + ch*16, Klg + (size_t)(k0 + row)*DK + ch*8);
        cp16(sb + KV_VH + row*QP + ch*16, Vhg + (size_t)row*SEQ + k0 + ch*8);
        cp16(sb + KV_VL + row*QP + ch*16, Vlg + (size_t)row*SEQ + k0 + ch*8);
    }
    if (tid < 16) cp16(sb + KV_MK + tid*16, mb + k0 + tid*4);
}

__global__ __launch_bounds__(256, 2)
void flash_mma()
{
    extern __shared__ char sm[];
    const int tid  = threadIdx.x;
    const int lane = tid & 31;
    const int warp = tid >> 5;
    const int gid  = lane >> 2;
    const int qid  = lane & 3;
    const int q0   = blockIdx.x << 7;
    const int h    = blockIdx.y;
    const int b    = blockIdx.z;

    const __half* Qhg = g_Qhh + ((size_t)((b*NH + h)*SEQ) + q0)*DK;
    const __half* Khg = g_Khh + (size_t)(b*NH + h)*SEQ*DK;
    const __half* Klg = g_Kll + (size_t)(b*NH + h)*SEQ*DK;
    const __half* Vhg = g_Vth + (size_t)(b*NH + h)*DK*SEQ;
    const __half* Vlg = g_Vtl + (size_t)(b*NH + h)*DK*SEQ;
    const int* mb = g_cmask + b * SEQ;
    const int ktmax = g_cntp[b] >> 6;

    // stage full Q tile: 128 rows x 8 chunks = 1024 cp16 ops -> 4 iterations
    #pragma unroll
    for (int it = 0; it < 4; it++) {
        int idx = tid + it*256;
        int row = idx >> 3, ch = idx & 7;
        cp16(sm + Q_H + row*QP + ch*16, Qhg + (size_t)row*DK + ch*8);
    }
    stage_kv(sm + QTOT, tid, Khg, Klg, Vhg, Vlg, mb, 0);
    CP_COMMIT();

    float O[8][4];
    #pragma unroll
    for (int ni = 0; ni < 8; ni++)
        #pragma unroll
        for (int r = 0; r < 4; r++) O[ni][r] = 0.f;
    float m_[2] = {-1e30f, -1e30f}, l_[2] = {0.f, 0.f};

    const int row0 = warp*16 + gid;

    for (int kt = 0; kt < ktmax; kt++) {
        char* sb = sm + QTOT + (kt & 1)*KV_SZ;
        if (kt + 1 < ktmax) {
            stage_kv(sm + QTOT + ((kt+1) & 1)*KV_SZ, tid,
                     Khg, Klg, Vhg, Vlg, mb, (kt+1) << 6);
            CP_COMMIT();
            CP_WAIT(1);
        } else {
            CP_WAIT(0);
        }
        __syncthreads();

        float c[8][4];
        #pragma unroll
        for (int ni = 0; ni < 8; ni++)
            #pragma unroll
            for (int r = 0; r < 4; r++) c[ni][r] = 0.f;

        #pragma unroll
        for (int ks = 0; ks < 4; ks++) {
            int w0 = (ks*8 + qid)*4;
            unsigned ah[4];
            ah[0] = ld32(sm + Q_H + row0*QP + w0);
            ah[1] = ld32(sm + Q_H + (row0+8)*QP + w0);
            ah[2] = ld32(sm + Q_H + row0*QP + w0 + 16);
            ah[3] = ld32(sm + Q_H + (row0+8)*QP + w0 + 16);
            #pragma unroll
            for (int ni = 0; ni < 8; ni++) {
                int kr = ni*8 + gid;
                unsigned bh[2], bl[2];
                bh[0] = ld32(sb + KV_KH + kr*QP + w0);
                bh[1] = ld32(sb + KV_KH + kr*QP + w0 + 16);
                bl[0] = ld32(sb + KV_KL + kr*QP + w0);
                bl[1] = ld32(sb + KV_KL + kr*QP + w0 + 16);
                mma16h(c[ni], ah, bh);
                mma16h(c[ni], ah, bl);
            }
        }

        const int* mks = (const int*)(sb + KV_MK);
        #pragma unroll
        for (int ni = 0; ni < 8; ni++) {
            int c0 = ni*8 + qid*2;
            if (mks[c0]     == 0) { c[ni][0] = -1.0e9f; c[ni][2] = -1.0e9f; }
            if (mks[c0 + 1] == 0) { c[ni][1] = -1.0e9f; c[ni][3] = -1.0e9f; }
        }

        #pragma unroll
        for (int r = 0; r < 2; r++) {
            const int bx = r*2;
            float rm = -1e30f;
            #pragma unroll
            for (int ni = 0; ni < 8; ni++)
                rm = fmaxf(rm, fmaxf(c[ni][bx], c[ni][bx+1]));
            rm = fmaxf(rm, __shfl_xor_sync(0xffffffffu, rm, 1));
            rm = fmaxf(rm, __shfl_xor_sync(0xffffffffu, rm, 2));
            float nm   = fmaxf(m_[r], rm);
            float corr = __expf(m_[r] - nm);
            float rs = 0.f;
            #pragma unroll
            for (int ni = 0; ni < 8; ni++) {
                float p0 = __expf(c[ni][bx]   - nm);
                float p1 = __expf(c[ni][bx+1] - nm);
                c[ni][bx] = p0; c[ni][bx+1] = p1;
                rs += p0 + p1;
            }
            rs += __shfl_xor_sync(0xffffffffu, rs, 1);
            rs += __shfl_xor_sync(0xffffffffu, rs, 2);
            l_[r] = l_[r] * corr + rs;
            m_[r] = nm;
            #pragma unroll
            for (int ni = 0; ni < 8; ni++) {
                O[ni][bx]   *= corr;
                O[ni][bx+1] *= corr;
            }
        }

        #pragma unroll
        for (int ks = 0; ks < 4; ks++) {
            unsigned pah[4];
            pah[0] = packh(c[2*ks][0],   c[2*ks][1]);
            pah[1] = packh(c[2*ks][2],   c[2*ks][3]);
            pah[2] = packh(c[2*ks+1][0], c[2*ks+1][1]);
            pah[3] = packh(c[2*ks+1][2], c[2*ks+1][3]);

            int w0 = (ks*8 + qid)*4;
            #pragma unroll
            for (int ni = 0; ni < 8; ni++) {
                int dr = ni*8 + gid;
                unsigned vh[2], vl[2];
                vh[0] = ld32(sb + KV_VH + dr*QP + w0);
                vh[1] = ld32(sb + KV_VH + dr*QP + w0 + 16);
                vl[0] = ld32(sb + KV_VL + dr*QP + w0);
                vl[1] = ld32(sb + KV_VL + dr*QP + w0 + 16);
                mma16h(O[ni], pah, vh);
                mma16h(O[ni], pah, vl);
            }
        }
        __syncthreads();
    }

    float inv0 = 1.0f / l_[0], inv1 = 1.0f / l_[1];
    int s = q0 + warp*16 + gid;
    size_t t0 = (size_t)(b*SEQ + s)*DM + h*DK;
    size_t t1 = t0 + (size_t)8*DM;
    #pragma unroll
    for (int ni = 0; ni < 8; ni++) {
        int d = ni*8 + (qid << 1);
        *(__half2*)&g_Ch[t0 + d] =
            __floats2half2_rn(O[ni][0]*inv0, O[ni][1]*inv0);
        *(__half2*)&g_Ch[t1 + d] =
            __floats2half2_rn(O[ni][2]*inv1, O[ni][3]*inv1);
    }
}

// ---------------------------------------------------------------------------
extern "C" void kernel_launch(void* const* d_in, const int* in_sizes, int n_in,
                              void* d_out, int out_size)
{
    (void)in_sizes; (void)n_in; (void)out_size;
    const float* query = (const float*)d_in[0];
    const float* key_  = (const float*)d_in[1];
    const float* value = (const float*)d_in[2];
    const int*   mask  = (const int*)  d_in[3];
    const float* Wq = (const float*)d_in[4];
    const float* bq = (const float*)d_in[5];
    const float* Wk = (const float*)d_in[6];
    const float* bk = (const float*)d_in[7];
    const float* Wv = (const float*)d_in[8];
    const float* bv = (const float*)d_in[9];
    const float* Wo = (const float*)d_in[10];
    const float* bo = (const float*)d_in[11];
    float* out = (float*)d_out;

    __half* Xh;
    cudaGetSymbolAddress((void**)&Xh, g_Xh);

    const int n4x = TOK * DM / 4;
    const int n4w = DM * DM / 4;

    build_compact<<<BB, 1024>>>(mask);

    cast_half<<<n4x/256, 256>>>(query, Xh, n4x);
    gather_cast_half<<<dim3(n4x/256, 2), 256>>>(key_, value);
    split_w<<<dim3(n4w/256, 4), 256>>>(Wq, Wk, Wv, Wo);

    cudaFuncSetAttribute(gemm_qkv_fp16,
                         cudaFuncAttributeMaxDynamicSharedMemorySize, 2*STAGEB);
    gemm_qkv_fp16<<<dim3(DM/128, TOK/128, 3), 256, 2*STAGEB>>>(bq, bk, bv);

    cudaFuncSetAttribute(flash_mma,
                         cudaFuncAttributeMaxDynamicSharedMemorySize, FL_SMEM);
    flash_mma<<<dim3(SEQ/128, NH, BB), 256, FL_SMEM>>>();

    cudaFuncSetAttribute(gemm_out_fp16,
                         cudaFuncAttributeMaxDynamicSharedMemorySize, 2*STAGEB);
    gemm_out_fp16<<<dim3(DM/128, TOK/128), 256, 2*STAGEB>>>(bo, out);
}

// round 13
// speedup vs baseline: 7.5046x; 1.0009x over previous
#include <cuda_runtime.h>
#include <cuda_fp16.h>
#include <math.h>

#define DM   1024
#define NH   16
#define DK   64
#define SEQ  2048
#define BB   2
#define TOK  (BB*SEQ)   // 4096

// ---------------- scratch (__device__ globals; no allocation allowed) -------
__device__ __half g_Xh[3*TOK*DM];      // q,kC,vC activations (fp16 hi only)
__device__ __half g_WWh[4*DM*DM];      // Wq,Wk,Wv,Wo hi
__device__ __half g_WWl[4*DM*DM];      // lo
__device__ __half g_Qhh[BB*NH*SEQ*DK]; // Q [B,H,S,DK], pre-scaled 1/8 (hi only)
__device__ __half g_Khh[BB*NH*SEQ*DK]; // K compacted hi
__device__ __half g_Kll[BB*NH*SEQ*DK]; // K lo
__device__ __half g_Vth[BB*NH*DK*SEQ]; // V compacted transposed hi
__device__ __half g_Vtl[BB*NH*DK*SEQ]; // V lo
__device__ __half g_Ch[TOK*DM];        // ctx (hi only)
// mask compaction state
__device__ int g_cidx[BB*SEQ];
__device__ int g_cmask[BB*SEQ];
__device__ int g_cntp[BB];

// ---- helpers ---------------------------------------------------------------
__device__ __forceinline__ __half hhi(float x) { return __float2half(x); }
__device__ __forceinline__ __half hlo(float x) {
    return __float2half(x - __half2float(__float2half(x)));
}
__device__ __forceinline__ unsigned packh(float lo, float hi) {
    __half2 t = __floats2half2_rn(lo, hi);
    return *(unsigned*)&t;
}
__device__ __forceinline__ void mma16h(float d[4], const unsigned a[4],
                                       const unsigned b[2]) {
    asm("mma.sync.aligned.m16n8k16.row.col.f32.f16.f16.f32 "
        "{%0,%1,%2,%3}, {%4,%5,%6,%7}, {%8,%9}, {%0,%1,%2,%3};"
        : "+f"(d[0]), "+f"(d[1]), "+f"(d[2]), "+f"(d[3])
        : "r"(a[0]), "r"(a[1]), "r"(a[2]), "r"(a[3]), "r"(b[0]), "r"(b[1]));
}
__device__ __forceinline__ void cp16(void* dst, const void* src) {
    unsigned d = (unsigned)__cvta_generic_to_shared(dst);
    asm volatile("cp.async.ca.shared.global [%0], [%1], 16;" :: "r"(d), "l"(src));
}
#define CP_COMMIT()  asm volatile("cp.async.commit_group;" ::: "memory")
#define CP_WAIT(n)   asm volatile("cp.async.wait_group %0;" :: "n"(n) : "memory")
__device__ __forceinline__ unsigned ld32(const void* p) { return *(const unsigned*)p; }

// ---------------------------------------------------------------------------
// Mask compaction (prefix scan per batch).
// ---------------------------------------------------------------------------
__global__ __launch_bounds__(1024)
void build_compact(const int* __restrict__ mask)
{
    __shared__ int wsum[32];
    const int b = blockIdx.x, t = threadIdx.x;
    const int lane = t & 31, warp = t >> 5;
    const int* mb = mask + b * SEQ;
    int m0 = mb[2*t], m1 = mb[2*t + 1];
    int loc = m0 + m1;
    int v = loc;
    #pragma unroll
    for (int o = 1; o < 32; o <<= 1) {
        int u = __shfl_up_sync(0xffffffffu, v, o);
        if (lane >= o) v += u;
    }
    if (lane == 31) wsum[warp] = v;
    __syncthreads();
    if (warp == 0) {
        int w = wsum[lane];
        #pragma unroll
        for (int o = 1; o < 32; o <<= 1) {
            int u = __shfl_up_sync(0xffffffffu, w, o);
            if (lane >= o) w += u;
        }
        wsum[lane] = w;
    }
    __syncthreads();
    const int base = (warp ? wsum[warp - 1] : 0) + v - loc;
    const int tot  = wsum[31];
    if (m0) g_cidx[b*SEQ + base]      = 2*t;
    if (m1) g_cidx[b*SEQ + base + m0] = 2*t + 1;
    if (2*t     >= tot) g_cidx[b*SEQ + 2*t]     = 0;
    if (2*t + 1 >= tot) g_cidx[b*SEQ + 2*t + 1] = 0;
    g_cmask[b*SEQ + 2*t]     = (2*t     < tot) ? 1 : 0;
    g_cmask[b*SEQ + 2*t + 1] = (2*t + 1 < tot) ? 1 : 0;
    if (t == 0) {
        int totp = (tot + 127) & ~127;
        if (totp == 0) totp = 128;
        g_cntp[b] = totp;
    }
}

// ---------------------------------------------------------------------------
// Fused prep: blockIdx.y selects work.
//  y=0: cast query -> Xh[0]
//  y=1: gather-cast key -> Xh[1];  y=2: gather-cast value -> Xh[2]
//  y=3..6: weight hi/lo split (Wq,Wk,Wv,Wo)
// ---------------------------------------------------------------------------
__global__ __launch_bounds__(256)
void prep_all(const float* __restrict__ query, const float* __restrict__ k_in,
              const float* __restrict__ v_in,
              const float* __restrict__ Wq, const float* __restrict__ Wk,
              const float* __restrict__ Wv, const float* __restrict__ Wo)
{
    const int y = blockIdx.y;
    int i = blockIdx.x * blockDim.x + threadIdx.x;
    if (y == 0) {
        float4 v = ((const float4*)query)[i];
        __half* hi = g_Xh;
        ((__half2*)hi)[2*i]   = __floats2half2_rn(v.x, v.y);
        ((__half2*)hi)[2*i+1] = __floats2half2_rn(v.z, v.w);
    } else if (y <= 2) {
        const float* x = (y == 2) ? v_in : k_in;
        __half* hi = g_Xh + (size_t)y * TOK * DM;
        int row = i >> 8, col4 = i & 255;
        int b = row >> 11, j = row & (SEQ - 1);
        int src = g_cidx[b*SEQ + j];
        float4 v = ((const float4*)x)[(size_t)(b*SEQ + src) * 256 + col4];
        ((__half2*)hi)[2*i]   = __floats2half2_rn(v.x, v.y);
        ((__half2*)hi)[2*i+1] = __floats2half2_rn(v.z, v.w);
    } else {
        const int z = y - 3;
        if (i >= DM*DM/4) return;
        const float* w = (z == 0) ? Wq : (z == 1) ? Wk : (z == 2) ? Wv : Wo;
        __half* hi = g_WWh + (size_t)z * DM * DM;
        __half* lo = g_WWl + (size_t)z * DM * DM;
        float4 v = ((const float4*)w)[i];
        float vv[4] = {v.x, v.y, v.z, v.w};
        __half h[4], l[4];
        #pragma unroll
        for (int j = 0; j < 4; j++) {
            h[j] = __float2half(vv[j]);
            l[j] = __float2half(vv[j] - __half2float(h[j]));
        }
        ((__half2*)hi)[2*i]   = __halves2half2(h[0], h[1]);
        ((__half2*)hi)[2*i+1] = __halves2half2(h[2], h[3]);
        ((__half2*)lo)[2*i]   = __halves2half2(l[0], l[1]);
        ((__half2*)lo)[2*i+1] = __halves2half2(l[2], l[3]);
    }
}

// ---- GEMM smem layout ------------------------------------------------------
#define PITCH   80
#define OFF_AH  0
#define OFF_BH  10240
#define OFF_BL  20480
#define STAGEB  30720
#define BKB     32

__device__ __forceinline__
void stage_load(char* sbase, int lrow, int lchk,
                const __half* __restrict__ Ah,
                const __half* __restrict__ Bh,
                const __half* __restrict__ Bl,
                int m0, int n0, int k0)
{
    #pragma unroll
    for (int r = 0; r < 2; r++) {
        int row = lrow + r*64;
        cp16(sbase + OFF_AH + row*PITCH + lchk*2, Ah + (size_t)(m0+row)*DM + k0 + lchk);
        cp16(sbase + OFF_BH + row*PITCH + lchk*2, Bh + (size_t)(n0+row)*DM + k0 + lchk);
        cp16(sbase + OFF_BL + row*PITCH + lchk*2, Bl + (size_t)(n0+row)*DM + k0 + lchk);
    }
}

// ---------------------------------------------------------------------------
// 2-term fp16 tensor-core GEMM: C = A_h @ (W_h + W_l)^T + bias.
// mode: 0=fp32 C; 1=head hi+lo (K); 2=transposed hi+lo (V); 3=head hi (Q).
// ---------------------------------------------------------------------------
__device__ __forceinline__
void gemm_fp16_core(const __half* __restrict__ Agh,
                    const __half* __restrict__ Bgh,
                    const __half* __restrict__ Bgl,
                    const float* __restrict__ bias,
                    int mode, float scale,
                    float* __restrict__ C,
                    __half* __restrict__ Oh,
                    __half* __restrict__ Ol)
{
    extern __shared__ char smem[];

    const int tid  = threadIdx.x;
    const int lane = tid & 31;
    const int warp = tid >> 5;
    const int wm   = warp >> 2;
    const int wn   = warp & 3;
    const int gid  = lane >> 2;
    const int qid  = lane & 3;
    const int m0   = blockIdx.y << 7;
    const int n0   = blockIdx.x << 7;

    const int lrow = tid >> 2;
    const int lchk = (tid & 3) << 3;

    float acc[4][4][4];
    #pragma unroll
    for (int mi = 0; mi < 4; mi++)
        #pragma unroll
        for (int ni = 0; ni < 4; ni++)
            #pragma unroll
            for (int r = 0; r < 4; r++) acc[mi][ni][r] = 0.f;

    const int NKB = DM / BKB;

    stage_load(smem, lrow, lchk, Agh, Bgh, Bgl, m0, n0, 0);
    CP_COMMIT();

    for (int kb = 0; kb < NKB; kb++) {
        if (kb + 1 < NKB) {
            stage_load(smem + ((kb+1)&1)*STAGEB, lrow, lchk,
                       Agh, Bgh, Bgl, m0, n0, (kb+1)*BKB);
            CP_COMMIT();
            CP_WAIT(1);
        } else {
            CP_WAIT(0);
        }
        __syncthreads();

        char* sb = smem + (kb & 1) * STAGEB;

        #pragma unroll
        for (int ks = 0; ks < 2; ks++) {
            unsigned afh[4][4];
            #pragma unroll
            for (int mi = 0; mi < 4; mi++) {
                int row = wm*64 + mi*16 + gid;
                #pragma unroll
                for (int r = 0; r < 4; r++) {
                    int rr = row + ((r & 1) << 3);
                    int w  = ks*8 + qid + ((r >> 1) << 2);
                    afh[mi][r] = ld32(sb + OFF_AH + rr*PITCH + w*4);
                }
            }
            #pragma unroll
            for (int ni = 0; ni < 4; ni++) {
                int col = wn*32 + ni*8 + gid;
                unsigned bfh[2], bfl[2];
                #pragma unroll
                for (int r = 0; r < 2; r++) {
                    int w = ks*8 + qid + (r << 2);
                    bfh[r] = ld32(sb + OFF_BH + col*PITCH + w*4);
                    bfl[r] = ld32(sb + OFF_BL + col*PITCH + w*4);
                }
                #pragma unroll
                for (int mi = 0; mi < 4; mi++) {
                    mma16h(acc[mi][ni], afh[mi], bfh);
                    mma16h(acc[mi][ni], afh[mi], bfl);
                }
            }
        }
        __syncthreads();
    }

    // ---- epilogue ----
    #pragma unroll
    for (int mi = 0; mi < 4; mi++) {
        #pragma unroll
        for (int ni = 0; ni < 4; ni++) {
            int row = m0 + wm*64 + mi*16 + gid;
            int col = n0 + wn*32 + ni*8 + (qid << 1);
            float b0 = bias[col], b1 = bias[col + 1];
            float v00 = (acc[mi][ni][0] + b0) * scale;
            float v01 = (acc[mi][ni][1] + b1) * scale;
            float v10 = (acc[mi][ni][2] + b0) * scale;
            float v11 = (acc[mi][ni][3] + b1) * scale;
            if (mode == 0) {
                *(float2*)&C[(size_t)row       * DM + col] = make_float2(v00, v01);
                *(float2*)&C[(size_t)(row + 8) * DM + col] = make_float2(v10, v11);
            } else if (mode == 1 || mode == 3) {
                int h = col >> 6, d = col & 63;
                {
                    int t = row, bbx = t >> 11, s = t & (SEQ - 1);
                    size_t off = ((size_t)((bbx*NH + h)*SEQ) + s)*DK + d;
                    *(__half2*)&Oh[off] = __halves2half2(hhi(v00), hhi(v01));
                    if (mode == 1)
                        *(__half2*)&Ol[off] = __halves2half2(hlo(v00), hlo(v01));
                }
                {
                    int t = row + 8, bbx = t >> 11, s = t & (SEQ - 1);
                    size_t off = ((size_t)((bbx*NH + h)*SEQ) + s)*DK + d;
                    *(__half2*)&Oh[off] = __halves2half2(hhi(v10), hhi(v11));
                    if (mode == 1)
                        *(__half2*)&Ol[off] = __halves2half2(hlo(v10), hlo(v11));
                }
            } else {
                int h = col >> 6, d = col & 63;
                int bbx = row >> 11, s = row & (SEQ - 1);
                size_t base = (size_t)(bbx*NH + h) * DK;
                Oh[(base + d    )*SEQ + s    ] = hhi(v00);
                Oh[(base + d + 1)*SEQ + s    ] = hhi(v01);
                Oh[(base + d    )*SEQ + s + 8] = hhi(v10);
                Oh[(base + d + 1)*SEQ + s + 8] = hhi(v11);
                Ol[(base + d    )*SEQ + s    ] = hlo(v00);
                Ol[(base + d + 1)*SEQ + s    ] = hlo(v01);
                Ol[(base + d    )*SEQ + s + 8] = hlo(v10);
                Ol[(base + d + 1)*SEQ + s + 8] = hlo(v11);
            }
        }
    }
}

__global__ __launch_bounds__(256, 2)
void gemm_qkv_fp16(const float* __restrict__ bq, const float* __restrict__ bk,
                   const float* __restrict__ bv)
{
    const int z = blockIdx.z;
    if (z >= 1) {
        int m0i = blockIdx.y << 7;
        if ((m0i & (SEQ - 1)) >= g_cntp[m0i >> 11]) return;
    }
    const __half* Agh = g_Xh  + (size_t)z * TOK * DM;
    const __half* Wgh = g_WWh + (size_t)z * DM * DM;
    const __half* Wgl = g_WWl + (size_t)z * DM * DM;
    if (z == 0)
        gemm_fp16_core(Agh, Wgh, Wgl, bq, 3, 0.125f, nullptr, g_Qhh, nullptr);
    else if (z == 1)
        gemm_fp16_core(Agh, Wgh, Wgl, bk, 1, 1.0f, nullptr, g_Khh, g_Kll);
    else
        gemm_fp16_core(Agh, Wgh, Wgl, bv, 2, 1.0f, nullptr, g_Vth, g_Vtl);
}

__global__ __launch_bounds__(256, 2)
void gemm_out_fp16(const float* __restrict__ bo, float* __restrict__ out)
{
    gemm_fp16_core(g_Ch,
                   g_WWh + (size_t)3 * DM * DM,
                   g_WWl + (size_t)3 * DM * DM,
                   bo, 0, 1.0f, out, nullptr, nullptr);
}

// ---------------------------------------------------------------------------
// fp16 flash attention v2: 64-query CTAs (128 thr, 4 warps x 16q),
// Q fragments in REGISTERS (no Q smem), KV double-buffered -> 3 CTAs/SM.
// ---------------------------------------------------------------------------
#define QP      144
#define KV_KH   0
#define KV_KL   (64*QP)
#define KV_VH   (2*64*QP)
#define KV_VL   (3*64*QP)
#define KV_MK   (4*64*QP)
#define KV_SZ   (4*64*QP + 256)     // 37120
#define FL_SMEM (2*KV_SZ)           // 74240

__device__ __forceinline__
void stage_kv(char* sb, int tid,
              const __half* __restrict__ Khg, const __half* __restrict__ Klg,
              const __half* __restrict__ Vhg, const __half* __restrict__ Vlg,
              const int* __restrict__ mb, int k0)
{
    // 64 rows x 8 chunks per array, 4 arrays: 2048 cp16 / 128 thr -> 4 iters
    #pragma unroll
    for (int it = 0; it < 4; it++) {
        int idx = tid + it*128;
        int row = idx >> 3, ch = idx & 7;
        cp16(sb + KV_KH + row*QP + ch*16, Khg + (size_t)(k0 + row)*DK + ch*8);
        cp16(sb + KV_KL + row*QP + ch*16, Klg + (size_t)(k0 + row)*DK + ch*8);
        cp16(sb + KV_VH + row*QP + ch*16, Vhg + (size_t)row*SEQ + k0 + ch*8);
        cp16(sb + KV_VL + row*QP + ch*16, Vlg + (size_t)row*SEQ + k0 + ch*8);
    }
    if (tid < 16) cp16(sb + KV_MK + tid*16, mb + k0 + tid*4);
}

__global__ __launch_bounds__(128, 3)
void flash_mma()
{
    extern __shared__ char sm[];
    const int tid  = threadIdx.x;
    const int lane = tid & 31;
    const int warp = tid >> 5;          // 0..3
    const int gid  = lane >> 2;
    const int qid  = lane & 3;
    const int q0   = blockIdx.x << 6;   // 64-query tiles
    const int h    = blockIdx.y;
    const int b    = blockIdx.z;

    const __half* Qhg = g_Qhh + ((size_t)((b*NH + h)*SEQ) + q0)*DK;
    const __half* Khg = g_Khh + (size_t)(b*NH + h)*SEQ*DK;
    const __half* Klg = g_Kll + (size_t)(b*NH + h)*SEQ*DK;
    const __half* Vhg = g_Vth + (size_t)(b*NH + h)*DK*SEQ;
    const __half* Vlg = g_Vtl + (size_t)(b*NH + h)*DK*SEQ;
    const int* mb = g_cmask + b * SEQ;
    const int ktmax = g_cntp[b] >> 6;

    const int row0 = warp*16 + gid;

    // Q a-fragments in registers: element (ks*8+qid)*2 == ks*16 + qid*2
    unsigned aq[4][4];
    #pragma unroll
    for (int ks = 0; ks < 4; ks++) {
        aq[ks][0] = ld32(&Qhg[(size_t)(row0    )*DK + ks*16 + qid*2]);
        aq[ks][1] = ld32(&Qhg[(size_t)(row0 + 8)*DK + ks*16 + qid*2]);
        aq[ks][2] = ld32(&Qhg[(size_t)(row0    )*DK + ks*16 + qid*2 + 8]);
        aq[ks][3] = ld32(&Qhg[(size_t)(row0 + 8)*DK + ks*16 + qid*2 + 8]);
    }

    stage_kv(sm, tid, Khg, Klg, Vhg, Vlg, mb, 0);
    CP_COMMIT();

    float O[8][4];
    #pragma unroll
    for (int ni = 0; ni < 8; ni++)
        #pragma unroll
        for (int r = 0; r < 4; r++) O[ni][r] = 0.f;
    float m_[2] = {-1e30f, -1e30f}, l_[2] = {0.f, 0.f};

    for (int kt = 0; kt < ktmax; kt++) {
        char* sb = sm + (kt & 1)*KV_SZ;
        if (kt + 1 < ktmax) {
            stage_kv(sm + ((kt+1) & 1)*KV_SZ, tid,
                     Khg, Klg, Vhg, Vlg, mb, (kt+1) << 6);
            CP_COMMIT();
            CP_WAIT(1);
        } else {
            CP_WAIT(0);
        }
        __syncthreads();

        float c[8][4];
        #pragma unroll
        for (int ni = 0; ni < 8; ni++)
            #pragma unroll
            for (int r = 0; r < 4; r++) c[ni][r] = 0.f;

        #pragma unroll
        for (int ks = 0; ks < 4; ks++) {
            int w0 = (ks*8 + qid)*4;
            #pragma unroll
            for (int ni = 0; ni < 8; ni++) {
                int kr = ni*8 + gid;
                unsigned bh[2], bl[2];
                bh[0] = ld32(sb + KV_KH + kr*QP + w0);
                bh[1] = ld32(sb + KV_KH + kr*QP + w0 + 16);
                bl[0] = ld32(sb + KV_KL + kr*QP + w0);
                bl[1] = ld32(sb + KV_KL + kr*QP + w0 + 16);
                mma16h(c[ni], aq[ks], bh);
                mma16h(c[ni], aq[ks], bl);
            }
        }

        const int* mks = (const int*)(sb + KV_MK);
        #pragma unroll
        for (int ni = 0; ni < 8; ni++) {
            int c0 = ni*8 + qid*2;
            if (mks[c0]     == 0) { c[ni][0] = -1.0e9f; c[ni][2] = -1.0e9f; }
            if (mks[c0 + 1] == 0) { c[ni][1] = -1.0e9f; c[ni][3] = -1.0e9f; }
        }

        #pragma unroll
        for (int r = 0; r < 2; r++) {
            const int bx = r*2;
            float rm = -1e30f;
            #pragma unroll
            for (int ni = 0; ni < 8; ni++)
                rm = fmaxf(rm, fmaxf(c[ni][bx], c[ni][bx+1]));
            rm = fmaxf(rm, __shfl_xor_sync(0xffffffffu, rm, 1));
            rm = fmaxf(rm, __shfl_xor_sync(0xffffffffu, rm, 2));
            float nm   = fmaxf(m_[r], rm);
            float corr = __expf(m_[r] - nm);
            float rs = 0.f;
            #pragma unroll
            for (int ni = 0; ni < 8; ni++) {
                float p0 = __expf(c[ni][bx]   - nm);
                float p1 = __expf(c[ni][bx+1] - nm);
                c[ni][bx] = p0; c[ni][bx+1] = p1;
                rs += p0 + p1;
            }
            rs += __shfl_xor_sync(0xffffffffu, rs, 1);
            rs += __shfl_xor_sync(0xffffffffu, rs, 2);
            l_[r] = l_[r] * corr + rs;
            m_[r] = nm;
            #pragma unroll
            for (int ni = 0; ni < 8; ni++) {
                O[ni][bx]   *= corr;
                O[ni][bx+1] *= corr;
            }
        }

        #pragma unroll
        for (int ks = 0; ks < 4; ks++) {
            unsigned pah[4];
            pah[0] = packh(c[2*ks][0],   c[2*ks][1]);
            pah[1] = packh(c[2*ks][2],   c[2*ks][3]);
            pah[2] = packh(c[2*ks+1][0], c[2*ks+1][1]);
            pah[3] = packh(c[2*ks+1][2], c[2*ks+1][3]);

            int w0 = (ks*8 + qid)*4;
            #pragma unroll
            for (int ni = 0; ni < 8; ni++) {
                int dr = ni*8 + gid;
                unsigned vh[2], vl[2];
                vh[0] = ld32(sb + KV_VH + dr*QP + w0);
                vh[1] = ld32(sb + KV_VH + dr*QP + w0 + 16);
                vl[0] = ld32(sb + KV_VL + dr*QP + w0);
                vl[1] = ld32(sb + KV_VL + dr*QP + w0 + 16);
                mma16h(O[ni], pah, vh);
                mma16h(O[ni], pah, vl);
            }
        }
        __syncthreads();
    }

    float inv0 = 1.0f / l_[0], inv1 = 1.0f / l_[1];
    int s = q0 + row0;
    size_t t0 = (size_t)(b*SEQ + s)*DM + h*DK;
    size_t t1 = t0 + (size_t)8*DM;
    #pragma unroll
    for (int ni = 0; ni < 8; ni++) {
        int d = ni*8 + (qid << 1);
        *(__half2*)&g_Ch[t0 + d] =
            __floats2half2_rn(O[ni][0]*inv0, O[ni][1]*inv0);
        *(__half2*)&g_Ch[t1 + d] =
            __floats2half2_rn(O[ni][2]*inv1, O[ni][3]*inv1);
    }
}

// ---------------------------------------------------------------------------
extern "C" void kernel_launch(void* const* d_in, const int* in_sizes, int n_in,
                              void* d_out, int out_size)
{
    (void)in_sizes; (void)n_in; (void)out_size;
    const float* query = (const float*)d_in[0];
    const float* key_  = (const float*)d_in[1];
    const float* value = (const float*)d_in[2];
    const int*   mask  = (const int*)  d_in[3];
    const float* Wq = (const float*)d_in[4];
    const float* bq = (const float*)d_in[5];
    const float* Wk = (const float*)d_in[6];
    const float* bk = (const float*)d_in[7];
    const float* Wv = (const float*)d_in[8];
    const float* bv = (const float*)d_in[9];
    const float* Wo = (const float*)d_in[10];
    const float* bo = (const float*)d_in[11];
    float* out = (float*)d_out;

    const int n4x = TOK * DM / 4;   // 1,048,576 -> 4096 blocks of 256

    build_compact<<<BB, 1024>>>(mask);

    // fused prep: y=0 cast Q, y=1,2 gather K/V, y=3..6 weight splits
    prep_all<<<dim3(n4x/256, 7), 256>>>(query, key_, value, Wq, Wk, Wv, Wo);

    cudaFuncSetAttribute(gemm_qkv_fp16,
                         cudaFuncAttributeMaxDynamicSharedMemorySize, 2*STAGEB);
    gemm_qkv_fp16<<<dim3(DM/128, TOK/128, 3), 256, 2*STAGEB>>>(bq, bk, bv);

    cudaFuncSetAttribute(flash_mma,
                         cudaFuncAttributeMaxDynamicSharedMemorySize, FL_SMEM);
    flash_mma<<<dim3(SEQ/64, NH, BB), 128, FL_SMEM>>>();

    cudaFuncSetAttribute(gemm_out_fp16,
                         cudaFuncAttributeMaxDynamicSharedMemorySize, 2*STAGEB);
    gemm_out_fp16<<<dim3(DM/128, TOK/128), 256, 2*STAGEB>>>(bo, out);
}

// round 14
// speedup vs baseline: 8.2184x; 1.0951x over previous
#include <cuda_runtime.h>
#include <cuda_fp16.h>
#include <math.h>

#define DM   1024
#define NH   16
#define DK   64
#define SEQ  2048
#define BB   2
#define TOK  (BB*SEQ)   // 4096

// ---------------- scratch (__device__ globals; no allocation allowed) -------
__device__ __half g_Xh[3*TOK*DM];      // q,kC,vC activations (fp16 hi only)
__device__ __half g_WWh[4*DM*DM];      // Wq,Wk,Wv,Wo hi
__device__ __half g_WWl[4*DM*DM];      // lo
__device__ __half g_Qhh[BB*NH*SEQ*DK]; // Q [B,H,S,DK], pre-scaled 1/8 (hi only)
__device__ __half g_Khh[BB*NH*SEQ*DK]; // K compacted hi
__device__ __half g_Kll[BB*NH*SEQ*DK]; // K lo
__device__ __half g_Vth[BB*NH*DK*SEQ]; // V compacted transposed (hi only)
__device__ __half g_Ch[TOK*DM];        // ctx (hi only)
// mask compaction state
__device__ int g_cidx[BB*SEQ];
__device__ int g_cmask[BB*SEQ];
__device__ int g_cntp[BB];

// ---- helpers ---------------------------------------------------------------
__device__ __forceinline__ __half hhi(float x) { return __float2half(x); }
__device__ __forceinline__ __half hlo(float x) {
    return __float2half(x - __half2float(__float2half(x)));
}
__device__ __forceinline__ unsigned packh(float lo, float hi) {
    __half2 t = __floats2half2_rn(lo, hi);
    return *(unsigned*)&t;
}
__device__ __forceinline__ void mma16h(float d[4], const unsigned a[4],
                                       const unsigned b[2]) {
    asm("mma.sync.aligned.m16n8k16.row.col.f32.f16.f16.f32 "
        "{%0,%1,%2,%3}, {%4,%5,%6,%7}, {%8,%9}, {%0,%1,%2,%3};"
        : "+f"(d[0]), "+f"(d[1]), "+f"(d[2]), "+f"(d[3])
        : "r"(a[0]), "r"(a[1]), "r"(a[2]), "r"(a[3]), "r"(b[0]), "r"(b[1]));
}
__device__ __forceinline__ void cp16(void* dst, const void* src) {
    unsigned d = (unsigned)__cvta_generic_to_shared(dst);
    asm volatile("cp.async.ca.shared.global [%0], [%1], 16;" :: "r"(d), "l"(src));
}
#define CP_COMMIT()  asm volatile("cp.async.commit_group;" ::: "memory")
#define CP_WAIT(n)   asm volatile("cp.async.wait_group %0;" :: "n"(n) : "memory")
__device__ __forceinline__ unsigned ld32(const void* p) { return *(const unsigned*)p; }

// ---------------------------------------------------------------------------
// Mask compaction (prefix scan per batch).
// ---------------------------------------------------------------------------
__global__ __launch_bounds__(1024)
void build_compact(const int* __restrict__ mask)
{
    __shared__ int wsum[32];
    const int b = blockIdx.x, t = threadIdx.x;
    const int lane = t & 31, warp = t >> 5;
    const int* mb = mask + b * SEQ;
    int m0 = mb[2*t], m1 = mb[2*t + 1];
    int loc = m0 + m1;
    int v = loc;
    #pragma unroll
    for (int o = 1; o < 32; o <<= 1) {
        int u = __shfl_up_sync(0xffffffffu, v, o);
        if (lane >= o) v += u;
    }
    if (lane == 31) wsum[warp] = v;
    __syncthreads();
    if (warp == 0) {
        int w = wsum[lane];
        #pragma unroll
        for (int o = 1; o < 32; o <<= 1) {
            int u = __shfl_up_sync(0xffffffffu, w, o);
            if (lane >= o) w += u;
        }
        wsum[lane] = w;
    }
    __syncthreads();
    const int base = (warp ? wsum[warp - 1] : 0) + v - loc;
    const int tot  = wsum[31];
    if (m0) g_cidx[b*SEQ + base]      = 2*t;
    if (m1) g_cidx[b*SEQ + base + m0] = 2*t + 1;
    if (2*t     >= tot) g_cidx[b*SEQ + 2*t]     = 0;
    if (2*t + 1 >= tot) g_cidx[b*SEQ + 2*t + 1] = 0;
    g_cmask[b*SEQ + 2*t]     = (2*t     < tot) ? 1 : 0;
    g_cmask[b*SEQ + 2*t + 1] = (2*t + 1 < tot) ? 1 : 0;
    if (t == 0) {
        int totp = (tot + 127) & ~127;
        if (totp == 0) totp = 128;
        g_cntp[b] = totp;
    }
}

// ---------------------------------------------------------------------------
// Fused prep: blockIdx.y selects work.
//  y=0: cast query; y=1,2: gather-cast key/value; y=3..6: weight splits
// ---------------------------------------------------------------------------
__global__ __launch_bounds__(256)
void prep_all(const float* __restrict__ query, const float* __restrict__ k_in,
              const float* __restrict__ v_in,
              const float* __restrict__ Wq, const float* __restrict__ Wk,
              const float* __restrict__ Wv, const float* __restrict__ Wo)
{
    const int y = blockIdx.y;
    int i = blockIdx.x * blockDim.x + threadIdx.x;
    if (y == 0) {
        float4 v = ((const float4*)query)[i];
        __half* hi = g_Xh;
        ((__half2*)hi)[2*i]   = __floats2half2_rn(v.x, v.y);
        ((__half2*)hi)[2*i+1] = __floats2half2_rn(v.z, v.w);
    } else if (y <= 2) {
        const float* x = (y == 2) ? v_in : k_in;
        __half* hi = g_Xh + (size_t)y * TOK * DM;
        int row = i >> 8, col4 = i & 255;
        int b = row >> 11, j = row & (SEQ - 1);
        int src = g_cidx[b*SEQ + j];
        float4 v = ((const float4*)x)[(size_t)(b*SEQ + src) * 256 + col4];
        ((__half2*)hi)[2*i]   = __floats2half2_rn(v.x, v.y);
        ((__half2*)hi)[2*i+1] = __floats2half2_rn(v.z, v.w);
    } else {
        const int z = y - 3;
        if (i >= DM*DM/4) return;
        const float* w = (z == 0) ? Wq : (z == 1) ? Wk : (z == 2) ? Wv : Wo;
        __half* hi = g_WWh + (size_t)z * DM * DM;
        __half* lo = g_WWl + (size_t)z * DM * DM;
        float4 v = ((const float4*)w)[i];
        float vv[4] = {v.x, v.y, v.z, v.w};
        __half h[4], l[4];
        #pragma unroll
        for (int j = 0; j < 4; j++) {
            h[j] = __float2half(vv[j]);
            l[j] = __float2half(vv[j] - __half2float(h[j]));
        }
        ((__half2*)hi)[2*i]   = __halves2half2(h[0], h[1]);
        ((__half2*)hi)[2*i+1] = __halves2half2(h[2], h[3]);
        ((__half2*)lo)[2*i]   = __halves2half2(l[0], l[1]);
        ((__half2*)lo)[2*i+1] = __halves2half2(l[2], l[3]);
    }
}

// ---- GEMM smem layout ------------------------------------------------------
#define PITCH   80
#define OFF_AH  0
#define OFF_BH  10240
#define OFF_BL  20480
#define STAGEB  30720
#define BKB     32

__device__ __forceinline__
void stage_load(char* sbase, int lrow, int lchk,
                const __half* __restrict__ Ah,
                const __half* __restrict__ Bh,
                const __half* __restrict__ Bl,
                int m0, int n0, int k0)
{
    #pragma unroll
    for (int r = 0; r < 2; r++) {
        int row = lrow + r*64;
        cp16(sbase + OFF_AH + row*PITCH + lchk*2, Ah + (size_t)(m0+row)*DM + k0 + lchk);
        cp16(sbase + OFF_BH + row*PITCH + lchk*2, Bh + (size_t)(n0+row)*DM + k0 + lchk);
        cp16(sbase + OFF_BL + row*PITCH + lchk*2, Bl + (size_t)(n0+row)*DM + k0 + lchk);
    }
}

// ---------------------------------------------------------------------------
// 2-term fp16 tensor-core GEMM: C = A_h @ (W_h + W_l)^T + bias.
// mode: 0=fp32 C; 1=head hi+lo (K); 2=transposed hi only (V); 3=head hi (Q).
// ---------------------------------------------------------------------------
__device__ __forceinline__
void gemm_fp16_core(const __half* __restrict__ Agh,
                    const __half* __restrict__ Bgh,
                    const __half* __restrict__ Bgl,
                    const float* __restrict__ bias,
                    int mode, float scale,
                    float* __restrict__ C,
                    __half* __restrict__ Oh,
                    __half* __restrict__ Ol)
{
    extern __shared__ char smem[];

    const int tid  = threadIdx.x;
    const int lane = tid & 31;
    const int warp = tid >> 5;
    const int wm   = warp >> 2;
    const int wn   = warp & 3;
    const int gid  = lane >> 2;
    const int qid  = lane & 3;
    const int m0   = blockIdx.y << 7;
    const int n0   = blockIdx.x << 7;

    const int lrow = tid >> 2;
    const int lchk = (tid & 3) << 3;

    float acc[4][4][4];
    #pragma unroll
    for (int mi = 0; mi < 4; mi++)
        #pragma unroll
        for (int ni = 0; ni < 4; ni++)
            #pragma unroll
            for (int r = 0; r < 4; r++) acc[mi][ni][r] = 0.f;

    const int NKB = DM / BKB;

    stage_load(smem, lrow, lchk, Agh, Bgh, Bgl, m0, n0, 0);
    CP_COMMIT();

    for (int kb = 0; kb < NKB; kb++) {
        if (kb + 1 < NKB) {
            stage_load(smem + ((kb+1)&1)*STAGEB, lrow, lchk,
                       Agh, Bgh, Bgl, m0, n0, (kb+1)*BKB);
            CP_COMMIT();
            CP_WAIT(1);
        } else {
            CP_WAIT(0);
        }
        __syncthreads();

        char* sb = smem + (kb & 1) * STAGEB;

        #pragma unroll
        for (int ks = 0; ks < 2; ks++) {
            unsigned afh[4][4];
            #pragma unroll
            for (int mi = 0; mi < 4; mi++) {
                int row = wm*64 + mi*16 + gid;
                #pragma unroll
                for (int r = 0; r < 4; r++) {
                    int rr = row + ((r & 1) << 3);
                    int w  = ks*8 + qid + ((r >> 1) << 2);
                    afh[mi][r] = ld32(sb + OFF_AH + rr*PITCH + w*4);
                }
            }
            #pragma unroll
            for (int ni = 0; ni < 4; ni++) {
                int col = wn*32 + ni*8 + gid;
                unsigned bfh[2], bfl[2];
                #pragma unroll
                for (int r = 0; r < 2; r++) {
                    int w = ks*8 + qid + (r << 2);
                    bfh[r] = ld32(sb + OFF_BH + col*PITCH + w*4);
                    bfl[r] = ld32(sb + OFF_BL + col*PITCH + w*4);
                }
                #pragma unroll
                for (int mi = 0; mi < 4; mi++) {
                    mma16h(acc[mi][ni], afh[mi], bfh);
                    mma16h(acc[mi][ni], afh[mi], bfl);
                }
            }
        }
        __syncthreads();
    }

    // ---- epilogue ----
    #pragma unroll
    for (int mi = 0; mi < 4; mi++) {
        #pragma unroll
        for (int ni = 0; ni < 4; ni++) {
            int row = m0 + wm*64 + mi*16 + gid;
            int col = n0 + wn*32 + ni*8 + (qid << 1);
            float b0 = bias[col], b1 = bias[col + 1];
            float v00 = (acc[mi][ni][0] + b0) * scale;
            float v01 = (acc[mi][ni][1] + b1) * scale;
            float v10 = (acc[mi][ni][2] + b0) * scale;
            float v11 = (acc[mi][ni][3] + b1) * scale;
            if (mode == 0) {
                *(float2*)&C[(size_t)row       * DM + col] = make_float2(v00, v01);
                *(float2*)&C[(size_t)(row + 8) * DM + col] = make_float2(v10, v11);
            } else if (mode == 1 || mode == 3) {
                int h = col >> 6, d = col & 63;
                {
                    int t = row, bbx = t >> 11, s = t & (SEQ - 1);
                    size_t off = ((size_t)((bbx*NH + h)*SEQ) + s)*DK + d;
                    *(__half2*)&Oh[off] = __halves2half2(hhi(v00), hhi(v01));
                    if (mode == 1)
                        *(__half2*)&Ol[off] = __halves2half2(hlo(v00), hlo(v01));
                }
                {
                    int t = row + 8, bbx = t >> 11, s = t & (SEQ - 1);
                    size_t off = ((size_t)((bbx*NH + h)*SEQ) + s)*DK + d;
                    *(__half2*)&Oh[off] = __halves2half2(hhi(v10), hhi(v11));
                    if (mode == 1)
                        *(__half2*)&Ol[off] = __halves2half2(hlo(v10), hlo(v11));
                }
            } else {
                // V transposed, hi only
                int h = col >> 6, d = col & 63;
                int bbx = row >> 11, s = row & (SEQ - 1);
                size_t base = (size_t)(bbx*NH + h) * DK;
                Oh[(base + d    )*SEQ + s    ] = hhi(v00);
                Oh[(base + d + 1)*SEQ + s    ] = hhi(v01);
                Oh[(base + d    )*SEQ + s + 8] = hhi(v10);
                Oh[(base + d + 1)*SEQ + s + 8] = hhi(v11);
            }
        }
    }
}

__global__ __launch_bounds__(256, 2)
void gemm_qkv_fp16(const float* __restrict__ bq, const float* __restrict__ bk,
                   const float* __restrict__ bv)
{
    const int z = blockIdx.z;
    if (z >= 1) {
        int m0i = blockIdx.y << 7;
        if ((m0i & (SEQ - 1)) >= g_cntp[m0i >> 11]) return;
    }
    const __half* Agh = g_Xh  + (size_t)z * TOK * DM;
    const __half* Wgh = g_WWh + (size_t)z * DM * DM;
    const __half* Wgl = g_WWl + (size_t)z * DM * DM;
    if (z == 0)
        gemm_fp16_core(Agh, Wgh, Wgl, bq, 3, 0.125f, nullptr, g_Qhh, nullptr);
    else if (z == 1)
        gemm_fp16_core(Agh, Wgh, Wgl, bk, 1, 1.0f, nullptr, g_Khh, g_Kll);
    else
        gemm_fp16_core(Agh, Wgh, Wgl, bv, 2, 1.0f, nullptr, g_Vth, nullptr);
}

__global__ __launch_bounds__(256, 2)
void gemm_out_fp16(const float* __restrict__ bo, float* __restrict__ out)
{
    gemm_fp16_core(g_Ch,
                   g_WWh + (size_t)3 * DM * DM,
                   g_WWl + (size_t)3 * DM * DM,
                   bo, 0, 1.0f, out, nullptr, nullptr);
}

// ---------------------------------------------------------------------------
// fp16 flash attention: 64-query CTAs (128 thr), Q fragments in registers,
// K hi+lo / V hi-only in smem (V-lo dropped: below P-rounding noise floor).
// ---------------------------------------------------------------------------
#define QP      144
#define KV_KH   0
#define KV_KL   (64*QP)             // 9216
#define KV_VH   (2*64*QP)           // 18432
#define KV_MK   (3*64*QP)           // 27648
#define KV_SZ   (3*64*QP + 256)     // 27904
#define FL_SMEM (2*KV_SZ)           // 55808

__device__ __forceinline__
void stage_kv(char* sb, int tid,
              const __half* __restrict__ Khg, const __half* __restrict__ Klg,
              const __half* __restrict__ Vhg,
              const int* __restrict__ mb, int k0)
{
    // 64 rows x 8 chunks per array, 3 arrays: 1536 cp16 / 128 thr -> 4 iters
    #pragma unroll
    for (int it = 0; it < 4; it++) {
        int idx = tid + it*128;
        int row = idx >> 3, ch = idx & 7;
        cp16(sb + KV_KH + row*QP + ch*16, Khg + (size_t)(k0 + row)*DK + ch*8);
        cp16(sb + KV_KL + row*QP + ch*16, Klg + (size_t)(k0 + row)*DK + ch*8);
        cp16(sb + KV_VH + row*QP + ch*16, Vhg + (size_t)row*SEQ + k0 + ch*8);
    }
    if (tid < 16) cp16(sb + KV_MK + tid*16, mb + k0 + tid*4);
}

__global__ __launch_bounds__(128, 3)
void flash_mma()
{
    extern __shared__ char sm[];
    const int tid  = threadIdx.x;
    const int lane = tid & 31;
    const int warp = tid >> 5;          // 0..3
    const int gid  = lane >> 2;
    const int qid  = lane & 3;
    const int q0   = blockIdx.x << 6;   // 64-query tiles
    const int h    = blockIdx.y;
    const int b    = blockIdx.z;

    const __half* Qhg = g_Qhh + ((size_t)((b*NH + h)*SEQ) + q0)*DK;
    const __half* Khg = g_Khh + (size_t)(b*NH + h)*SEQ*DK;
    const __half* Klg = g_Kll + (size_t)(b*NH + h)*SEQ*DK;
    const __half* Vhg = g_Vth + (size_t)(b*NH + h)*DK*SEQ;
    const int* mb = g_cmask + b * SEQ;
    const int ktmax = g_cntp[b] >> 6;

    const int row0 = warp*16 + gid;

    // Q a-fragments in registers: element (ks*8+qid)*2 == ks*16 + qid*2
    unsigned aq[4][4];
    #pragma unroll
    for (int ks = 0; ks < 4; ks++) {
        aq[ks][0] = ld32(&Qhg[(size_t)(row0    )*DK + ks*16 + qid*2]);
        aq[ks][1] = ld32(&Qhg[(size_t)(row0 + 8)*DK + ks*16 + qid*2]);
        aq[ks][2] = ld32(&Qhg[(size_t)(row0    )*DK + ks*16 + qid*2 + 8]);
        aq[ks][3] = ld32(&Qhg[(size_t)(row0 + 8)*DK + ks*16 + qid*2 + 8]);
    }

    stage_kv(sm, tid, Khg, Klg, Vhg, mb, 0);
    CP_COMMIT();

    float O[8][4];
    #pragma unroll
    for (int ni = 0; ni < 8; ni++)
        #pragma unroll
        for (int r = 0; r < 4; r++) O[ni][r] = 0.f;
    float m_[2] = {-1e30f, -1e30f}, l_[2] = {0.f, 0.f};

    for (int kt = 0; kt < ktmax; kt++) {
        char* sb = sm + (kt & 1)*KV_SZ;
        if (kt + 1 < ktmax) {
            stage_kv(sm + ((kt+1) & 1)*KV_SZ, tid,
                     Khg, Klg, Vhg, mb, (kt+1) << 6);
            CP_COMMIT();
            CP_WAIT(1);
        } else {
            CP_WAIT(0);
        }
        __syncthreads();

        float c[8][4];
        #pragma unroll
        for (int ni = 0; ni < 8; ni++)
            #pragma unroll
            for (int r = 0; r < 4; r++) c[ni][r] = 0.f;

        #pragma unroll
        for (int ks = 0; ks < 4; ks++) {
            int w0 = (ks*8 + qid)*4;
            #pragma unroll
            for (int ni = 0; ni < 8; ni++) {
                int kr = ni*8 + gid;
                unsigned bh[2], bl[2];
                bh[0] = ld32(sb + KV_KH + kr*QP + w0);
                bh[1] = ld32(sb + KV_KH + kr*QP + w0 + 16);
                bl[0] = ld32(sb + KV_KL + kr*QP + w0);
                bl[1] = ld32(sb + KV_KL + kr*QP + w0 + 16);
                mma16h(c[ni], aq[ks], bh);
                mma16h(c[ni], aq[ks], bl);
            }
        }

        const int* mks = (const int*)(sb + KV_MK);
        #pragma unroll
        for (int ni = 0; ni < 8; ni++) {
            int c0 = ni*8 + qid*2;
            if (mks[c0]     == 0) { c[ni][0] = -1.0e9f; c[ni][2] = -1.0e9f; }
            if (mks[c0 + 1] == 0) { c[ni][1] = -1.0e9f; c[ni][3] = -1.0e9f; }
        }

        #pragma unroll
        for (int r = 0; r < 2; r++) {
            const int bx = r*2;
            float rm = -1e30f;
            #pragma unroll
            for (int ni = 0; ni < 8; ni++)
                rm = fmaxf(rm, fmaxf(c[ni][bx], c[ni][bx+1]));
            rm = fmaxf(rm, __shfl_xor_sync(0xffffffffu, rm, 1));
            rm = fmaxf(rm, __shfl_xor_sync(0xffffffffu, rm, 2));
            float nm   = fmaxf(m_[r], rm);
            float corr = __expf(m_[r] - nm);
            float rs = 0.f;
            #pragma unroll
            for (int ni = 0; ni < 8; ni++) {
                float p0 = __expf(c[ni][bx]   - nm);
                float p1 = __expf(c[ni][bx+1] - nm);
                c[ni][bx] = p0; c[ni][bx+1] = p1;
                rs += p0 + p1;
            }
            rs += __shfl_xor_sync(0xffffffffu, rs, 1);
            rs += __shfl_xor_sync(0xffffffffu, rs, 2);
            l_[r] = l_[r] * corr + rs;
            m_[r] = nm;
            #pragma unroll
            for (int ni = 0; ni < 8; ni++) {
                O[ni][bx]   *= corr;
                O[ni][bx+1] *= corr;
            }
        }

        #pragma unroll
        for (int ks = 0; ks < 4; ks++) {
            unsigned pah[4];
            pah[0] = packh(c[2*ks][0],   c[2*ks][1]);
            pah[1] = packh(c[2*ks][2],   c[2*ks][3]);
            pah[2] = packh(c[2*ks+1][0], c[2*ks+1][1]);
            pah[3] = packh(c[2*ks+1][2], c[2*ks+1][3]);

            int w0 = (ks*8 + qid)*4;
            #pragma unroll
            for (int ni = 0; ni < 8; ni++) {
                int dr = ni*8 + gid;
                unsigned vh[2];
                vh[0] = ld32(sb + KV_VH + dr*QP + w0);
                vh[1] = ld32(sb + KV_VH + dr*QP + w0 + 16);
                mma16h(O[ni], pah, vh);
            }
        }
        __syncthreads();
    }

    float inv0 = 1.0f / l_[0], inv1 = 1.0f / l_[1];
    int s = q0 + row0;
    size_t t0 = (size_t)(b*SEQ + s)*DM + h*DK;
    size_t t1 = t0 + (size_t)8*DM;
    #pragma unroll
    for (int ni = 0; ni < 8; ni++) {
        int d = ni*8 + (qid << 1);
        *(__half2*)&g_Ch[t0 + d] =
            __floats2half2_rn(O[ni][0]*inv0, O[ni][1]*inv0);
        *(__half2*)&g_Ch[t1 + d] =
            __floats2half2_rn(O[ni][2]*inv1, O[ni][3]*inv1);
    }
}

// ---------------------------------------------------------------------------
extern "C" void kernel_launch(void* const* d_in, const int* in_sizes, int n_in,
                              void* d_out, int out_size)
{
    (void)in_sizes; (void)n_in; (void)out_size;
    const float* query = (const float*)d_in[0];
    const float* key_  = (const float*)d_in[1];
    const float* value = (const float*)d_in[2];
    const int*   mask  = (const int*)  d_in[3];
    const float* Wq = (const float*)d_in[4];
    const float* bq = (const float*)d_in[5];
    const float* Wk = (const float*)d_in[6];
    const float* bk = (const float*)d_in[7];
    const float* Wv = (const float*)d_in[8];
    const float* bv = (const float*)d_in[9];
    const float* Wo = (const float*)d_in[10];
    const float* bo = (const float*)d_in[11];
    float* out = (float*)d_out;

    const int n4x = TOK * DM / 4;

    build_compact<<<BB, 1024>>>(mask);

    prep_all<<<dim3(n4x/256, 7), 256>>>(query, key_, value, Wq, Wk, Wv, Wo);

    cudaFuncSetAttribute(gemm_qkv_fp16,
                         cudaFuncAttributeMaxDynamicSharedMemorySize, 2*STAGEB);
    gemm_qkv_fp16<<<dim3(DM/128, TOK/128, 3), 256, 2*STAGEB>>>(bq, bk, bv);

    cudaFuncSetAttribute(flash_mma,
                         cudaFuncAttributeMaxDynamicSharedMemorySize, FL_SMEM);
    flash_mma<<<dim3(SEQ/64, NH, BB), 128, FL_SMEM>>>();

    cudaFuncSetAttribute(gemm_out_fp16,
                         cudaFuncAttributeMaxDynamicSharedMemorySize, 2*STAGEB);
    gemm_out_fp16<<<dim3(DM/128, TOK/128), 256, 2*STAGEB>>>(bo, out);
}

// round 16
// speedup vs baseline: 8.9185x; 1.0852x over previous
#include <cuda_runtime.h>
#include <cuda_fp16.h>
#include <math.h>

#define DM   1024
#define NH   16
#define DK   64
#define SEQ  2048
#define BB   2
#define TOK  (BB*SEQ)   // 4096

// ---------------- scratch (__device__ globals; no allocation allowed) -------
__device__ __half g_Xh[3*TOK*DM];      // q,kC,vC activations (fp16 hi only)
__device__ __half g_WWh[4*DM*DM];      // Wq,Wk,Wv,Wo hi
__device__ __half g_WWl[4*DM*DM];      // lo
__device__ __half g_Qhh[BB*NH*SEQ*DK]; // Q [B,H,S,DK], pre-scaled 1/8 (hi only)
__device__ __half g_Khh[BB*NH*SEQ*DK]; // K compacted (hi only)
__device__ __half g_Vth[BB*NH*DK*SEQ]; // V compacted transposed (hi only)
__device__ __half g_Ch[TOK*DM];        // ctx (hi only)
// mask compaction state
__device__ int g_cidx[BB*SEQ];
__device__ int g_cmask[BB*SEQ];
__device__ int g_cntp[BB];

// ---- helpers ---------------------------------------------------------------
__device__ __forceinline__ __half hhi(float x) { return __float2half(x); }
__device__ __forceinline__ __half hlo(float x) {
    return __float2half(x - __half2float(__float2half(x)));
}
__device__ __forceinline__ unsigned packh(float lo, float hi) {
    __half2 t = __floats2half2_rn(lo, hi);
    return *(unsigned*)&t;
}
__device__ __forceinline__ void mma16h(float d[4], const unsigned a[4],
                                       const unsigned b[2]) {
    asm("mma.sync.aligned.m16n8k16.row.col.f32.f16.f16.f32 "
        "{%0,%1,%2,%3}, {%4,%5,%6,%7}, {%8,%9}, {%0,%1,%2,%3};"
        : "+f"(d[0]), "+f"(d[1]), "+f"(d[2]), "+f"(d[3])
        : "r"(a[0]), "r"(a[1]), "r"(a[2]), "r"(a[3]), "r"(b[0]), "r"(b[1]));
}
__device__ __forceinline__ void cp16(void* dst, const void* src) {
    unsigned d = (unsigned)__cvta_generic_to_shared(dst);
    asm volatile("cp.async.ca.shared.global [%0], [%1], 16;" :: "r"(d), "l"(src));
}
#define CP_COMMIT()  asm volatile("cp.async.commit_group;" ::: "memory")
#define CP_WAIT(n)   asm volatile("cp.async.wait_group %0;" :: "n"(n) : "memory")
__device__ __forceinline__ unsigned ld32(const void* p) { return *(const unsigned*)p; }

// ---------------------------------------------------------------------------
// Mask compaction (prefix scan per batch).
// ---------------------------------------------------------------------------
__global__ __launch_bounds__(1024)
void build_compact(const int* __restrict__ mask)
{
    __shared__ int wsum[32];
    const int b = blockIdx.x, t = threadIdx.x;
    const int lane = t & 31, warp = t >> 5;
    const int* mb = mask + b * SEQ;
    int m0 = mb[2*t], m1 = mb[2*t + 1];
    int loc = m0 + m1;
    int v = loc;
    #pragma unroll
    for (int o = 1; o < 32; o <<= 1) {
        int u = __shfl_up_sync(0xffffffffu, v, o);
        if (lane >= o) v += u;
    }
    if (lane == 31) wsum[warp] = v;
    __syncthreads();
    if (warp == 0) {
        int w = wsum[lane];
        #pragma unroll
        for (int o = 1; o < 32; o <<= 1) {
            int u = __shfl_up_sync(0xffffffffu, w, o);
            if (lane >= o) w += u;
        }
        wsum[lane] = w;
    }
    __syncthreads();
    const int base = (warp ? wsum[warp - 1] : 0) + v - loc;
    const int tot  = wsum[31];
    if (m0) g_cidx[b*SEQ + base]      = 2*t;
    if (m1) g_cidx[b*SEQ + base + m0] = 2*t + 1;
    if (2*t     >= tot) g_cidx[b*SEQ + 2*t]     = 0;
    if (2*t + 1 >= tot) g_cidx[b*SEQ + 2*t + 1] = 0;
    g_cmask[b*SEQ + 2*t]     = (2*t     < tot) ? 1 : 0;
    g_cmask[b*SEQ + 2*t + 1] = (2*t + 1 < tot) ? 1 : 0;
    if (t == 0) {
        int totp = (tot + 127) & ~127;
        if (totp == 0) totp = 128;
        g_cntp[b] = totp;
    }
}

// ---------------------------------------------------------------------------
// Fused prep: blockIdx.y selects work.
//  y=0: cast query; y=1,2: gather-cast key/value; y=3..6: weight splits
// ---------------------------------------------------------------------------
__global__ __launch_bounds__(256)
void prep_all(const float* __restrict__ query, const float* __restrict__ k_in,
              const float* __restrict__ v_in,
              const float* __restrict__ Wq, const float* __restrict__ Wk,
              const float* __restrict__ Wv, const float* __restrict__ Wo)
{
    const int y = blockIdx.y;
    int i = blockIdx.x * blockDim.x + threadIdx.x;
    if (y == 0) {
        float4 v = ((const float4*)query)[i];
        __half* hi = g_Xh;
        ((__half2*)hi)[2*i]   = __floats2half2_rn(v.x, v.y);
        ((__half2*)hi)[2*i+1] = __floats2half2_rn(v.z, v.w);
    } else if (y <= 2) {
        const float* x = (y == 2) ? v_in : k_in;
        __half* hi = g_Xh + (size_t)y * TOK * DM;
        int row = i >> 8, col4 = i & 255;
        int b = row >> 11, j = row & (SEQ - 1);
        int src = g_cidx[b*SEQ + j];
        float4 v = ((const float4*)x)[(size_t)(b*SEQ + src) * 256 + col4];
        ((__half2*)hi)[2*i]   = __floats2half2_rn(v.x, v.y);
        ((__half2*)hi)[2*i+1] = __floats2half2_rn(v.z, v.w);
    } else {
        const int z = y - 3;
        if (i >= DM*DM/4) return;
        const float* w = (z == 0) ? Wq : (z == 1) ? Wk : (z == 2) ? Wv : Wo;
        __half* hi = g_WWh + (size_t)z * DM * DM;
        __half* lo = g_WWl + (size_t)z * DM * DM;
        float4 v = ((const float4*)w)[i];
        float vv[4] = {v.x, v.y, v.z, v.w};
        __half h[4], l[4];
        #pragma unroll
        for (int j = 0; j < 4; j++) {
            h[j] = __float2half(vv[j]);
            l[j] = __float2half(vv[j] - __half2float(h[j]));
        }
        ((__half2*)hi)[2*i]   = __halves2half2(h[0], h[1]);
        ((__half2*)hi)[2*i+1] = __halves2half2(h[2], h[3]);
        ((__half2*)lo)[2*i]   = __halves2half2(l[0], l[1]);
        ((__half2*)lo)[2*i+1] = __halves2half2(l[2], l[3]);
    }
}

// ---- GEMM smem layout ------------------------------------------------------
#define PITCH   80
#define OFF_AH  0
#define OFF_BH  10240
#define OFF_BL  20480
#define STAGEB  30720
#define BKB     32

__device__ __forceinline__
void stage_load(char* sbase, int lrow, int lchk,
                const __half* __restrict__ Ah,
                const __half* __restrict__ Bh,
                const __half* __restrict__ Bl,
                int m0, int n0, int k0)
{
    #pragma unroll
    for (int r = 0; r < 2; r++) {
        int row = lrow + r*64;
        cp16(sbase + OFF_AH + row*PITCH + lchk*2, Ah + (size_t)(m0+row)*DM + k0 + lchk);
        cp16(sbase + OFF_BH + row*PITCH + lchk*2, Bh + (size_t)(n0+row)*DM + k0 + lchk);
        cp16(sbase + OFF_BL + row*PITCH + lchk*2, Bl + (size_t)(n0+row)*DM + k0 + lchk);
    }
}

// ---------------------------------------------------------------------------
// 2-term fp16 tensor-core GEMM: C = A_h @ (W_h + W_l)^T + bias.
// mode: 0=fp32 C; 2=transposed hi only (V); 3=head-layout hi only (Q/K).
// ---------------------------------------------------------------------------
__device__ __forceinline__
void gemm_fp16_core(const __half* __restrict__ Agh,
                    const __half* __restrict__ Bgh,
                    const __half* __restrict__ Bgl,
                    const float* __restrict__ bias,
                    int mode, float scale,
                    float* __restrict__ C,
                    __half* __restrict__ Oh)
{
    extern __shared__ char smem[];

    const int tid  = threadIdx.x;
    const int lane = tid & 31;
    const int warp = tid >> 5;
    const int wm   = warp >> 2;
    const int wn   = warp & 3;
    const int gid  = lane >> 2;
    const int qid  = lane & 3;
    const int m0   = blockIdx.y << 7;
    const int n0   = blockIdx.x << 7;

    const int lrow = tid >> 2;
    const int lchk = (tid & 3) << 3;

    float acc[4][4][4];
    #pragma unroll
    for (int mi = 0; mi < 4; mi++)
        #pragma unroll
        for (int ni = 0; ni < 4; ni++)
            #pragma unroll
            for (int r = 0; r < 4; r++) acc[mi][ni][r] = 0.f;

    const int NKB = DM / BKB;

    stage_load(smem, lrow, lchk, Agh, Bgh, Bgl, m0, n0, 0);
    CP_COMMIT();

    for (int kb = 0; kb < NKB; kb++) {
        if (kb + 1 < NKB) {
            stage_load(smem + ((kb+1)&1)*STAGEB, lrow, lchk,
                       Agh, Bgh, Bgl, m0, n0, (kb+1)*BKB);
            CP_COMMIT();
            CP_WAIT(1);
        } else {
            CP_WAIT(0);
        }
        __syncthreads();

        char* sb = smem + (kb & 1) * STAGEB;

        #pragma unroll
        for (int ks = 0; ks < 2; ks++) {
            unsigned afh[4][4];
            #pragma unroll
            for (int mi = 0; mi < 4; mi++) {
                int row = wm*64 + mi*16 + gid;
                #pragma unroll
                for (int r = 0; r < 4; r++) {
                    int rr = row + ((r & 1) << 3);
                    int w  = ks*8 + qid + ((r >> 1) << 2);
                    afh[mi][r] = ld32(sb + OFF_AH + rr*PITCH + w*4);
                }
            }
            #pragma unroll
            for (int ni = 0; ni < 4; ni++) {
                int col = wn*32 + ni*8 + gid;
                unsigned bfh[2], bfl[2];
                #pragma unroll
                for (int r = 0; r < 2; r++) {
                    int w = ks*8 + qid + (r << 2);
                    bfh[r] = ld32(sb + OFF_BH + col*PITCH + w*4);
                    bfl[r] = ld32(sb + OFF_BL + col*PITCH + w*4);
                }
                #pragma unroll
                for (int mi = 0; mi < 4; mi++) {
                    mma16h(acc[mi][ni], afh[mi], bfh);
                    mma16h(acc[mi][ni], afh[mi], bfl);
                }
            }
        }
        __syncthreads();
    }

    // ---- epilogue ----
    #pragma unroll
    for (int mi = 0; mi < 4; mi++) {
        #pragma unroll
        for (int ni = 0; ni < 4; ni++) {
            int row = m0 + wm*64 + mi*16 + gid;
            int col = n0 + wn*32 + ni*8 + (qid << 1);
            float b0 = bias[col], b1 = bias[col + 1];
            float v00 = (acc[mi][ni][0] + b0) * scale;
            float v01 = (acc[mi][ni][1] + b1) * scale;
            float v10 = (acc[mi][ni][2] + b0) * scale;
            float v11 = (acc[mi][ni][3] + b1) * scale;
            if (mode == 0) {
                *(float2*)&C[(size_t)row       * DM + col] = make_float2(v00, v01);
                *(float2*)&C[(size_t)(row + 8) * DM + col] = make_float2(v10, v11);
            } else if (mode == 3) {
                int h = col >> 6, d = col & 63;
                {
                    int t = row, bbx = t >> 11, s = t & (SEQ - 1);
                    size_t off = ((size_t)((bbx*NH + h)*SEQ) + s)*DK + d;
                    *(__half2*)&Oh[off] = __halves2half2(hhi(v00), hhi(v01));
                }
                {
                    int t = row + 8, bbx = t >> 11, s = t & (SEQ - 1);
                    size_t off = ((size_t)((bbx*NH + h)*SEQ) + s)*DK + d;
                    *(__half2*)&Oh[off] = __halves2half2(hhi(v10), hhi(v11));
                }
            } else {
                // V transposed, hi only
                int h = col >> 6, d = col & 63;
                int bbx = row >> 11, s = row & (SEQ - 1);
                size_t base = (size_t)(bbx*NH + h) * DK;
                Oh[(base + d    )*SEQ + s    ] = hhi(v00);
                Oh[(base + d + 1)*SEQ + s    ] = hhi(v01);
                Oh[(base + d    )*SEQ + s + 8] = hhi(v10);
                Oh[(base + d + 1)*SEQ + s + 8] = hhi(v11);
            }
        }
    }
}

__global__ __launch_bounds__(256, 2)
void gemm_qkv_fp16(const float* __restrict__ bq, const float* __restrict__ bk,
                   const float* __restrict__ bv)
{
    const int z = blockIdx.z;
    if (z >= 1) {
        int m0i = blockIdx.y << 7;
        if ((m0i & (SEQ - 1)) >= g_cntp[m0i >> 11]) return;
    }
    const __half* Agh = g_Xh  + (size_t)z * TOK * DM;
    const __half* Wgh = g_WWh + (size_t)z * DM * DM;
    const __half* Wgl = g_WWl + (size_t)z * DM * DM;
    if (z == 0)
        gemm_fp16_core(Agh, Wgh, Wgl, bq, 3, 0.125f, nullptr, g_Qhh);
    else if (z == 1)
        gemm_fp16_core(Agh, Wgh, Wgl, bk, 3, 1.0f, nullptr, g_Khh);
    else
        gemm_fp16_core(Agh, Wgh, Wgl, bv, 2, 1.0f, nullptr, g_Vth);
}

__global__ __launch_bounds__(256, 2)
void gemm_out_fp16(const float* __restrict__ bo, float* __restrict__ out)
{
    gemm_fp16_core(g_Ch,
                   g_WWh + (size_t)3 * DM * DM,
                   g_WWl + (size_t)3 * DM * DM,
                   bo, 0, 1.0f, out, nullptr);
}

// ---------------------------------------------------------------------------
// fp16 flash attention: 64-query CTAs (128 thr), Q fragments in registers,
// K hi-only / V hi-only in smem (K-lo and V-lo both below the Q/P-rounding
// noise floor -- validated empirically for V-lo in R14: +0.04e-4).
// ---------------------------------------------------------------------------
#define QP      144
#define KV_KH   0
#define KV_VH   (64*QP)             // 9216
#define KV_MK   (2*64*QP)           // 18432
#define KV_SZ   (2*64*QP + 256)     // 18688
#define FL_SMEM (2*KV_SZ)           // 37376

__device__ __forceinline__
void stage_kv(char* sb, int tid,
              const __half* __restrict__ Khg,
              const __half* __restrict__ Vhg,
              const int* __restrict__ mb, int k0)
{
    // 64 rows x 8 chunks per array, 2 arrays: 1024 cp16 / 128 thr -> 4 iters
    #pragma unroll
    for (int it = 0; it < 4; it++) {
        int idx = tid + it*128;
        int row = idx >> 3, ch = idx & 7;
        cp16(sb + KV_KH + row*QP + ch*16, Khg + (size_t)(k0 + row)*DK + ch*8);
        cp16(sb + KV_VH + row*QP + ch*16, Vhg + (size_t)row*SEQ + k0 + ch*8);
    }
    if (tid < 16) cp16(sb + KV_MK + tid*16, mb + k0 + tid*4);
}

__global__ __launch_bounds__(128, 3)
void flash_mma()
{
    extern __shared__ char sm[];
    const int tid  = threadIdx.x;
    const int lane = tid & 31;
    const int warp = tid >> 5;          // 0..3
    const int gid  = lane >> 2;
    const int qid  = lane & 3;
    const int q0   = blockIdx.x << 6;   // 64-query tiles
    const int h    = blockIdx.y;
    const int b    = blockIdx.z;

    const __half* Qhg = g_Qhh + ((size_t)((b*NH + h)*SEQ) + q0)*DK;
    const __half* Khg = g_Khh + (size_t)(b*NH + h)*SEQ*DK;
    const __half* Vhg = g_Vth + (size_t)(b*NH + h)*DK*SEQ;
    const int* mb = g_cmask + b * SEQ;
    const int ktmax = g_cntp[b] >> 6;

    const int row0 = warp*16 + gid;

    // Q a-fragments in registers
    unsigned aq[4][4];
    #pragma unroll
    for (int ks = 0; ks < 4; ks++) {
        aq[ks][0] = ld32(&Qhg[(size_t)(row0    )*DK + ks*16 + qid*2]);
        aq[ks][1] = ld32(&Qhg[(size_t)(row0 + 8)*DK + ks*16 + qid*2]);
        aq[ks][2] = ld32(&Qhg[(size_t)(row0    )*DK + ks*16 + qid*2 + 8]);
        aq[ks][3] = ld32(&Qhg[(size_t)(row0 + 8)*DK + ks*16 + qid*2 + 8]);
    }

    stage_kv(sm, tid, Khg, Vhg, mb, 0);
    CP_COMMIT();

    float O[8][4];
    #pragma unroll
    for (int ni = 0; ni < 8; ni++)
        #pragma unroll
        for (int r = 0; r < 4; r++) O[ni][r] = 0.f;
    float m_[2] = {-1e30f, -1e30f}, l_[2] = {0.f, 0.f};

    for (int kt = 0; kt < ktmax; kt++) {
        char* sb = sm + (kt & 1)*KV_SZ;
        if (kt + 1 < ktmax) {
            stage_kv(sm + ((kt+1) & 1)*KV_SZ, tid, Khg, Vhg, mb, (kt+1) << 6);
            CP_COMMIT();
            CP_WAIT(1);
        } else {
            CP_WAIT(0);
        }
        __syncthreads();

        float c[8][4];
        #pragma unroll
        for (int ni = 0; ni < 8; ni++)
            #pragma unroll
            for (int r = 0; r < 4; r++) c[ni][r] = 0.f;

        #pragma unroll
        for (int ks = 0; ks < 4; ks++) {
            int w0 = (ks*8 + qid)*4;
            #pragma unroll
            for (int ni = 0; ni < 8; ni++) {
                int kr = ni*8 + gid;
                unsigned bh[2];
                bh[0] = ld32(sb + KV_KH + kr*QP + w0);
                bh[1] = ld32(sb + KV_KH + kr*QP + w0 + 16);
                mma16h(c[ni], aq[ks], bh);
            }
        }

        const int* mks = (const int*)(sb + KV_MK);
        #pragma unroll
        for (int ni = 0; ni < 8; ni++) {
            int c0 = ni*8 + qid*2;
            if (mks[c0]     == 0) { c[ni][0] = -1.0e9f; c[ni][2] = -1.0e9f; }
            if (mks[c0 + 1] == 0) { c[ni][1] = -1.0e9f; c[ni][3] = -1.0e9f; }
        }

        #pragma unroll
        for (int r = 0; r < 2; r++) {
            const int bx = r*2;
            float rm = -1e30f;
            #pragma unroll
            for (int ni = 0; ni < 8; ni++)
                rm = fmaxf(rm, fmaxf(c[ni][bx], c[ni][bx+1]));
            rm = fmaxf(rm, __shfl_xor_sync(0xffffffffu, rm, 1));
            rm = fmaxf(rm, __shfl_xor_sync(0xffffffffu, rm, 2));
            float nm   = fmaxf(m_[r], rm);
            float corr = __expf(m_[r] - nm);
            float rs = 0.f;
            #pragma unroll
            for (int ni = 0; ni < 8; ni++) {
                float p0 = __expf(c[ni][bx]   - nm);
                float p1 = __expf(c[ni][bx+1] - nm);
                c[ni][bx] = p0; c[ni][bx+1] = p1;
                rs += p0 + p1;
            }
            rs += __shfl_xor_sync(0xffffffffu, rs, 1);
            rs += __shfl_xor_sync(0xffffffffu, rs, 2);
            l_[r] = l_[r] * corr + rs;
            m_[r] = nm;
            #pragma unroll
            for (int ni = 0; ni < 8; ni++) {
                O[ni][bx]   *= corr;
                O[ni][bx+1] *= corr;
            }
        }

        #pragma unroll
        for (int ks = 0; ks < 4; ks++) {
            unsigned pah[4];
            pah[0] = packh(c[2*ks][0],   c[2*ks][1]);
            pah[1] = packh(c[2*ks][2],   c[2*ks][3]);
            pah[2] = packh(c[2*ks+1][0], c[2*ks+1][1]);
            pah[3] = packh(c[2*ks+1][2], c[2*ks+1][3]);

            int w0 = (ks*8 + qid)*4;
            #pragma unroll
            for (int ni = 0; ni < 8; ni++) {
                int dr = ni*8 + gid;
                unsigned vh[2];
                vh[0] = ld32(sb + KV_VH + dr*QP + w0);
                vh[1] = ld32(sb + KV_VH + dr*QP + w0 + 16);
                mma16h(O[ni], pah, vh);
            }
        }
        __syncthreads();
    }

    float inv0 = 1.0f / l_[0], inv1 = 1.0f / l_[1];
    int s = q0 + row0;
    size_t t0 = (size_t)(b*SEQ + s)*DM + h*DK;
    size_t t1 = t0 + (size_t)8*DM;
    #pragma unroll
    for (int ni = 0; ni < 8; ni++) {
        int d = ni*8 + (qid << 1);
        *(__half2*)&g_Ch[t0 + d] =
            __floats2half2_rn(O[ni][0]*inv0, O[ni][1]*inv0);
        *(__half2*)&g_Ch[t1 + d] =
            __floats2half2_rn(O[ni][2]*inv1, O[ni][3]*inv1);
    }
}

// ---------------------------------------------------------------------------
extern "C" void kernel_launch(void* const* d_in, const int* in_sizes, int n_in,
                              void* d_out, int out_size)
{
    (void)in_sizes; (void)n_in; (void)out_size;
    const float* query = (const float*)d_in[0];
    const float* key_  = (const float*)d_in[1];
    const float* value = (const float*)d_in[2];
    const int*   mask  = (const int*)  d_in[3];
    const float* Wq = (const float*)d_in[4];
    const float* bq = (const float*)d_in[5];
    const float* Wk = (const float*)d_in[6];
    const float* bk = (const float*)d_in[7];
    const float* Wv = (const float*)d_in[8];
    const float* bv = (const float*)d_in[9];
    const float* Wo = (const float*)d_in[10];
    const float* bo = (const float*)d_in[11];
    float* out = (float*)d_out;

    const int n4x = TOK * DM / 4;

    build_compact<<<BB, 1024>>>(mask);

    prep_all<<<dim3(n4x/256, 7), 256>>>(query, key_, value, Wq, Wk, Wv, Wo);

    cudaFuncSetAttribute(gemm_qkv_fp16,
                         cudaFuncAttributeMaxDynamicSharedMemorySize, 2*STAGEB);
    gemm_qkv_fp16<<<dim3(DM/128, TOK/128, 3), 256, 2*STAGEB>>>(bq, bk, bv);

    cudaFuncSetAttribute(flash_mma,
                         cudaFuncAttributeMaxDynamicSharedMemorySize, FL_SMEM);
    flash_mma<<<dim3(SEQ/64, NH, BB), 128, FL_SMEM>>>();

    cudaFuncSetAttribute(gemm_out_fp16,
                         cudaFuncAttributeMaxDynamicSharedMemorySize, 2*STAGEB);
    gemm_out_fp16<<<dim3(DM/128, TOK/128), 256, 2*STAGEB>>>(bo, out);
}